// round 6
// baseline (speedup 1.0000x reference)
#include <cuda_runtime.h>
#include <cstdint>

#define B_     8
#define S_     1024
#define D_     512
#define H_     8
#define HD_    64
#define FF_    2048
#define STEPS_ 64
#define CAP_   1088
#define MTOK   (B_*S_)   /* 8192 */
#define NBLK   128
#define DTH    512       /* decode threads per block */

// ---------------- device scratch (no cudaMalloc allowed) ----------------
__device__ float g_qkv [MTOK*1536];
__device__ float g_attn[MTOK*D_];
__device__ float g_pre [MTOK*D_];
__device__ float g_h   [MTOK*D_];
__device__ float g_hff [MTOK*FF_];
__device__ float g_kc  [B_*CAP_*D_];
__device__ float g_vc  [B_*CAP_*D_];
__device__ float g_qt  [B_*D_];
__device__ float g_hfft[B_*FF_];
__device__ float g_t1  [B_*D_];
__device__ float g_op  [2*64*64];
__device__ float g_ml  [2*64*2];
__device__ unsigned g_bar_count;
__device__ unsigned g_bar_sense;

// ---------------- reductions ----------------
__device__ __forceinline__ float warpRedSum(float v) {
#pragma unroll
    for (int o = 16; o; o >>= 1) v += __shfl_xor_sync(0xffffffffu, v, o);
    return v;
}
__device__ __forceinline__ float warpRedMax(float v) {
#pragma unroll
    for (int o = 16; o; o >>= 1) v = fmaxf(v, __shfl_xor_sync(0xffffffffu, v, o));
    return v;
}

// ---------------- central barrier, load-based poll ----------------
__device__ __forceinline__ unsigned ld_acq(const unsigned* p) {
    unsigned v;
    asm volatile("ld.acquire.gpu.u32 %0, [%1];" : "=r"(v) : "l"(p) : "memory");
    return v;
}
__device__ __forceinline__ void st_rel(unsigned* p, unsigned v) {
    asm volatile("st.release.gpu.u32 [%0], %1;" :: "l"(p), "r"(v) : "memory");
}
__device__ __forceinline__ void gbar(unsigned& target, int tid) {
    __threadfence();
    __syncthreads();
    target += 1;
    if (tid == 0) {
        unsigned a = atomicAdd(&g_bar_count, 1u) + 1u;
        if (a == (unsigned)NBLK) {
            atomicExch(&g_bar_count, 0u);
            st_rel(&g_bar_sense, target);
        } else {
            while ((int)(ld_acq(&g_bar_sense) - target) < 0) { }
        }
    }
    __syncthreads();
    __threadfence();
}

// ---------------- SGEMM (NT), double-buffered smem + reg prefetch ----------------
// BM=BN=128, BK=16, 256 threads, 2 blocks/SM; ONE sync per K-tile.
template<int BIAS, int RELU, int RES>
__global__ void __launch_bounds__(256, 2) sgemm_nt(
    const float* __restrict__ A, const float* __restrict__ Bm,
    const float* __restrict__ bias, const float* __restrict__ R,
    float* __restrict__ C, int M, int N, int K)
{
    __shared__ float As[2][16][132];
    __shared__ float Bs[2][16][132];
    const int tid = threadIdx.x;
    const int m0 = blockIdx.y * 128;
    const int n0 = blockIdx.x * 128;
    const int tx = tid & 15, ty = tid >> 4;
    const int r0 = ty * 4, c0 = tx * 4;
    const int lrow = tid >> 2;
    const int lk4  = (tid & 3) * 4;

    const float* Ap0 = A  + (size_t)(m0 + lrow)      * K + lk4;
    const float* Ap1 = A  + (size_t)(m0 + lrow + 64) * K + lk4;
    const float* Bp0 = Bm + (size_t)(n0 + lrow)      * K + lk4;
    const float* Bp1 = Bm + (size_t)(n0 + lrow + 64) * K + lk4;

    float acc[8][8];
#pragma unroll
    for (int i = 0; i < 8; i++)
#pragma unroll
        for (int j = 0; j < 8; j++) acc[i][j] = 0.f;

    float4 pa0 = *(const float4*)(Ap0);
    float4 pa1 = *(const float4*)(Ap1);
    float4 pb0 = *(const float4*)(Bp0);
    float4 pb1 = *(const float4*)(Bp1);
    As[0][lk4 + 0][lrow]      = pa0.x; As[0][lk4 + 1][lrow]      = pa0.y;
    As[0][lk4 + 2][lrow]      = pa0.z; As[0][lk4 + 3][lrow]      = pa0.w;
    As[0][lk4 + 0][lrow + 64] = pa1.x; As[0][lk4 + 1][lrow + 64] = pa1.y;
    As[0][lk4 + 2][lrow + 64] = pa1.z; As[0][lk4 + 3][lrow + 64] = pa1.w;
    Bs[0][lk4 + 0][lrow]      = pb0.x; Bs[0][lk4 + 1][lrow]      = pb0.y;
    Bs[0][lk4 + 2][lrow]      = pb0.z; Bs[0][lk4 + 3][lrow]      = pb0.w;
    Bs[0][lk4 + 0][lrow + 64] = pb1.x; Bs[0][lk4 + 1][lrow + 64] = pb1.y;
    Bs[0][lk4 + 2][lrow + 64] = pb1.z; Bs[0][lk4 + 3][lrow + 64] = pb1.w;
    __syncthreads();

    int buf = 0;
    for (int k0 = 0; k0 < K; k0 += 16) {
        const bool more = (k0 + 16) < K;
        if (more) {   // prefetch next tile; latency hidden under compute
            pa0 = *(const float4*)(Ap0 + k0 + 16);
            pa1 = *(const float4*)(Ap1 + k0 + 16);
            pb0 = *(const float4*)(Bp0 + k0 + 16);
            pb1 = *(const float4*)(Bp1 + k0 + 16);
        }
#pragma unroll
        for (int kk = 0; kk < 16; kk++) {
            float af[8], bf[8];
            *(float4*)(af)     = *(const float4*)(&As[buf][kk][r0]);
            *(float4*)(af + 4) = *(const float4*)(&As[buf][kk][r0 + 64]);
            *(float4*)(bf)     = *(const float4*)(&Bs[buf][kk][c0]);
            *(float4*)(bf + 4) = *(const float4*)(&Bs[buf][kk][c0 + 64]);
#pragma unroll
            for (int i = 0; i < 8; i++)
#pragma unroll
                for (int j = 0; j < 8; j++)
                    acc[i][j] = fmaf(af[i], bf[j], acc[i][j]);
        }
        if (more) {
            const int nb = buf ^ 1;
            As[nb][lk4 + 0][lrow]      = pa0.x; As[nb][lk4 + 1][lrow]      = pa0.y;
            As[nb][lk4 + 2][lrow]      = pa0.z; As[nb][lk4 + 3][lrow]      = pa0.w;
            As[nb][lk4 + 0][lrow + 64] = pa1.x; As[nb][lk4 + 1][lrow + 64] = pa1.y;
            As[nb][lk4 + 2][lrow + 64] = pa1.z; As[nb][lk4 + 3][lrow + 64] = pa1.w;
            Bs[nb][lk4 + 0][lrow]      = pb0.x; Bs[nb][lk4 + 1][lrow]      = pb0.y;
            Bs[nb][lk4 + 2][lrow]      = pb0.z; Bs[nb][lk4 + 3][lrow]      = pb0.w;
            Bs[nb][lk4 + 0][lrow + 64] = pb1.x; Bs[nb][lk4 + 1][lrow + 64] = pb1.y;
            Bs[nb][lk4 + 2][lrow + 64] = pb1.z; Bs[nb][lk4 + 3][lrow + 64] = pb1.w;
            __syncthreads();
            buf = nb;
        }
    }

    float bl[8];
#pragma unroll
    for (int j = 0; j < 8; j++)
        bl[j] = BIAS ? bias[n0 + c0 + (j < 4 ? j : 60 + j)] : 0.f;

#pragma unroll
    for (int i = 0; i < 8; i++) {
        const int row = m0 + r0 + (i < 4 ? i : 60 + i);
        const size_t rowoff = (size_t)row * N + n0;
#pragma unroll
        for (int jg = 0; jg < 2; jg++) {
            const int cb = c0 + jg * 64;
            float t0 = acc[i][jg * 4 + 0] + bl[jg * 4 + 0];
            float t1 = acc[i][jg * 4 + 1] + bl[jg * 4 + 1];
            float t2 = acc[i][jg * 4 + 2] + bl[jg * 4 + 2];
            float t3 = acc[i][jg * 4 + 3] + bl[jg * 4 + 3];
            if (RES) {
                float4 r = *(const float4*)(R + rowoff + cb);
                t0 += r.x; t1 += r.y; t2 += r.z; t3 += r.w;
            }
            if (RELU) {
                t0 = fmaxf(t0, 0.f); t1 = fmaxf(t1, 0.f);
                t2 = fmaxf(t2, 0.f); t3 = fmaxf(t3, 0.f);
            }
            float4 v; v.x = t0; v.y = t1; v.z = t2; v.w = t3;
            *(float4*)(C + rowoff + cb) = v;
        }
    }
}

// ---------------- prefill flash attention (causal), 64x64 tiles ----------------
__global__ void __launch_bounds__(256) attn_prefill(const float* __restrict__ qkv,
                                                    float* __restrict__ attn)
{
    extern __shared__ float sm[];
    float* Qs = sm;
    float* KP = sm + 64 * 64;
    float* Vs = KP + 64 * 65;

    const int b  = blockIdx.y >> 3;
    const int h  = blockIdx.y & 7;
    const int l0 = blockIdx.x * 64;
    const int tid = threadIdx.x;
    const int tx = tid & 15, ty = tid >> 4;
    const int r0 = ty * 4, c0 = tx * 4;

    const size_t rowbase = (size_t)(b * S_) * 1536;
    const float* qbase = qkv + rowbase + h * 64;
    const float* kbase = qkv + rowbase + 512 + h * 64;
    const float* vbase = qkv + rowbase + 1024 + h * 64;

    const int lt  = tid >> 4;
    const int ld4 = (tid & 15) * 4;

#pragma unroll
    for (int tt = lt; tt < 64; tt += 16) {
        float4 q4 = *(const float4*)(qbase + (size_t)(l0 + tt) * 1536 + ld4);
        Qs[(ld4 + 0) * 64 + tt] = q4.x;
        Qs[(ld4 + 1) * 64 + tt] = q4.y;
        Qs[(ld4 + 2) * 64 + tt] = q4.z;
        Qs[(ld4 + 3) * 64 + tt] = q4.w;
    }

    float o[4][4];
    float mrow[4], lrow[4];
#pragma unroll
    for (int i = 0; i < 4; i++) {
        mrow[i] = -1e30f; lrow[i] = 0.f;
#pragma unroll
        for (int j = 0; j < 4; j++) o[i][j] = 0.f;
    }

    const int ntiles = (l0 >> 6) + 1;
    for (int tile = 0; tile < ntiles; ++tile) {
        const int j0 = tile * 64;
        __syncthreads();
#pragma unroll
        for (int tt = lt; tt < 64; tt += 16) {
            float4 k4 = *(const float4*)(kbase + (size_t)(j0 + tt) * 1536 + ld4);
            KP[(ld4 + 0) * 65 + tt] = k4.x;
            KP[(ld4 + 1) * 65 + tt] = k4.y;
            KP[(ld4 + 2) * 65 + tt] = k4.z;
            KP[(ld4 + 3) * 65 + tt] = k4.w;
            float4 v4 = *(const float4*)(vbase + (size_t)(j0 + tt) * 1536 + ld4);
            *(float4*)(Vs + tt * 64 + ld4) = v4;
        }
        __syncthreads();

        float s[4][4];
#pragma unroll
        for (int i = 0; i < 4; i++)
#pragma unroll
            for (int j = 0; j < 4; j++) s[i][j] = 0.f;

        for (int d = 0; d < 64; d++) {
            float qf[4];
            *(float4*)qf = *(const float4*)(Qs + d * 64 + r0);
            float kf0 = KP[d * 65 + c0 + 0];
            float kf1 = KP[d * 65 + c0 + 1];
            float kf2 = KP[d * 65 + c0 + 2];
            float kf3 = KP[d * 65 + c0 + 3];
#pragma unroll
            for (int i = 0; i < 4; i++) {
                s[i][0] = fmaf(qf[i], kf0, s[i][0]);
                s[i][1] = fmaf(qf[i], kf1, s[i][1]);
                s[i][2] = fmaf(qf[i], kf2, s[i][2]);
                s[i][3] = fmaf(qf[i], kf3, s[i][3]);
            }
        }

        if (j0 == l0) {
#pragma unroll
            for (int i = 0; i < 4; i++)
#pragma unroll
                for (int j = 0; j < 4; j++)
                    s[i][j] = (j0 + c0 + j > l0 + r0 + i) ? -1e30f : s[i][j] * 0.125f;
        } else {
#pragma unroll
            for (int i = 0; i < 4; i++)
#pragma unroll
                for (int j = 0; j < 4; j++) s[i][j] *= 0.125f;
        }

        float p[4][4];
#pragma unroll
        for (int i = 0; i < 4; i++) {
            float rm = fmaxf(fmaxf(s[i][0], s[i][1]), fmaxf(s[i][2], s[i][3]));
#pragma unroll
            for (int off = 8; off; off >>= 1)
                rm = fmaxf(rm, __shfl_xor_sync(0xffffffffu, rm, off));
            float mnew  = fmaxf(mrow[i], rm);
            float alpha = __expf(mrow[i] - mnew);
            float ps = 0.f;
#pragma unroll
            for (int j = 0; j < 4; j++) { p[i][j] = __expf(s[i][j] - mnew); ps += p[i][j]; }
#pragma unroll
            for (int off = 8; off; off >>= 1)
                ps += __shfl_xor_sync(0xffffffffu, ps, off);
            lrow[i] = lrow[i] * alpha + ps;
            mrow[i] = mnew;
#pragma unroll
            for (int j = 0; j < 4; j++) o[i][j] *= alpha;
        }

        __syncthreads();
#pragma unroll
        for (int i = 0; i < 4; i++)
#pragma unroll
            for (int j = 0; j < 4; j++)
                KP[(r0 + i) * 65 + c0 + j] = p[i][j];
        __syncthreads();

        for (int c = 0; c < 64; c++) {
            float vv[4];
            *(float4*)vv = *(const float4*)(Vs + c * 64 + c0);
            float p0 = KP[(r0 + 0) * 65 + c];
            float p1 = KP[(r0 + 1) * 65 + c];
            float p2 = KP[(r0 + 2) * 65 + c];
            float p3 = KP[(r0 + 3) * 65 + c];
#pragma unroll
            for (int j = 0; j < 4; j++) {
                o[0][j] = fmaf(p0, vv[j], o[0][j]);
                o[1][j] = fmaf(p1, vv[j], o[1][j]);
                o[2][j] = fmaf(p2, vv[j], o[2][j]);
                o[3][j] = fmaf(p3, vv[j], o[3][j]);
            }
        }
    }

    float* ob = attn + (size_t)(b * S_ + l0) * 512 + h * 64;
#pragma unroll
    for (int i = 0; i < 4; i++) {
        float inv = 1.f / lrow[i];
        float4 v;
        v.x = o[i][0] * inv; v.y = o[i][1] * inv;
        v.z = o[i][2] * inv; v.w = o[i][3] * inv;
        *(float4*)(ob + (size_t)(r0 + i) * 512 + c0) = v;
    }
}

// ---------------- copy prefill K/V slices into the caches ----------------
__global__ void __launch_bounds__(128) copy_kv(const float* __restrict__ qkv,
                                               float* __restrict__ kc, float* __restrict__ vc)
{
    const int r = blockIdx.x;
    const int b = r >> 10, s = r & 1023;
    const int tid = threadIdx.x;
    const float4* src = (const float4*)(qkv + (size_t)r * 1536);
    float4* kd = (float4*)(kc + (size_t)(b * CAP_ + s) * 512);
    float4* vd = (float4*)(vc + (size_t)(b * CAP_ + s) * 512);
    kd[tid] = src[128 + tid];
    vd[tid] = src[256 + tid];
}

// ---------------- prefill LayerNorm over rows of 512 ----------------
__global__ void __launch_bounds__(256) ln_rows(const float* __restrict__ in,
                                               const float* __restrict__ g,
                                               const float* __restrict__ be,
                                               float* __restrict__ out, int outExtra)
{
    const int r = blockIdx.x;
    const int tid = threadIdx.x;
    const float* row = in + (size_t)r * 512;
    float v0 = row[tid], v1 = row[tid + 256];
    float s  = warpRedSum(v0 + v1);
    float s2 = warpRedSum(v0 * v0 + v1 * v1);
    __shared__ float r1[8], r2[8];
    __shared__ float smu, srs;
    const int w = tid >> 5, lane = tid & 31;
    if (lane == 0) { r1[w] = s; r2[w] = s2; }
    __syncthreads();
    if (tid == 0) {
        float S = 0.f, S2 = 0.f;
#pragma unroll
        for (int i = 0; i < 8; i++) { S += r1[i]; S2 += r2[i]; }
        float mu  = S * (1.f / 512.f);
        float var = S2 * (1.f / 512.f) - mu * mu;
        smu = mu; srs = rsqrtf(var + 1e-5f);
    }
    __syncthreads();
    const int orow = r + (r >> 10) * outExtra;
    float* od = out + (size_t)orow * 512;
    od[tid]       = (v0 - smu) * srs * g[tid]       + be[tid];
    od[tid + 256] = (v1 - smu) * srs * g[tid + 256] + be[tid + 256];
}

// ---------------- megakernel building blocks ----------------
template<int KP>
__device__ __forceinline__ void dot4(const float* __restrict__ wr,
                                     const float* xs, int Kstride, int lane,
                                     float& a0, float& a1, float& a2, float& a3)
{
    a0 = a1 = a2 = a3 = 0.f;
#pragma unroll
    for (int kp = 0; kp < KP; kp++) {
        const int k4 = kp * 128 + lane * 4;
        float4 wv = *(const float4*)(wr + k4);
        float4 x0 = *(const float4*)(xs + k4);
        float4 x1 = *(const float4*)(xs + Kstride + k4);
        float4 x2 = *(const float4*)(xs + 2 * Kstride + k4);
        float4 x3 = *(const float4*)(xs + 3 * Kstride + k4);
        a0 = fmaf(wv.x, x0.x, fmaf(wv.y, x0.y, fmaf(wv.z, x0.z, fmaf(wv.w, x0.w, a0))));
        a1 = fmaf(wv.x, x1.x, fmaf(wv.y, x1.y, fmaf(wv.z, x1.z, fmaf(wv.w, x1.w, a1))));
        a2 = fmaf(wv.x, x2.x, fmaf(wv.y, x2.y, fmaf(wv.z, x2.z, fmaf(wv.w, x2.w, a2))));
        a3 = fmaf(wv.x, x3.x, fmaf(wv.y, x3.y, fmaf(wv.z, x3.z, fmaf(wv.w, x3.w, a3))));
    }
    a0 = warpRedSum(a0); a1 = warpRedSum(a1);
    a2 = warpRedSum(a2); a3 = warpRedSum(a3);
}

__device__ __forceinline__ void warp_ln(const float* __restrict__ a,
                                        const float* __restrict__ r,
                                        const float* __restrict__ gw,
                                        const float* __restrict__ gb,
                                        float* __restrict__ o, int lane)
{
    float vals[16];
    float sv = 0.f, sq = 0.f;
#pragma unroll
    for (int g = 0; g < 4; g++) {
        const int idx = g * 128 + lane * 4;
        float4 av = *(const float4*)(a + idx);
        float4 rv = *(const float4*)(r + idx);
        float a0 = av.x + rv.x, a1 = av.y + rv.y;
        float a2 = av.z + rv.z, a3 = av.w + rv.w;
        vals[g * 4 + 0] = a0; vals[g * 4 + 1] = a1;
        vals[g * 4 + 2] = a2; vals[g * 4 + 3] = a3;
        sv += a0 + a1 + a2 + a3;
        sq += a0 * a0 + a1 * a1 + a2 * a2 + a3 * a3;
    }
    sv = warpRedSum(sv); sq = warpRedSum(sq);
    float mu = sv * (1.f / 512.f);
    float rs = rsqrtf(sq * (1.f / 512.f) - mu * mu + 1e-5f);
#pragma unroll
    for (int g = 0; g < 4; g++)
#pragma unroll
        for (int j = 0; j < 4; j++) {
            const int idx = g * 128 + lane * 4 + j;
            o[idx] = (vals[g * 4 + j] - mu) * rs * gw[idx] + gb[idx];
        }
}

// ---------------- decode megakernel: 512 threads/block, 16 warps/SM ----------------
__global__ void __launch_bounds__(DTH, 1) decode_mega(
    const float* __restrict__ dx,
    const float* __restrict__ qkvW, const float* __restrict__ qkvB,
    const float* __restrict__ outW, const float* __restrict__ outB,
    const float* __restrict__ w1, const float* __restrict__ b1,
    const float* __restrict__ w2, const float* __restrict__ b2,
    const float* __restrict__ ln1w, const float* __restrict__ ln1b,
    const float* __restrict__ ln2w, const float* __restrict__ ln2b,
    float* __restrict__ out,
    float* __restrict__ qt, float* __restrict__ kc, float* __restrict__ vc,
    float* __restrict__ hfft, float* __restrict__ t1,
    float* __restrict__ opart, float* __restrict__ mlpart)
{
    extern __shared__ float xs[];      // 8192 floats (32KB)
    __shared__ float s_ln[4 * 512];    // LN1 rows — persists to next step
    __shared__ float s_red[32];
    __shared__ float s_q[64];
    __shared__ float s_part[DTH];
    __shared__ float s_comb[128];
    __shared__ float s_xch[8][4];
    __shared__ unsigned s_base;

    const int tid  = threadIdx.x;
    const int bid  = blockIdx.x;
    const int w    = tid >> 5, lane = tid & 31;
    const int half = bid >> 6;             // 0/1: 4-batch group
    const int b0   = half * 4;
    const int wg   = (bid & 63) * 16 + w;  // 0..1023 within half
    const int kw   = w >> 3;               // split-K half (phases C/F)
    const int wr8  = w & 7;
    const int rowCF = (bid & 63) * 8 + wr8; // 0..511 output row (phases C/F)

    if (tid == 0) s_base = ld_acq(&g_bar_sense);
    __syncthreads();
    unsigned target = s_base;

    for (int step = 0; step < STEPS_; step++) {
        const int cur = S_ + step;
        const float* xt = dx + (size_t)step * (B_ * D_);

        // ===== phase A: LN2(prev) on blocks 0 & 64 + QKV GEMV =====
        if (step > 0 && (bid == 0 || bid == 64) && w < 4)
            warp_ln(t1 + (b0 + w) * 512, s_ln + w * 512, ln2w, ln2b,
                    out + ((size_t)(b0 + w) * CAP_ + (cur - 1)) * 512, lane);
        {
            const float4* src = (const float4*)(xt + b0 * 512);
            float4* dst = (float4*)xs;
            for (int i = tid; i < 512; i += DTH) dst[i] = src[i];
        }
        __syncthreads();
        {   // rows: wg (q 0-511 / k 512-1023), and wg+1024 (v) for wg<512
            float a0, a1, a2, a3;
            dot4<4>(qkvW + (size_t)wg * 512, xs, 512, lane, a0, a1, a2, a3);
            if (lane == 0) {
                const float bv = qkvB[wg];
                if (wg < 512) {
                    qt[(b0 + 0) * 512 + wg] = a0 + bv;
                    qt[(b0 + 1) * 512 + wg] = a1 + bv;
                    qt[(b0 + 2) * 512 + wg] = a2 + bv;
                    qt[(b0 + 3) * 512 + wg] = a3 + bv;
                } else {
                    const int kcol = wg - 512;
                    kc[((size_t)(b0 + 0) * CAP_ + cur) * 512 + kcol] = a0 + bv;
                    kc[((size_t)(b0 + 1) * CAP_ + cur) * 512 + kcol] = a1 + bv;
                    kc[((size_t)(b0 + 2) * CAP_ + cur) * 512 + kcol] = a2 + bv;
                    kc[((size_t)(b0 + 3) * CAP_ + cur) * 512 + kcol] = a3 + bv;
                }
            }
            if (wg < 512) {
                dot4<4>(qkvW + (size_t)(wg + 1024) * 512, xs, 512, lane, a0, a1, a2, a3);
                if (lane == 0) {
                    const float bv = qkvB[wg + 1024];
                    vc[((size_t)(b0 + 0) * CAP_ + cur) * 512 + wg] = a0 + bv;
                    vc[((size_t)(b0 + 1) * CAP_ + cur) * 512 + wg] = a1 + bv;
                    vc[((size_t)(b0 + 2) * CAP_ + cur) * 512 + wg] = a2 + bv;
                    vc[((size_t)(b0 + 3) * CAP_ + cur) * 512 + wg] = a3 + bv;
                }
            }
        }
        gbar(target, tid);

        // ===== phase B: attention partials, 128 blocks = (part, b, h) =====
        {
            const int part = bid >> 6;
            const int bb = (bid >> 3) & 7;
            const int h  = bid & 7;
            const int kvlen = cur + 1;
            const int hlen  = kvlen >> 1;
            const int tstart = part ? hlen : 0;
            const int tend   = part ? kvlen : hlen;
            if (tid < 64) s_q[tid] = qt[bb * 512 + h * 64 + tid];
            __syncthreads();
            const int tl = lane >> 2;
            const int kq = (lane & 3) * 16;
            const float4 qa = *(const float4*)(s_q + kq);
            const float4 qb = *(const float4*)(s_q + kq + 4);
            const float4 qc = *(const float4*)(s_q + kq + 8);
            const float4 qd = *(const float4*)(s_q + kq + 12);
            const float* kb = kc + (size_t)bb * CAP_ * 512 + h * 64;
            for (int t0 = tstart; t0 < tend; t0 += 128) {
                const int t = t0 + w * 8 + tl;
                const bool valid = t < tend;
                const float* kr = kb + (size_t)(valid ? t : tstart) * 512 + kq;
                float4 k0 = *(const float4*)(kr);
                float4 k1 = *(const float4*)(kr + 4);
                float4 k2 = *(const float4*)(kr + 8);
                float4 k3 = *(const float4*)(kr + 12);
                float s;
                s = k0.x * qa.x;
                s = fmaf(k0.y, qa.y, s); s = fmaf(k0.z, qa.z, s); s = fmaf(k0.w, qa.w, s);
                s = fmaf(k1.x, qb.x, s); s = fmaf(k1.y, qb.y, s);
                s = fmaf(k1.z, qb.z, s); s = fmaf(k1.w, qb.w, s);
                s = fmaf(k2.x, qc.x, s); s = fmaf(k2.y, qc.y, s);
                s = fmaf(k2.z, qc.z, s); s = fmaf(k2.w, qc.w, s);
                s = fmaf(k3.x, qd.x, s); s = fmaf(k3.y, qd.y, s);
                s = fmaf(k3.z, qd.z, s); s = fmaf(k3.w, qd.w, s);
                s += __shfl_xor_sync(0xffffffffu, s, 1);
                s += __shfl_xor_sync(0xffffffffu, s, 2);
                if (valid && (lane & 3) == 0) xs[t] = s * 0.125f;
            }
            __syncthreads();
            float lmax = -1e30f;
            for (int t = tstart + tid; t < tend; t += DTH) lmax = fmaxf(lmax, xs[t]);
            lmax = warpRedMax(lmax);
            if (lane == 0) s_red[w] = lmax;
            __syncthreads();
            float gm = s_red[0];
#pragma unroll
            for (int i = 1; i < 16; i++) gm = fmaxf(gm, s_red[i]);
            float ls = 0.f;
            for (int t = tstart + tid; t < tend; t += DTH) {
                float p = __expf(xs[t] - gm);
                xs[t] = p;
                ls += p;
            }
            ls = warpRedSum(ls);
            if (lane == 0) s_red[16 + w] = ls;
            __syncthreads();
            float ssum = 0.f;
#pragma unroll
            for (int i = 0; i < 16; i++) ssum += s_red[16 + i];
            const int d = tid & 63, pt = tid >> 6;   // 8 partials
            const float* vb = vc + (size_t)bb * CAP_ * 512 + h * 64 + d;
            float vacc = 0.f;
            for (int t = tstart + pt; t < tend; t += 8)
                vacc = fmaf(xs[t], vb[(size_t)t * 512], vacc);
            s_part[tid] = vacc;
            __syncthreads();
            const int gi = part * 64 + bb * 8 + h;
            if (pt == 0) {
                float r = 0.f;
#pragma unroll
                for (int p = 0; p < 8; p++) r += s_part[p * 64 + d];
                opart[gi * 64 + d] = r;
            }
            if (tid == 0) { mlpart[gi * 2] = gm; mlpart[gi * 2 + 1] = ssum; }
        }
        gbar(target, tid);

        // ===== phase C: combine attn parts + out-proj (split-K) =====
        if (tid < 64) {
            float m1 = mlpart[tid * 2],        l1 = mlpart[tid * 2 + 1];
            float m2 = mlpart[(64 + tid) * 2], l2 = mlpart[(64 + tid) * 2 + 1];
            float gm = fmaxf(m1, m2);
            float e1 = __expf(m1 - gm), e2 = __expf(m2 - gm);
            float inv = 1.f / (e1 * l1 + e2 * l2);
            s_comb[tid * 2]     = e1 * inv;
            s_comb[tid * 2 + 1] = e2 * inv;
        }
        __syncthreads();
        for (int i = tid; i < 2048; i += DTH) {
            const int b = b0 + (i >> 9);
            const int col = i & 511;
            const int gi = b * 8 + (col >> 6);
            const int d = col & 63;
            xs[i] = s_comb[gi * 2]     * opart[gi * 64 + d]
                  + s_comb[gi * 2 + 1] * opart[(64 + gi) * 64 + d];
        }
        __syncthreads();
        {
            float a0, a1, a2, a3;
            dot4<2>(outW + (size_t)rowCF * 512 + kw * 256, xs + kw * 256,
                    512, lane, a0, a1, a2, a3);
            if (kw == 1 && lane == 0) {
                s_xch[wr8][0] = a0; s_xch[wr8][1] = a1;
                s_xch[wr8][2] = a2; s_xch[wr8][3] = a3;
            }
            __syncthreads();
            if (kw == 0 && lane == 0) {
                const float bv = outB[rowCF];
                t1[(b0 + 0) * 512 + rowCF] = a0 + s_xch[wr8][0] + bv;
                t1[(b0 + 1) * 512 + rowCF] = a1 + s_xch[wr8][1] + bv;
                t1[(b0 + 2) * 512 + rowCF] = a2 + s_xch[wr8][2] + bv;
                t1[(b0 + 3) * 512 + rowCF] = a3 + s_xch[wr8][3] + bv;
            }
        }
        gbar(target, tid);

        // ===== phase E: LN1 (warps 0-3, into s_ln) + FF1 (N=2048, relu) =====
        if (w < 4)
            warp_ln(t1 + (b0 + w) * 512, xt + (b0 + w) * 512,
                    ln1w, ln1b, s_ln + w * 512, lane);
        __syncthreads();
#pragma unroll
        for (int o = 0; o < 2; o++) {
            const int n = wg + o * 1024;
            float a0, a1, a2, a3;
            dot4<4>(w1 + (size_t)n * 512, s_ln, 512, lane, a0, a1, a2, a3);
            if (lane == 0) {
                const float bv = b1[n];
                hfft[(b0 + 0) * 2048 + n] = fmaxf(a0 + bv, 0.f);
                hfft[(b0 + 1) * 2048 + n] = fmaxf(a1 + bv, 0.f);
                hfft[(b0 + 2) * 2048 + n] = fmaxf(a2 + bv, 0.f);
                hfft[(b0 + 3) * 2048 + n] = fmaxf(a3 + bv, 0.f);
            }
        }
        gbar(target, tid);

        // ===== phase F: FF2 (N=512, K=2048, split-K) -> t1 =====
        {
            const float4* src = (const float4*)(hfft + b0 * 2048);
            float4* dst = (float4*)xs;
            for (int i = tid; i < 2048; i += DTH) dst[i] = src[i];
        }
        __syncthreads();
        {
            float a0, a1, a2, a3;
            dot4<8>(w2 + (size_t)rowCF * 2048 + kw * 1024, xs + kw * 1024,
                    2048, lane, a0, a1, a2, a3);
            if (kw == 1 && lane == 0) {
                s_xch[wr8][0] = a0; s_xch[wr8][1] = a1;
                s_xch[wr8][2] = a2; s_xch[wr8][3] = a3;
            }
            __syncthreads();
            if (kw == 0 && lane == 0) {
                const float bv = b2[rowCF];
                t1[(b0 + 0) * 512 + rowCF] = a0 + s_xch[wr8][0] + bv;
                t1[(b0 + 1) * 512 + rowCF] = a1 + s_xch[wr8][1] + bv;
                t1[(b0 + 2) * 512 + rowCF] = a2 + s_xch[wr8][2] + bv;
                t1[(b0 + 3) * 512 + rowCF] = a3 + s_xch[wr8][3] + bv;
            }
        }
        gbar(target, tid);
    }

    // final LN2 for the last step
    if ((bid == 0 || bid == 64) && w < 4)
        warp_ln(t1 + (b0 + w) * 512, s_ln + w * 512, ln2w, ln2b,
                out + ((size_t)(b0 + w) * CAP_ + (S_ + STEPS_ - 1)) * 512, lane);
}

// ---------------- host launcher ----------------
struct ScratchPtrs {
    float *Qkv, *Attn, *Pre, *Hb, *Hff, *Kc, *Vc, *Qt, *Hfft, *T1, *Op, *Ml;
};

static const ScratchPtrs& get_scratch() {
    static ScratchPtrs p;
    static bool init = false;
    if (!init) {
        cudaGetSymbolAddress((void**)&p.Qkv,  g_qkv);
        cudaGetSymbolAddress((void**)&p.Attn, g_attn);
        cudaGetSymbolAddress((void**)&p.Pre,  g_pre);
        cudaGetSymbolAddress((void**)&p.Hb,   g_h);
        cudaGetSymbolAddress((void**)&p.Hff,  g_hff);
        cudaGetSymbolAddress((void**)&p.Kc,   g_kc);
        cudaGetSymbolAddress((void**)&p.Vc,   g_vc);
        cudaGetSymbolAddress((void**)&p.Qt,   g_qt);
        cudaGetSymbolAddress((void**)&p.Hfft, g_hfft);
        cudaGetSymbolAddress((void**)&p.T1,   g_t1);
        cudaGetSymbolAddress((void**)&p.Op,   g_op);
        cudaGetSymbolAddress((void**)&p.Ml,   g_ml);
        cudaFuncSetAttribute(attn_prefill,
                             cudaFuncAttributeMaxDynamicSharedMemorySize, 49408);
        cudaFuncSetAttribute(decode_mega,
                             cudaFuncAttributeMaxDynamicSharedMemorySize, 32768);
        init = true;
    }
    return p;
}

extern "C" void kernel_launch(void* const* d_in, const int* in_sizes, int n_in,
                              void* d_out, int out_size)
{
    (void)in_sizes; (void)n_in; (void)out_size;
    const float* x    = (const float*)d_in[0];
    const float* dx   = (const float*)d_in[1];
    // d_in[2] = causal_mask (bool) — unused, causality computed analytically
    const float* qkvW = (const float*)d_in[3];
    const float* qkvB = (const float*)d_in[4];
    const float* outW = (const float*)d_in[5];
    const float* outB = (const float*)d_in[6];
    const float* w1   = (const float*)d_in[7];
    const float* b1   = (const float*)d_in[8];
    const float* w2   = (const float*)d_in[9];
    const float* b2   = (const float*)d_in[10];
    const float* ln1w = (const float*)d_in[11];
    const float* ln1b = (const float*)d_in[12];
    const float* ln2w = (const float*)d_in[13];
    const float* ln2b = (const float*)d_in[14];
    float* out = (float*)d_out;

    const ScratchPtrs& sp = get_scratch();

    // ---- prefill ----
    sgemm_nt<1,0,0><<<dim3(12, 64), 256>>>(x, qkvW, qkvB, nullptr, sp.Qkv, MTOK, 1536, 512);
    copy_kv<<<MTOK, 128>>>(sp.Qkv, sp.Kc, sp.Vc);
    attn_prefill<<<dim3(16, 64), 256, 49408>>>(sp.Qkv, sp.Attn);
    sgemm_nt<1,0,1><<<dim3(4, 64), 256>>>(sp.Attn, outW, outB, x, sp.Pre, MTOK, 512, 512);
    ln_rows<<<MTOK, 256>>>(sp.Pre, ln1w, ln1b, sp.Hb, 0);
    sgemm_nt<1,1,0><<<dim3(16, 64), 256>>>(sp.Hb, w1, b1, nullptr, sp.Hff, MTOK, 2048, 512);
    sgemm_nt<1,0,1><<<dim3(4, 64), 256>>>(sp.Hff, w2, b2, sp.Hb, sp.Pre, MTOK, 512, 2048);
    ln_rows<<<MTOK, 256>>>(sp.Pre, ln2w, ln2b, out, 64);

    // ---- decode: all 64 steps in one persistent launch ----
    decode_mega<<<NBLK, DTH, 32768>>>(dx, qkvW, qkvB, outW, outB,
                                      w1, b1, w2, b2,
                                      ln1w, ln1b, ln2w, ln2b, out,
                                      sp.Qt, sp.Kc, sp.Vc,
                                      sp.Hfft, sp.T1, sp.Op, sp.Ml);
}

// round 7
// speedup vs baseline: 1.0436x; 1.0436x over previous
#include <cuda_runtime.h>
#include <cstdint>

#define B_     8
#define S_     1024
#define D_     512
#define H_     8
#define HD_    64
#define FF_    2048
#define STEPS_ 64
#define CAP_   1088
#define MTOK   (B_*S_)   /* 8192 */
#define NBLK   128

// ---------------- device scratch (no cudaMalloc allowed) ----------------
__device__ float g_qkv [MTOK*1536];
__device__ float g_attn[MTOK*D_];
__device__ float g_pre [MTOK*D_];
__device__ float g_h   [MTOK*D_];
__device__ float g_hff [MTOK*FF_];
__device__ float g_kc  [B_*CAP_*D_];
__device__ float g_vc  [B_*CAP_*D_];
__device__ float g_qt  [B_*D_];
__device__ float g_hfft[B_*FF_];
__device__ float g_t1  [B_*D_];
__device__ float g_op  [2*64*64];
__device__ float g_ml  [2*64*2];
__device__ unsigned g_bar_count;
__device__ unsigned g_bar_sense;

// ---------------- reductions ----------------
__device__ __forceinline__ float warpRedSum(float v) {
#pragma unroll
    for (int o = 16; o; o >>= 1) v += __shfl_xor_sync(0xffffffffu, v, o);
    return v;
}
__device__ __forceinline__ float warpRedMax(float v) {
#pragma unroll
    for (int o = 16; o; o >>= 1) v = fmaxf(v, __shfl_xor_sync(0xffffffffu, v, o));
    return v;
}

// ---------------- fence-free global barrier (cooperative-groups pattern) ----
// No __threadfence -> no CCTL.IVALL -> weights stay L1-resident across steps.
// All cross-block data uses .cg (L2) loads/stores, so L1 staleness is moot.
__device__ __forceinline__ unsigned ld_acq(const unsigned* p) {
    unsigned v;
    asm volatile("ld.acquire.gpu.u32 %0, [%1];" : "=r"(v) : "l"(p) : "memory");
    return v;
}
__device__ __forceinline__ void st_rel(unsigned* p, unsigned v) {
    asm volatile("st.release.gpu.u32 [%0], %1;" :: "l"(p), "r"(v) : "memory");
}
__device__ __forceinline__ unsigned atomAddAcqRel(unsigned* p, unsigned v) {
    unsigned old;
    asm volatile("atom.acq_rel.gpu.global.add.u32 %0, [%1], %2;"
                 : "=r"(old) : "l"(p), "r"(v) : "memory");
    return old;
}
__device__ __forceinline__ void gbar(unsigned& target, int tid) {
    __syncthreads();                 // CTA-scope ordering of all block's work
    target += 1;
    if (tid == 0) {
        unsigned a = atomAddAcqRel(&g_bar_count, 1u) + 1u;
        if (a == (unsigned)NBLK) {
            atomicExch(&g_bar_count, 0u);
            st_rel(&g_bar_sense, target);
        } else {
            while ((int)(ld_acq(&g_bar_sense) - target) < 0) { }
        }
    }
    __syncthreads();
}

// ---------------- SGEMM (NT), register-prefetch (round-5 proven version) ----
// KVOUT: additionally scatter K/V columns into the decode caches (QKV GEMM).
template<int BIAS, int RELU, int RES, int KVOUT>
__global__ void __launch_bounds__(256, 2) sgemm_nt(
    const float* __restrict__ A, const float* __restrict__ Bm,
    const float* __restrict__ bias, const float* __restrict__ R,
    float* __restrict__ C, int M, int N, int K,
    float* __restrict__ kc, float* __restrict__ vc)
{
    __shared__ float As[16][132];
    __shared__ float Bs[16][132];
    const int tid = threadIdx.x;
    const int m0 = blockIdx.y * 128;
    const int n0 = blockIdx.x * 128;
    const int tx = tid & 15, ty = tid >> 4;
    const int r0 = ty * 4, c0 = tx * 4;
    const int lrow = tid >> 2;
    const int lk4  = (tid & 3) * 4;

    const float* Ap0 = A  + (size_t)(m0 + lrow)      * K + lk4;
    const float* Ap1 = A  + (size_t)(m0 + lrow + 64) * K + lk4;
    const float* Bp0 = Bm + (size_t)(n0 + lrow)      * K + lk4;
    const float* Bp1 = Bm + (size_t)(n0 + lrow + 64) * K + lk4;

    float acc[8][8];
#pragma unroll
    for (int i = 0; i < 8; i++)
#pragma unroll
        for (int j = 0; j < 8; j++) acc[i][j] = 0.f;

    float4 pa0 = *(const float4*)(Ap0);
    float4 pa1 = *(const float4*)(Ap1);
    float4 pb0 = *(const float4*)(Bp0);
    float4 pb1 = *(const float4*)(Bp1);

    for (int k0 = 0; k0 < K; k0 += 16) {
        As[lk4 + 0][lrow]      = pa0.x; As[lk4 + 1][lrow]      = pa0.y;
        As[lk4 + 2][lrow]      = pa0.z; As[lk4 + 3][lrow]      = pa0.w;
        As[lk4 + 0][lrow + 64] = pa1.x; As[lk4 + 1][lrow + 64] = pa1.y;
        As[lk4 + 2][lrow + 64] = pa1.z; As[lk4 + 3][lrow + 64] = pa1.w;
        Bs[lk4 + 0][lrow]      = pb0.x; Bs[lk4 + 1][lrow]      = pb0.y;
        Bs[lk4 + 2][lrow]      = pb0.z; Bs[lk4 + 3][lrow]      = pb0.w;
        Bs[lk4 + 0][lrow + 64] = pb1.x; Bs[lk4 + 1][lrow + 64] = pb1.y;
        Bs[lk4 + 2][lrow + 64] = pb1.z; Bs[lk4 + 3][lrow + 64] = pb1.w;
        __syncthreads();
        if (k0 + 16 < K) {
            pa0 = *(const float4*)(Ap0 + k0 + 16);
            pa1 = *(const float4*)(Ap1 + k0 + 16);
            pb0 = *(const float4*)(Bp0 + k0 + 16);
            pb1 = *(const float4*)(Bp1 + k0 + 16);
        }
#pragma unroll
        for (int kk = 0; kk < 16; kk++) {
            float af[8], bf[8];
            *(float4*)(af)     = *(const float4*)(&As[kk][r0]);
            *(float4*)(af + 4) = *(const float4*)(&As[kk][r0 + 64]);
            *(float4*)(bf)     = *(const float4*)(&Bs[kk][c0]);
            *(float4*)(bf + 4) = *(const float4*)(&Bs[kk][c0 + 64]);
#pragma unroll
            for (int i = 0; i < 8; i++)
#pragma unroll
                for (int j = 0; j < 8; j++)
                    acc[i][j] = fmaf(af[i], bf[j], acc[i][j]);
        }
        __syncthreads();
    }

    float bl[8];
#pragma unroll
    for (int j = 0; j < 8; j++)
        bl[j] = BIAS ? bias[n0 + c0 + (j < 4 ? j : 60 + j)] : 0.f;

#pragma unroll
    for (int i = 0; i < 8; i++) {
        const int row = m0 + r0 + (i < 4 ? i : 60 + i);
        const size_t rowoff = (size_t)row * N + n0;
#pragma unroll
        for (int jg = 0; jg < 2; jg++) {
            const int cb = c0 + jg * 64;
            float t0 = acc[i][jg * 4 + 0] + bl[jg * 4 + 0];
            float t1 = acc[i][jg * 4 + 1] + bl[jg * 4 + 1];
            float t2 = acc[i][jg * 4 + 2] + bl[jg * 4 + 2];
            float t3 = acc[i][jg * 4 + 3] + bl[jg * 4 + 3];
            if (RES) {
                float4 r = *(const float4*)(R + rowoff + cb);
                t0 += r.x; t1 += r.y; t2 += r.z; t3 += r.w;
            }
            if (RELU) {
                t0 = fmaxf(t0, 0.f); t1 = fmaxf(t1, 0.f);
                t2 = fmaxf(t2, 0.f); t3 = fmaxf(t3, 0.f);
            }
            float4 v; v.x = t0; v.y = t1; v.z = t2; v.w = t3;
            *(float4*)(C + rowoff + cb) = v;
            if (KVOUT) {
                const int ncol = n0 + cb;
                if (ncol >= 512) {
                    const int bb = row >> 10, ss = row & 1023;
                    float* dst = (ncol < 1024)
                        ? kc + ((size_t)(bb * CAP_ + ss) * 512 + (ncol - 512))
                        : vc + ((size_t)(bb * CAP_ + ss) * 512 + (ncol - 1024));
                    *(float4*)dst = v;
                }
            }
        }
    }
}

// ---------------- prefill flash attention (causal), 64x64 tiles ----------------
__global__ void __launch_bounds__(256) attn_prefill(const float* __restrict__ qkv,
                                                    float* __restrict__ attn)
{
    extern __shared__ float sm[];
    float* Qs = sm;
    float* KP = sm + 64 * 64;
    float* Vs = KP + 64 * 65;

    const int b  = blockIdx.y >> 3;
    const int h  = blockIdx.y & 7;
    const int l0 = blockIdx.x * 64;
    const int tid = threadIdx.x;
    const int tx = tid & 15, ty = tid >> 4;
    const int r0 = ty * 4, c0 = tx * 4;

    const size_t rowbase = (size_t)(b * S_) * 1536;
    const float* qbase = qkv + rowbase + h * 64;
    const float* kbase = qkv + rowbase + 512 + h * 64;
    const float* vbase = qkv + rowbase + 1024 + h * 64;

    const int lt  = tid >> 4;
    const int ld4 = (tid & 15) * 4;

#pragma unroll
    for (int tt = lt; tt < 64; tt += 16) {
        float4 q4 = *(const float4*)(qbase + (size_t)(l0 + tt) * 1536 + ld4);
        Qs[(ld4 + 0) * 64 + tt] = q4.x;
        Qs[(ld4 + 1) * 64 + tt] = q4.y;
        Qs[(ld4 + 2) * 64 + tt] = q4.z;
        Qs[(ld4 + 3) * 64 + tt] = q4.w;
    }

    float o[4][4];
    float mrow[4], lrow[4];
#pragma unroll
    for (int i = 0; i < 4; i++) {
        mrow[i] = -1e30f; lrow[i] = 0.f;
#pragma unroll
        for (int j = 0; j < 4; j++) o[i][j] = 0.f;
    }

    const int ntiles = (l0 >> 6) + 1;
    for (int tile = 0; tile < ntiles; ++tile) {
        const int j0 = tile * 64;
        __syncthreads();
#pragma unroll
        for (int tt = lt; tt < 64; tt += 16) {
            float4 k4 = *(const float4*)(kbase + (size_t)(j0 + tt) * 1536 + ld4);
            KP[(ld4 + 0) * 65 + tt] = k4.x;
            KP[(ld4 + 1) * 65 + tt] = k4.y;
            KP[(ld4 + 2) * 65 + tt] = k4.z;
            KP[(ld4 + 3) * 65 + tt] = k4.w;
            float4 v4 = *(const float4*)(vbase + (size_t)(j0 + tt) * 1536 + ld4);
            *(float4*)(Vs + tt * 64 + ld4) = v4;
        }
        __syncthreads();

        float s[4][4];
#pragma unroll
        for (int i = 0; i < 4; i++)
#pragma unroll
            for (int j = 0; j < 4; j++) s[i][j] = 0.f;

        for (int d = 0; d < 64; d++) {
            float qf[4];
            *(float4*)qf = *(const float4*)(Qs + d * 64 + r0);
            float kf0 = KP[d * 65 + c0 + 0];
            float kf1 = KP[d * 65 + c0 + 1];
            float kf2 = KP[d * 65 + c0 + 2];
            float kf3 = KP[d * 65 + c0 + 3];
#pragma unroll
            for (int i = 0; i < 4; i++) {
                s[i][0] = fmaf(qf[i], kf0, s[i][0]);
                s[i][1] = fmaf(qf[i], kf1, s[i][1]);
                s[i][2] = fmaf(qf[i], kf2, s[i][2]);
                s[i][3] = fmaf(qf[i], kf3, s[i][3]);
            }
        }

        if (j0 == l0) {
#pragma unroll
            for (int i = 0; i < 4; i++)
#pragma unroll
                for (int j = 0; j < 4; j++)
                    s[i][j] = (j0 + c0 + j > l0 + r0 + i) ? -1e30f : s[i][j] * 0.125f;
        } else {
#pragma unroll
            for (int i = 0; i < 4; i++)
#pragma unroll
                for (int j = 0; j < 4; j++) s[i][j] *= 0.125f;
        }

        float p[4][4];
#pragma unroll
        for (int i = 0; i < 4; i++) {
            float rm = fmaxf(fmaxf(s[i][0], s[i][1]), fmaxf(s[i][2], s[i][3]));
#pragma unroll
            for (int off = 8; off; off >>= 1)
                rm = fmaxf(rm, __shfl_xor_sync(0xffffffffu, rm, off));
            float mnew  = fmaxf(mrow[i], rm);
            float alpha = __expf(mrow[i] - mnew);
            float ps = 0.f;
#pragma unroll
            for (int j = 0; j < 4; j++) { p[i][j] = __expf(s[i][j] - mnew); ps += p[i][j]; }
#pragma unroll
            for (int off = 8; off; off >>= 1)
                ps += __shfl_xor_sync(0xffffffffu, ps, off);
            lrow[i] = lrow[i] * alpha + ps;
            mrow[i] = mnew;
#pragma unroll
            for (int j = 0; j < 4; j++) o[i][j] *= alpha;
        }

        __syncthreads();
#pragma unroll
        for (int i = 0; i < 4; i++)
#pragma unroll
            for (int j = 0; j < 4; j++)
                KP[(r0 + i) * 65 + c0 + j] = p[i][j];
        __syncthreads();

        for (int c = 0; c < 64; c++) {
            float vv[4];
            *(float4*)vv = *(const float4*)(Vs + c * 64 + c0);
            float p0 = KP[(r0 + 0) * 65 + c];
            float p1 = KP[(r0 + 1) * 65 + c];
            float p2 = KP[(r0 + 2) * 65 + c];
            float p3 = KP[(r0 + 3) * 65 + c];
#pragma unroll
            for (int j = 0; j < 4; j++) {
                o[0][j] = fmaf(p0, vv[j], o[0][j]);
                o[1][j] = fmaf(p1, vv[j], o[1][j]);
                o[2][j] = fmaf(p2, vv[j], o[2][j]);
                o[3][j] = fmaf(p3, vv[j], o[3][j]);
            }
        }
    }

    float* ob = attn + (size_t)(b * S_ + l0) * 512 + h * 64;
#pragma unroll
    for (int i = 0; i < 4; i++) {
        float inv = 1.f / lrow[i];
        float4 v;
        v.x = o[i][0] * inv; v.y = o[i][1] * inv;
        v.z = o[i][2] * inv; v.w = o[i][3] * inv;
        *(float4*)(ob + (size_t)(r0 + i) * 512 + c0) = v;
    }
}

// ---------------- prefill LayerNorm over rows of 512 ----------------
__global__ void __launch_bounds__(256) ln_rows(const float* __restrict__ in,
                                               const float* __restrict__ g,
                                               const float* __restrict__ be,
                                               float* __restrict__ out, int outExtra)
{
    const int r = blockIdx.x;
    const int tid = threadIdx.x;
    const float* row = in + (size_t)r * 512;
    float v0 = row[tid], v1 = row[tid + 256];
    float s  = warpRedSum(v0 + v1);
    float s2 = warpRedSum(v0 * v0 + v1 * v1);
    __shared__ float r1[8], r2[8];
    __shared__ float smu, srs;
    const int w = tid >> 5, lane = tid & 31;
    if (lane == 0) { r1[w] = s; r2[w] = s2; }
    __syncthreads();
    if (tid == 0) {
        float S = 0.f, S2 = 0.f;
#pragma unroll
        for (int i = 0; i < 8; i++) { S += r1[i]; S2 += r2[i]; }
        float mu  = S * (1.f / 512.f);
        float var = S2 * (1.f / 512.f) - mu * mu;
        smu = mu; srs = rsqrtf(var + 1e-5f);
    }
    __syncthreads();
    const int orow = r + (r >> 10) * outExtra;
    float* od = out + (size_t)orow * 512;
    od[tid]       = (v0 - smu) * srs * g[tid]       + be[tid];
    od[tid + 256] = (v1 - smu) * srs * g[tid + 256] + be[tid + 256];
}

// ---------------- megakernel building blocks ----------------
// weights via plain (L1-cached) loads; x from smem
template<int KP>
__device__ __forceinline__ void dot4(const float* __restrict__ wr,
                                     const float* xs, int Kstride, int lane,
                                     float& a0, float& a1, float& a2, float& a3)
{
    a0 = a1 = a2 = a3 = 0.f;
#pragma unroll
    for (int kp = 0; kp < KP; kp++) {
        const int k4 = kp * 128 + lane * 4;
        float4 wv = *(const float4*)(wr + k4);
        float4 x0 = *(const float4*)(xs + k4);
        float4 x1 = *(const float4*)(xs + Kstride + k4);
        float4 x2 = *(const float4*)(xs + 2 * Kstride + k4);
        float4 x3 = *(const float4*)(xs + 3 * Kstride + k4);
        a0 = fmaf(wv.x, x0.x, fmaf(wv.y, x0.y, fmaf(wv.z, x0.z, fmaf(wv.w, x0.w, a0))));
        a1 = fmaf(wv.x, x1.x, fmaf(wv.y, x1.y, fmaf(wv.z, x1.z, fmaf(wv.w, x1.w, a1))));
        a2 = fmaf(wv.x, x2.x, fmaf(wv.y, x2.y, fmaf(wv.z, x2.z, fmaf(wv.w, x2.w, a2))));
        a3 = fmaf(wv.x, x3.x, fmaf(wv.y, x3.y, fmaf(wv.z, x3.z, fmaf(wv.w, x3.w, a3))));
    }
    a0 = warpRedSum(a0); a1 = warpRedSum(a1);
    a2 = warpRedSum(a2); a3 = warpRedSum(a3);
}

// per-warp LN; 'a' is cross-block global (read .cg), 'r' is smem or private global
__device__ __forceinline__ void warp_ln(const float* __restrict__ a,
                                        const float* r,
                                        const float* __restrict__ gw,
                                        const float* __restrict__ gb,
                                        float* o, int lane)
{
    float vals[16];
    float sv = 0.f, sq = 0.f;
#pragma unroll
    for (int g = 0; g < 4; g++) {
        const int idx = g * 128 + lane * 4;
        float4 av = __ldcg((const float4*)(a + idx));
        float4 rv = *(const float4*)(r + idx);
        float a0 = av.x + rv.x, a1 = av.y + rv.y;
        float a2 = av.z + rv.z, a3 = av.w + rv.w;
        vals[g * 4 + 0] = a0; vals[g * 4 + 1] = a1;
        vals[g * 4 + 2] = a2; vals[g * 4 + 3] = a3;
        sv += a0 + a1 + a2 + a3;
        sq += a0 * a0 + a1 * a1 + a2 * a2 + a3 * a3;
    }
    sv = warpRedSum(sv); sq = warpRedSum(sq);
    float mu = sv * (1.f / 512.f);
    float rs = rsqrtf(sq * (1.f / 512.f) - mu * mu + 1e-5f);
#pragma unroll
    for (int g = 0; g < 4; g++)
#pragma unroll
        for (int j = 0; j < 4; j++) {
            const int idx = g * 128 + lane * 4 + j;
            o[idx] = (vals[g * 4 + j] - mu) * rs * gw[idx] + gb[idx];
        }
}

// ---------------- decode megakernel (round-5 skeleton + L1-preserving sync) ---
__global__ void __launch_bounds__(256, 1) decode_mega(
    const float* __restrict__ dx,
    const float* __restrict__ qkvW, const float* __restrict__ qkvB,
    const float* __restrict__ outW, const float* __restrict__ outB,
    const float* __restrict__ w1, const float* __restrict__ b1,
    const float* __restrict__ w2, const float* __restrict__ b2,
    const float* __restrict__ ln1w, const float* __restrict__ ln1b,
    const float* __restrict__ ln2w, const float* __restrict__ ln2b,
    float* __restrict__ out,
    float* __restrict__ qt, float* __restrict__ kc, float* __restrict__ vc,
    float* __restrict__ hfft, float* __restrict__ t1,
    float* __restrict__ opart, float* __restrict__ mlpart)
{
    extern __shared__ float xs[];      // 8192 floats (32KB)
    __shared__ float s_ln[4 * 512];
    __shared__ float s_red[16];
    __shared__ float s_q[64];
    __shared__ float s_part[256];
    __shared__ float s_comb[128];
    __shared__ unsigned s_base;

    const int tid  = threadIdx.x;
    const int bid  = blockIdx.x;
    const int w    = tid >> 5, lane = tid & 31;
    const int half = bid >> 6;
    const int b0   = half * 4;
    const int wg   = (bid & 63) * 8 + w;

    if (tid == 0) s_base = ld_acq(&g_bar_sense);
    __syncthreads();
    unsigned target = s_base;

    for (int step = 0; step < STEPS_; step++) {
        const int cur = S_ + step;
        const float* xt = dx + (size_t)step * (B_ * D_);

        // ===== phase A: LN2(prev) on blocks 0 & 64 + QKV GEMV =====
        if (step > 0 && (bid == 0 || bid == 64) && w < 4)
            warp_ln(t1 + (b0 + w) * 512, s_ln + w * 512, ln2w, ln2b,
                    out + ((size_t)(b0 + w) * CAP_ + (cur - 1)) * 512, lane);
        {
            const float4* src = (const float4*)(xt + b0 * 512);
            float4* dst = (float4*)xs;
            for (int i = tid; i < 512; i += 256) dst[i] = src[i];
        }
        __syncthreads();
#pragma unroll
        for (int o = 0; o < 3; o++) {
            const int n = wg + o * 512;
            float a0, a1, a2, a3;
            dot4<4>(qkvW + (size_t)n * 512, xs, 512, lane, a0, a1, a2, a3);
            if (lane == 0) {
                const float bv = qkvB[n];
                if (o == 0) {
                    __stcg(&qt[(b0 + 0) * 512 + wg], a0 + bv);
                    __stcg(&qt[(b0 + 1) * 512 + wg], a1 + bv);
                    __stcg(&qt[(b0 + 2) * 512 + wg], a2 + bv);
                    __stcg(&qt[(b0 + 3) * 512 + wg], a3 + bv);
                } else if (o == 1) {
                    __stcg(&kc[((size_t)(b0 + 0) * CAP_ + cur) * 512 + wg], a0 + bv);
                    __stcg(&kc[((size_t)(b0 + 1) * CAP_ + cur) * 512 + wg], a1 + bv);
                    __stcg(&kc[((size_t)(b0 + 2) * CAP_ + cur) * 512 + wg], a2 + bv);
                    __stcg(&kc[((size_t)(b0 + 3) * CAP_ + cur) * 512 + wg], a3 + bv);
                } else {
                    __stcg(&vc[((size_t)(b0 + 0) * CAP_ + cur) * 512 + wg], a0 + bv);
                    __stcg(&vc[((size_t)(b0 + 1) * CAP_ + cur) * 512 + wg], a1 + bv);
                    __stcg(&vc[((size_t)(b0 + 2) * CAP_ + cur) * 512 + wg], a2 + bv);
                    __stcg(&vc[((size_t)(b0 + 3) * CAP_ + cur) * 512 + wg], a3 + bv);
                }
            }
        }
        gbar(target, tid);

        // ===== phase B: attention partials, 128 blocks = (part, b, h) =====
        {
            const int part = bid >> 6;
            const int bb = (bid >> 3) & 7;
            const int h  = bid & 7;
            const int kvlen = cur + 1;
            const int hlen  = kvlen >> 1;
            const int tstart = part ? hlen : 0;
            const int tend   = part ? kvlen : hlen;
            if (tid < 64) s_q[tid] = __ldcg(&qt[bb * 512 + h * 64 + tid]);
            __syncthreads();
            const int tl = lane >> 2;
            const int kq = (lane & 3) * 16;
            const float4 qa = *(const float4*)(s_q + kq);
            const float4 qb = *(const float4*)(s_q + kq + 4);
            const float4 qc = *(const float4*)(s_q + kq + 8);
            const float4 qd = *(const float4*)(s_q + kq + 12);
            const float* kb = kc + (size_t)bb * CAP_ * 512 + h * 64;
            for (int t0 = tstart; t0 < tend; t0 += 64) {
                const int t = t0 + w * 8 + tl;
                const bool valid = t < tend;
                const float* kr = kb + (size_t)(valid ? t : tstart) * 512 + kq;
                float4 k0 = __ldcg((const float4*)(kr));
                float4 k1 = __ldcg((const float4*)(kr + 4));
                float4 k2 = __ldcg((const float4*)(kr + 8));
                float4 k3 = __ldcg((const float4*)(kr + 12));
                float s;
                s = k0.x * qa.x;
                s = fmaf(k0.y, qa.y, s); s = fmaf(k0.z, qa.z, s); s = fmaf(k0.w, qa.w, s);
                s = fmaf(k1.x, qb.x, s); s = fmaf(k1.y, qb.y, s);
                s = fmaf(k1.z, qb.z, s); s = fmaf(k1.w, qb.w, s);
                s = fmaf(k2.x, qc.x, s); s = fmaf(k2.y, qc.y, s);
                s = fmaf(k2.z, qc.z, s); s = fmaf(k2.w, qc.w, s);
                s = fmaf(k3.x, qd.x, s); s = fmaf(k3.y, qd.y, s);
                s = fmaf(k3.z, qd.z, s); s = fmaf(k3.w, qd.w, s);
                s += __shfl_xor_sync(0xffffffffu, s, 1);
                s += __shfl_xor_sync(0xffffffffu, s, 2);
                if (valid && (lane & 3) == 0) xs[t] = s * 0.125f;
            }
            __syncthreads();
            float lmax = -1e30f;
            for (int t = tstart + tid; t < tend; t += 256) lmax = fmaxf(lmax, xs[t]);
            lmax = warpRedMax(lmax);
            if (lane == 0) s_red[w] = lmax;
            __syncthreads();
            float gm = s_red[0];
#pragma unroll
            for (int i = 1; i < 8; i++) gm = fmaxf(gm, s_red[i]);
            float ls = 0.f;
            for (int t = tstart + tid; t < tend; t += 256) {
                float p = __expf(xs[t] - gm);
                xs[t] = p;
                ls += p;
            }
            ls = warpRedSum(ls);
            if (lane == 0) s_red[8 + w] = ls;
            __syncthreads();
            float ssum = 0.f;
#pragma unroll
            for (int i = 0; i < 8; i++) ssum += s_red[8 + i];
            const int d = tid & 63, pt = tid >> 6;
            const float* vb = vc + (size_t)bb * CAP_ * 512 + h * 64 + d;
            float vacc = 0.f;
            for (int t = tstart + pt; t < tend; t += 4)
                vacc = fmaf(xs[t], __ldcg(vb + (size_t)t * 512), vacc);
            s_part[tid] = vacc;
            __syncthreads();
            const int gi = part * 64 + bb * 8 + h;
            if (pt == 0)
                __stcg(&opart[gi * 64 + d],
                       s_part[d] + s_part[64 + d] + s_part[128 + d] + s_part[192 + d]);
            if (tid == 0) {
                __stcg(&mlpart[gi * 2], gm);
                __stcg(&mlpart[gi * 2 + 1], ssum);
            }
        }
        gbar(target, tid);

        // ===== phase C: combine attn parts + out-proj =====
        if (tid < 64) {
            float m1 = __ldcg(&mlpart[tid * 2]);
            float l1 = __ldcg(&mlpart[tid * 2 + 1]);
            float m2 = __ldcg(&mlpart[(64 + tid) * 2]);
            float l2 = __ldcg(&mlpart[(64 + tid) * 2 + 1]);
            float gm = fmaxf(m1, m2);
            float e1 = __expf(m1 - gm), e2 = __expf(m2 - gm);
            float inv = 1.f / (e1 * l1 + e2 * l2);
            s_comb[tid * 2]     = e1 * inv;
            s_comb[tid * 2 + 1] = e2 * inv;
        }
        __syncthreads();
        for (int i = tid; i < 2048; i += 256) {
            const int b = b0 + (i >> 9);
            const int col = i & 511;
            const int gi = b * 8 + (col >> 6);
            const int d = col & 63;
            xs[i] = s_comb[gi * 2]     * __ldcg(&opart[gi * 64 + d])
                  + s_comb[gi * 2 + 1] * __ldcg(&opart[(64 + gi) * 64 + d]);
        }
        __syncthreads();
        {
            float a0, a1, a2, a3;
            dot4<4>(outW + (size_t)wg * 512, xs, 512, lane, a0, a1, a2, a3);
            if (lane == 0) {
                const float bv = outB[wg];
                __stcg(&t1[(b0 + 0) * 512 + wg], a0 + bv);
                __stcg(&t1[(b0 + 1) * 512 + wg], a1 + bv);
                __stcg(&t1[(b0 + 2) * 512 + wg], a2 + bv);
                __stcg(&t1[(b0 + 3) * 512 + wg], a3 + bv);
            }
        }
        gbar(target, tid);

        // ===== phase E: LN1 (warps 0-3, into s_ln) + FF1 (N=2048, relu) =====
        if (w < 4)
            warp_ln(t1 + (b0 + w) * 512, xt + (b0 + w) * 512,
                    ln1w, ln1b, s_ln + w * 512, lane);
        __syncthreads();
#pragma unroll
        for (int o = 0; o < 4; o++) {
            const int n = wg + o * 512;
            float a0, a1, a2, a3;
            dot4<4>(w1 + (size_t)n * 512, s_ln, 512, lane, a0, a1, a2, a3);
            if (lane == 0) {
                const float bv = b1[n];
                __stcg(&hfft[(b0 + 0) * 2048 + n], fmaxf(a0 + bv, 0.f));
                __stcg(&hfft[(b0 + 1) * 2048 + n], fmaxf(a1 + bv, 0.f));
                __stcg(&hfft[(b0 + 2) * 2048 + n], fmaxf(a2 + bv, 0.f));
                __stcg(&hfft[(b0 + 3) * 2048 + n], fmaxf(a3 + bv, 0.f));
            }
        }
        gbar(target, tid);

        // ===== phase F: FF2 (N=512, K=2048) -> t1 =====
        {
            const float4* src = (const float4*)(hfft + b0 * 2048);
            float4* dst = (float4*)xs;
            for (int i = tid; i < 2048; i += 256) dst[i] = __ldcg(src + i);
        }
        __syncthreads();
        {
            float a0, a1, a2, a3;
            dot4<16>(w2 + (size_t)wg * 2048, xs, 2048, lane, a0, a1, a2, a3);
            if (lane == 0) {
                const float bv = b2[wg];
                __stcg(&t1[(b0 + 0) * 512 + wg], a0 + bv);
                __stcg(&t1[(b0 + 1) * 512 + wg], a1 + bv);
                __stcg(&t1[(b0 + 2) * 512 + wg], a2 + bv);
                __stcg(&t1[(b0 + 3) * 512 + wg], a3 + bv);
            }
        }
        gbar(target, tid);
    }

    // final LN2 for the last step
    if ((bid == 0 || bid == 64) && w < 4)
        warp_ln(t1 + (b0 + w) * 512, s_ln + w * 512, ln2w, ln2b,
                out + ((size_t)(b0 + w) * CAP_ + (S_ + STEPS_ - 1)) * 512, lane);
}

// ---------------- host launcher ----------------
struct ScratchPtrs {
    float *Qkv, *Attn, *Pre, *Hb, *Hff, *Kc, *Vc, *Qt, *Hfft, *T1, *Op, *Ml;
};

static const ScratchPtrs& get_scratch() {
    static ScratchPtrs p;
    static bool init = false;
    if (!init) {
        cudaGetSymbolAddress((void**)&p.Qkv,  g_qkv);
        cudaGetSymbolAddress((void**)&p.Attn, g_attn);
        cudaGetSymbolAddress((void**)&p.Pre,  g_pre);
        cudaGetSymbolAddress((void**)&p.Hb,   g_h);
        cudaGetSymbolAddress((void**)&p.Hff,  g_hff);
        cudaGetSymbolAddress((void**)&p.Kc,   g_kc);
        cudaGetSymbolAddress((void**)&p.Vc,   g_vc);
        cudaGetSymbolAddress((void**)&p.Qt,   g_qt);
        cudaGetSymbolAddress((void**)&p.Hfft, g_hfft);
        cudaGetSymbolAddress((void**)&p.T1,   g_t1);
        cudaGetSymbolAddress((void**)&p.Op,   g_op);
        cudaGetSymbolAddress((void**)&p.Ml,   g_ml);
        cudaFuncSetAttribute(attn_prefill,
                             cudaFuncAttributeMaxDynamicSharedMemorySize, 49408);
        cudaFuncSetAttribute(decode_mega,
                             cudaFuncAttributeMaxDynamicSharedMemorySize, 32768);
        init = true;
    }
    return p;
}

extern "C" void kernel_launch(void* const* d_in, const int* in_sizes, int n_in,
                              void* d_out, int out_size)
{
    (void)in_sizes; (void)n_in; (void)out_size;
    const float* x    = (const float*)d_in[0];
    const float* dx   = (const float*)d_in[1];
    // d_in[2] = causal_mask (bool) — unused, causality computed analytically
    const float* qkvW = (const float*)d_in[3];
    const float* qkvB = (const float*)d_in[4];
    const float* outW = (const float*)d_in[5];
    const float* outB = (const float*)d_in[6];
    const float* w1   = (const float*)d_in[7];
    const float* b1   = (const float*)d_in[8];
    const float* w2   = (const float*)d_in[9];
    const float* b2   = (const float*)d_in[10];
    const float* ln1w = (const float*)d_in[11];
    const float* ln1b = (const float*)d_in[12];
    const float* ln2w = (const float*)d_in[13];
    const float* ln2b = (const float*)d_in[14];
    float* out = (float*)d_out;

    const ScratchPtrs& sp = get_scratch();

    // ---- prefill (QKV GEMM also scatters K/V into the decode caches) ----
    sgemm_nt<1,0,0,1><<<dim3(12, 64), 256>>>(x, qkvW, qkvB, nullptr, sp.Qkv,
                                             MTOK, 1536, 512, sp.Kc, sp.Vc);
    attn_prefill<<<dim3(16, 64), 256, 49408>>>(sp.Qkv, sp.Attn);
    sgemm_nt<1,0,1,0><<<dim3(4, 64), 256>>>(sp.Attn, outW, outB, x, sp.Pre,
                                            MTOK, 512, 512, nullptr, nullptr);
    ln_rows<<<MTOK, 256>>>(sp.Pre, ln1w, ln1b, sp.Hb, 0);
    sgemm_nt<1,1,0,0><<<dim3(16, 64), 256>>>(sp.Hb, w1, b1, nullptr, sp.Hff,
                                             MTOK, 2048, 512, nullptr, nullptr);
    sgemm_nt<1,0,1,0><<<dim3(4, 64), 256>>>(sp.Hff, w2, b2, sp.Hb, sp.Pre,
                                            MTOK, 512, 2048, nullptr, nullptr);
    ln_rows<<<MTOK, 256>>>(sp.Pre, ln2w, ln2b, out, 64);

    // ---- decode: all 64 steps in one persistent launch ----
    decode_mega<<<NBLK, 256, 32768>>>(dx, qkvW, qkvB, outW, outB,
                                      w1, b1, w2, b2,
                                      ln1w, ln1b, ln2w, ln2b, out,
                                      sp.Qt, sp.Kc, sp.Vc,
                                      sp.Hfft, sp.T1, sp.Op, sp.Ml);
}

// round 8
// speedup vs baseline: 1.1689x; 1.1201x over previous
#include <cuda_runtime.h>
#include <cstdint>

#define B_     8
#define S_     1024
#define D_     512
#define H_     8
#define HD_    64
#define FF_    2048
#define STEPS_ 64
#define CAP_   1088
#define MTOK   (B_*S_)   /* 8192 */
#define NBLK   128

// ---------------- device scratch (no cudaMalloc allowed) ----------------
__device__ float g_qkv [MTOK*1536];
__device__ float g_attn[MTOK*D_];
__device__ float g_pre [MTOK*D_];
__device__ float g_h   [MTOK*D_];
__device__ float g_hff [MTOK*FF_];
__device__ float g_kc  [B_*CAP_*D_];
__device__ float g_vc  [B_*CAP_*D_];
__device__ float g_qt  [B_*D_];
__device__ float g_hfft[B_*FF_];
__device__ float g_t1  [B_*D_];
__device__ float g_op  [2*64*64];
__device__ float g_ml  [2*64*2];
__device__ unsigned g_bar_count;
__device__ unsigned g_bar_sense;

// ---------------- reductions ----------------
__device__ __forceinline__ float warpRedSum(float v) {
#pragma unroll
    for (int o = 16; o; o >>= 1) v += __shfl_xor_sync(0xffffffffu, v, o);
    return v;
}
__device__ __forceinline__ float warpRedMax(float v) {
#pragma unroll
    for (int o = 16; o; o >>= 1) v = fmaxf(v, __shfl_xor_sync(0xffffffffu, v, o));
    return v;
}

// ---------------- fence-free global barrier (.cg data protocol) ----------------
__device__ __forceinline__ unsigned ld_acq(const unsigned* p) {
    unsigned v;
    asm volatile("ld.acquire.gpu.u32 %0, [%1];" : "=r"(v) : "l"(p) : "memory");
    return v;
}
__device__ __forceinline__ void st_rel(unsigned* p, unsigned v) {
    asm volatile("st.release.gpu.u32 [%0], %1;" :: "l"(p), "r"(v) : "memory");
}
__device__ __forceinline__ unsigned atomAddAcqRel(unsigned* p, unsigned v) {
    unsigned old;
    asm volatile("atom.acq_rel.gpu.global.add.u32 %0, [%1], %2;"
                 : "=r"(old) : "l"(p), "r"(v) : "memory");
    return old;
}
__device__ __forceinline__ void gbar(unsigned& target, int tid) {
    __syncthreads();
    target += 1;
    if (tid == 0) {
        unsigned a = atomAddAcqRel(&g_bar_count, 1u) + 1u;
        if (a == (unsigned)NBLK) {
            atomicExch(&g_bar_count, 0u);
            st_rel(&g_bar_sense, target);
        } else {
            while ((int)(ld_acq(&g_bar_sense) - target) < 0) { }
        }
    }
    __syncthreads();
}

// ---------------- SGEMM (NT), register-prefetch ----------------
template<int BIAS, int RELU, int RES, int KVOUT>
__global__ void __launch_bounds__(256, 2) sgemm_nt(
    const float* __restrict__ A, const float* __restrict__ Bm,
    const float* __restrict__ bias, const float* __restrict__ R,
    float* __restrict__ C, int M, int N, int K,
    float* __restrict__ kc, float* __restrict__ vc)
{
    __shared__ float As[16][132];
    __shared__ float Bs[16][132];
    const int tid = threadIdx.x;
    const int m0 = blockIdx.y * 128;
    const int n0 = blockIdx.x * 128;
    const int tx = tid & 15, ty = tid >> 4;
    const int r0 = ty * 4, c0 = tx * 4;
    const int lrow = tid >> 2;
    const int lk4  = (tid & 3) * 4;

    const float* Ap0 = A  + (size_t)(m0 + lrow)      * K + lk4;
    const float* Ap1 = A  + (size_t)(m0 + lrow + 64) * K + lk4;
    const float* Bp0 = Bm + (size_t)(n0 + lrow)      * K + lk4;
    const float* Bp1 = Bm + (size_t)(n0 + lrow + 64) * K + lk4;

    float acc[8][8];
#pragma unroll
    for (int i = 0; i < 8; i++)
#pragma unroll
        for (int j = 0; j < 8; j++) acc[i][j] = 0.f;

    float4 pa0 = *(const float4*)(Ap0);
    float4 pa1 = *(const float4*)(Ap1);
    float4 pb0 = *(const float4*)(Bp0);
    float4 pb1 = *(const float4*)(Bp1);

    for (int k0 = 0; k0 < K; k0 += 16) {
        As[lk4 + 0][lrow]      = pa0.x; As[lk4 + 1][lrow]      = pa0.y;
        As[lk4 + 2][lrow]      = pa0.z; As[lk4 + 3][lrow]      = pa0.w;
        As[lk4 + 0][lrow + 64] = pa1.x; As[lk4 + 1][lrow + 64] = pa1.y;
        As[lk4 + 2][lrow + 64] = pa1.z; As[lk4 + 3][lrow + 64] = pa1.w;
        Bs[lk4 + 0][lrow]      = pb0.x; Bs[lk4 + 1][lrow]      = pb0.y;
        Bs[lk4 + 2][lrow]      = pb0.z; Bs[lk4 + 3][lrow]      = pb0.w;
        Bs[lk4 + 0][lrow + 64] = pb1.x; Bs[lk4 + 1][lrow + 64] = pb1.y;
        Bs[lk4 + 2][lrow + 64] = pb1.z; Bs[lk4 + 3][lrow + 64] = pb1.w;
        __syncthreads();
        if (k0 + 16 < K) {
            pa0 = *(const float4*)(Ap0 + k0 + 16);
            pa1 = *(const float4*)(Ap1 + k0 + 16);
            pb0 = *(const float4*)(Bp0 + k0 + 16);
            pb1 = *(const float4*)(Bp1 + k0 + 16);
        }
#pragma unroll
        for (int kk = 0; kk < 16; kk++) {
            float af[8], bf[8];
            *(float4*)(af)     = *(const float4*)(&As[kk][r0]);
            *(float4*)(af + 4) = *(const float4*)(&As[kk][r0 + 64]);
            *(float4*)(bf)     = *(const float4*)(&Bs[kk][c0]);
            *(float4*)(bf + 4) = *(const float4*)(&Bs[kk][c0 + 64]);
#pragma unroll
            for (int i = 0; i < 8; i++)
#pragma unroll
                for (int j = 0; j < 8; j++)
                    acc[i][j] = fmaf(af[i], bf[j], acc[i][j]);
        }
        __syncthreads();
    }

    float bl[8];
#pragma unroll
    for (int j = 0; j < 8; j++)
        bl[j] = BIAS ? bias[n0 + c0 + (j < 4 ? j : 60 + j)] : 0.f;

#pragma unroll
    for (int i = 0; i < 8; i++) {
        const int row = m0 + r0 + (i < 4 ? i : 60 + i);
        const size_t rowoff = (size_t)row * N + n0;
#pragma unroll
        for (int jg = 0; jg < 2; jg++) {
            const int cb = c0 + jg * 64;
            float t0 = acc[i][jg * 4 + 0] + bl[jg * 4 + 0];
            float t1 = acc[i][jg * 4 + 1] + bl[jg * 4 + 1];
            float t2 = acc[i][jg * 4 + 2] + bl[jg * 4 + 2];
            float t3 = acc[i][jg * 4 + 3] + bl[jg * 4 + 3];
            if (RES) {
                float4 r = *(const float4*)(R + rowoff + cb);
                t0 += r.x; t1 += r.y; t2 += r.z; t3 += r.w;
            }
            if (RELU) {
                t0 = fmaxf(t0, 0.f); t1 = fmaxf(t1, 0.f);
                t2 = fmaxf(t2, 0.f); t3 = fmaxf(t3, 0.f);
            }
            float4 v; v.x = t0; v.y = t1; v.z = t2; v.w = t3;
            *(float4*)(C + rowoff + cb) = v;
            if (KVOUT) {
                const int ncol = n0 + cb;
                if (ncol >= 512) {
                    const int bb = row >> 10, ss = row & 1023;
                    float* dst = (ncol < 1024)
                        ? kc + ((size_t)(bb * CAP_ + ss) * 512 + (ncol - 512))
                        : vc + ((size_t)(bb * CAP_ + ss) * 512 + (ncol - 1024));
                    *(float4*)dst = v;
                }
            }
        }
    }
}

// ---------------- prefill flash attention (causal), 64x64 tiles ----------------
__global__ void __launch_bounds__(256) attn_prefill(const float* __restrict__ qkv,
                                                    float* __restrict__ attn)
{
    extern __shared__ float sm[];
    float* Qs = sm;
    float* KP = sm + 64 * 64;
    float* Vs = KP + 64 * 65;

    const int b  = blockIdx.y >> 3;
    const int h  = blockIdx.y & 7;
    const int l0 = blockIdx.x * 64;
    const int tid = threadIdx.x;
    const int tx = tid & 15, ty = tid >> 4;
    const int r0 = ty * 4, c0 = tx * 4;

    const size_t rowbase = (size_t)(b * S_) * 1536;
    const float* qbase = qkv + rowbase + h * 64;
    const float* kbase = qkv + rowbase + 512 + h * 64;
    const float* vbase = qkv + rowbase + 1024 + h * 64;

    const int lt  = tid >> 4;
    const int ld4 = (tid & 15) * 4;

#pragma unroll
    for (int tt = lt; tt < 64; tt += 16) {
        float4 q4 = *(const float4*)(qbase + (size_t)(l0 + tt) * 1536 + ld4);
        Qs[(ld4 + 0) * 64 + tt] = q4.x;
        Qs[(ld4 + 1) * 64 + tt] = q4.y;
        Qs[(ld4 + 2) * 64 + tt] = q4.z;
        Qs[(ld4 + 3) * 64 + tt] = q4.w;
    }

    float o[4][4];
    float mrow[4], lrow[4];
#pragma unroll
    for (int i = 0; i < 4; i++) {
        mrow[i] = -1e30f; lrow[i] = 0.f;
#pragma unroll
        for (int j = 0; j < 4; j++) o[i][j] = 0.f;
    }

    const int ntiles = (l0 >> 6) + 1;
    for (int tile = 0; tile < ntiles; ++tile) {
        const int j0 = tile * 64;
        __syncthreads();
#pragma unroll
        for (int tt = lt; tt < 64; tt += 16) {
            float4 k4 = *(const float4*)(kbase + (size_t)(j0 + tt) * 1536 + ld4);
            KP[(ld4 + 0) * 65 + tt] = k4.x;
            KP[(ld4 + 1) * 65 + tt] = k4.y;
            KP[(ld4 + 2) * 65 + tt] = k4.z;
            KP[(ld4 + 3) * 65 + tt] = k4.w;
            float4 v4 = *(const float4*)(vbase + (size_t)(j0 + tt) * 1536 + ld4);
            *(float4*)(Vs + tt * 64 + ld4) = v4;
        }
        __syncthreads();

        float s[4][4];
#pragma unroll
        for (int i = 0; i < 4; i++)
#pragma unroll
            for (int j = 0; j < 4; j++) s[i][j] = 0.f;

        for (int d = 0; d < 64; d++) {
            float qf[4];
            *(float4*)qf = *(const float4*)(Qs + d * 64 + r0);
            float kf0 = KP[d * 65 + c0 + 0];
            float kf1 = KP[d * 65 + c0 + 1];
            float kf2 = KP[d * 65 + c0 + 2];
            float kf3 = KP[d * 65 + c0 + 3];
#pragma unroll
            for (int i = 0; i < 4; i++) {
                s[i][0] = fmaf(qf[i], kf0, s[i][0]);
                s[i][1] = fmaf(qf[i], kf1, s[i][1]);
                s[i][2] = fmaf(qf[i], kf2, s[i][2]);
                s[i][3] = fmaf(qf[i], kf3, s[i][3]);
            }
        }

        if (j0 == l0) {
#pragma unroll
            for (int i = 0; i < 4; i++)
#pragma unroll
                for (int j = 0; j < 4; j++)
                    s[i][j] = (j0 + c0 + j > l0 + r0 + i) ? -1e30f : s[i][j] * 0.125f;
        } else {
#pragma unroll
            for (int i = 0; i < 4; i++)
#pragma unroll
                for (int j = 0; j < 4; j++) s[i][j] *= 0.125f;
        }

        float p[4][4];
#pragma unroll
        for (int i = 0; i < 4; i++) {
            float rm = fmaxf(fmaxf(s[i][0], s[i][1]), fmaxf(s[i][2], s[i][3]));
#pragma unroll
            for (int off = 8; off; off >>= 1)
                rm = fmaxf(rm, __shfl_xor_sync(0xffffffffu, rm, off));
            float mnew  = fmaxf(mrow[i], rm);
            float alpha = __expf(mrow[i] - mnew);
            float ps = 0.f;
#pragma unroll
            for (int j = 0; j < 4; j++) { p[i][j] = __expf(s[i][j] - mnew); ps += p[i][j]; }
#pragma unroll
            for (int off = 8; off; off >>= 1)
                ps += __shfl_xor_sync(0xffffffffu, ps, off);
            lrow[i] = lrow[i] * alpha + ps;
            mrow[i] = mnew;
#pragma unroll
            for (int j = 0; j < 4; j++) o[i][j] *= alpha;
        }

        __syncthreads();
#pragma unroll
        for (int i = 0; i < 4; i++)
#pragma unroll
            for (int j = 0; j < 4; j++)
                KP[(r0 + i) * 65 + c0 + j] = p[i][j];
        __syncthreads();

        for (int c = 0; c < 64; c++) {
            float vv[4];
            *(float4*)vv = *(const float4*)(Vs + c * 64 + c0);
            float p0 = KP[(r0 + 0) * 65 + c];
            float p1 = KP[(r0 + 1) * 65 + c];
            float p2 = KP[(r0 + 2) * 65 + c];
            float p3 = KP[(r0 + 3) * 65 + c];
#pragma unroll
            for (int j = 0; j < 4; j++) {
                o[0][j] = fmaf(p0, vv[j], o[0][j]);
                o[1][j] = fmaf(p1, vv[j], o[1][j]);
                o[2][j] = fmaf(p2, vv[j], o[2][j]);
                o[3][j] = fmaf(p3, vv[j], o[3][j]);
            }
        }
    }

    float* ob = attn + (size_t)(b * S_ + l0) * 512 + h * 64;
#pragma unroll
    for (int i = 0; i < 4; i++) {
        float inv = 1.f / lrow[i];
        float4 v;
        v.x = o[i][0] * inv; v.y = o[i][1] * inv;
        v.z = o[i][2] * inv; v.w = o[i][3] * inv;
        *(float4*)(ob + (size_t)(r0 + i) * 512 + c0) = v;
    }
}

// ---------------- prefill LayerNorm over rows of 512 ----------------
__global__ void __launch_bounds__(256) ln_rows(const float* __restrict__ in,
                                               const float* __restrict__ g,
                                               const float* __restrict__ be,
                                               float* __restrict__ out, int outExtra)
{
    const int r = blockIdx.x;
    const int tid = threadIdx.x;
    const float* row = in + (size_t)r * 512;
    float v0 = row[tid], v1 = row[tid + 256];
    float s  = warpRedSum(v0 + v1);
    float s2 = warpRedSum(v0 * v0 + v1 * v1);
    __shared__ float r1[8], r2[8];
    __shared__ float smu, srs;
    const int w = tid >> 5, lane = tid & 31;
    if (lane == 0) { r1[w] = s; r2[w] = s2; }
    __syncthreads();
    if (tid == 0) {
        float S = 0.f, S2 = 0.f;
#pragma unroll
        for (int i = 0; i < 8; i++) { S += r1[i]; S2 += r2[i]; }
        float mu  = S * (1.f / 512.f);
        float var = S2 * (1.f / 512.f) - mu * mu;
        smu = mu; srs = rsqrtf(var + 1e-5f);
    }
    __syncthreads();
    const int orow = r + (r >> 10) * outExtra;
    float* od = out + (size_t)orow * 512;
    od[tid]       = (v0 - smu) * srs * g[tid]       + be[tid];
    od[tid + 256] = (v1 - smu) * srs * g[tid + 256] + be[tid + 256];
}

// ---------------- megakernel building blocks ----------------
template<int KP>
__device__ __forceinline__ void dot4(const float* __restrict__ wr,
                                     const float* xs, int Kstride, int lane,
                                     float& a0, float& a1, float& a2, float& a3)
{
    a0 = a1 = a2 = a3 = 0.f;
#pragma unroll
    for (int kp = 0; kp < KP; kp++) {
        const int k4 = kp * 128 + lane * 4;
        float4 wv = *(const float4*)(wr + k4);
        float4 x0 = *(const float4*)(xs + k4);
        float4 x1 = *(const float4*)(xs + Kstride + k4);
        float4 x2 = *(const float4*)(xs + 2 * Kstride + k4);
        float4 x3 = *(const float4*)(xs + 3 * Kstride + k4);
        a0 = fmaf(wv.x, x0.x, fmaf(wv.y, x0.y, fmaf(wv.z, x0.z, fmaf(wv.w, x0.w, a0))));
        a1 = fmaf(wv.x, x1.x, fmaf(wv.y, x1.y, fmaf(wv.z, x1.z, fmaf(wv.w, x1.w, a1))));
        a2 = fmaf(wv.x, x2.x, fmaf(wv.y, x2.y, fmaf(wv.z, x2.z, fmaf(wv.w, x2.w, a2))));
        a3 = fmaf(wv.x, x3.x, fmaf(wv.y, x3.y, fmaf(wv.z, x3.z, fmaf(wv.w, x3.w, a3))));
    }
    a0 = warpRedSum(a0); a1 = warpRedSum(a1);
    a2 = warpRedSum(a2); a3 = warpRedSum(a3);
}

__device__ __forceinline__ void warp_ln(const float* __restrict__ a,
                                        const float* r,
                                        const float* __restrict__ gw,
                                        const float* __restrict__ gb,
                                        float* o, int lane)
{
    float vals[16];
    float sv = 0.f, sq = 0.f;
#pragma unroll
    for (int g = 0; g < 4; g++) {
        const int idx = g * 128 + lane * 4;
        float4 av = __ldcg((const float4*)(a + idx));
        float4 rv = *(const float4*)(r + idx);
        float a0 = av.x + rv.x, a1 = av.y + rv.y;
        float a2 = av.z + rv.z, a3 = av.w + rv.w;
        vals[g * 4 + 0] = a0; vals[g * 4 + 1] = a1;
        vals[g * 4 + 2] = a2; vals[g * 4 + 3] = a3;
        sv += a0 + a1 + a2 + a3;
        sq += a0 * a0 + a1 * a1 + a2 * a2 + a3 * a3;
    }
    sv = warpRedSum(sv); sq = warpRedSum(sq);
    float mu = sv * (1.f / 512.f);
    float rs = rsqrtf(sq * (1.f / 512.f) - mu * mu + 1e-5f);
#pragma unroll
    for (int g = 0; g < 4; g++)
#pragma unroll
        for (int j = 0; j < 4; j++) {
            const int idx = g * 128 + lane * 4 + j;
            o[idx] = (vals[g * 4 + j] - mu) * rs * gw[idx] + gb[idx];
        }
}

// ---------------- decode megakernel ----------------
__global__ void __launch_bounds__(256, 1) decode_mega(
    const float* __restrict__ dx,
    const float* __restrict__ qkvW, const float* __restrict__ qkvB,
    const float* __restrict__ outW, const float* __restrict__ outB,
    const float* __restrict__ w1, const float* __restrict__ b1,
    const float* __restrict__ w2, const float* __restrict__ b2,
    const float* __restrict__ ln1w, const float* __restrict__ ln1b,
    const float* __restrict__ ln2w, const float* __restrict__ ln2b,
    float* __restrict__ out,
    float* __restrict__ qt, float* __restrict__ kc, float* __restrict__ vc,
    float* __restrict__ hfft, float* __restrict__ t1,
    float* __restrict__ opart, float* __restrict__ mlpart)
{
    extern __shared__ float xs[];      // 8192 floats (32KB)
    __shared__ float s_ln[4 * 512];
    __shared__ float s_red[16];
    __shared__ float s_q[64];
    __shared__ float s_part[256];
    __shared__ float s_comb[128];
    __shared__ unsigned s_base;

    const int tid  = threadIdx.x;
    const int bid  = blockIdx.x;
    const int w    = tid >> 5, lane = tid & 31;
    const int half = bid >> 6;
    const int b0   = half * 4;
    const int wg   = (bid & 63) * 8 + w;

    if (tid == 0) s_base = ld_acq(&g_bar_sense);
    __syncthreads();
    unsigned target = s_base;

    for (int step = 0; step < STEPS_; step++) {
        const int cur = S_ + step;
        const float* xt = dx + (size_t)step * (B_ * D_);

        // ===== phase A: LN2(prev) on blocks 0 & 64 + QKV GEMV =====
        if (step > 0 && (bid == 0 || bid == 64) && w < 4)
            warp_ln(t1 + (b0 + w) * 512, s_ln + w * 512, ln2w, ln2b,
                    out + ((size_t)(b0 + w) * CAP_ + (cur - 1)) * 512, lane);
        {
            const float4* src = (const float4*)(xt + b0 * 512);
            float4* dst = (float4*)xs;
            for (int i = tid; i < 512; i += 256) dst[i] = src[i];
        }
        __syncthreads();
#pragma unroll
        for (int o = 0; o < 3; o++) {
            const int n = wg + o * 512;
            float a0, a1, a2, a3;
            dot4<4>(qkvW + (size_t)n * 512, xs, 512, lane, a0, a1, a2, a3);
            if (lane == 0) {
                const float bv = qkvB[n];
                if (o == 0) {
                    __stcg(&qt[(b0 + 0) * 512 + wg], a0 + bv);
                    __stcg(&qt[(b0 + 1) * 512 + wg], a1 + bv);
                    __stcg(&qt[(b0 + 2) * 512 + wg], a2 + bv);
                    __stcg(&qt[(b0 + 3) * 512 + wg], a3 + bv);
                } else if (o == 1) {
                    __stcg(&kc[((size_t)(b0 + 0) * CAP_ + cur) * 512 + wg], a0 + bv);
                    __stcg(&kc[((size_t)(b0 + 1) * CAP_ + cur) * 512 + wg], a1 + bv);
                    __stcg(&kc[((size_t)(b0 + 2) * CAP_ + cur) * 512 + wg], a2 + bv);
                    __stcg(&kc[((size_t)(b0 + 3) * CAP_ + cur) * 512 + wg], a3 + bv);
                } else {
                    __stcg(&vc[((size_t)(b0 + 0) * CAP_ + cur) * 512 + wg], a0 + bv);
                    __stcg(&vc[((size_t)(b0 + 1) * CAP_ + cur) * 512 + wg], a1 + bv);
                    __stcg(&vc[((size_t)(b0 + 2) * CAP_ + cur) * 512 + wg], a2 + bv);
                    __stcg(&vc[((size_t)(b0 + 3) * CAP_ + cur) * 512 + wg], a3 + bv);
                }
            }
        }
        gbar(target, tid);

        // ===== phase B: attention partials, 128 blocks = (part, b, h) =====
        {
            const int part = bid >> 6;
            const int bb = (bid >> 3) & 7;
            const int h  = bid & 7;
            const int kvlen = cur + 1;
            const int hlen  = kvlen >> 1;
            const int tstart = part ? hlen : 0;
            const int tend   = part ? kvlen : hlen;
            if (tid < 64) s_q[tid] = __ldcg(&qt[bb * 512 + h * 64 + tid]);
            __syncthreads();
            const int tl = lane >> 2;
            const int kq = (lane & 3) * 16;
            const float4 qa = *(const float4*)(s_q + kq);
            const float4 qb = *(const float4*)(s_q + kq + 4);
            const float4 qc = *(const float4*)(s_q + kq + 8);
            const float4 qd = *(const float4*)(s_q + kq + 12);
            const float* kb = kc + (size_t)bb * CAP_ * 512 + h * 64;
            for (int t0 = tstart; t0 < tend; t0 += 64) {
                const int t = t0 + w * 8 + tl;
                const bool valid = t < tend;
                const float* kr = kb + (size_t)(valid ? t : tstart) * 512 + kq;
                float4 k0 = __ldcg((const float4*)(kr));
                float4 k1 = __ldcg((const float4*)(kr + 4));
                float4 k2 = __ldcg((const float4*)(kr + 8));
                float4 k3 = __ldcg((const float4*)(kr + 12));
                float s;
                s = k0.x * qa.x;
                s = fmaf(k0.y, qa.y, s); s = fmaf(k0.z, qa.z, s); s = fmaf(k0.w, qa.w, s);
                s = fmaf(k1.x, qb.x, s); s = fmaf(k1.y, qb.y, s);
                s = fmaf(k1.z, qb.z, s); s = fmaf(k1.w, qb.w, s);
                s = fmaf(k2.x, qc.x, s); s = fmaf(k2.y, qc.y, s);
                s = fmaf(k2.z, qc.z, s); s = fmaf(k2.w, qc.w, s);
                s = fmaf(k3.x, qd.x, s); s = fmaf(k3.y, qd.y, s);
                s = fmaf(k3.z, qd.z, s); s = fmaf(k3.w, qd.w, s);
                s += __shfl_xor_sync(0xffffffffu, s, 1);
                s += __shfl_xor_sync(0xffffffffu, s, 2);
                if (valid && (lane & 3) == 0) xs[t] = s * 0.125f;
            }
            __syncthreads();
            float lmax = -1e30f;
            for (int t = tstart + tid; t < tend; t += 256) lmax = fmaxf(lmax, xs[t]);
            lmax = warpRedMax(lmax);
            if (lane == 0) s_red[w] = lmax;
            __syncthreads();
            float gm = s_red[0];
#pragma unroll
            for (int i = 1; i < 8; i++) gm = fmaxf(gm, s_red[i]);
            float ls = 0.f;
            for (int t = tstart + tid; t < tend; t += 256) {
                float p = __expf(xs[t] - gm);
                xs[t] = p;
                ls += p;
            }
            ls = warpRedSum(ls);
            if (lane == 0) s_red[8 + w] = ls;
            __syncthreads();
            float ssum = 0.f;
#pragma unroll
            for (int i = 0; i < 8; i++) ssum += s_red[8 + i];
            const int d = tid & 63, pt = tid >> 6;
            const float* vb = vc + (size_t)bb * CAP_ * 512 + h * 64 + d;
            float vacc = 0.f;
            for (int t = tstart + pt; t < tend; t += 4)
                vacc = fmaf(xs[t], __ldcg(vb + (size_t)t * 512), vacc);
            s_part[tid] = vacc;
            __syncthreads();
            const int gi = part * 64 + bb * 8 + h;
            if (pt == 0)
                __stcg(&opart[gi * 64 + d],
                       s_part[d] + s_part[64 + d] + s_part[128 + d] + s_part[192 + d]);
            if (tid == 0) {
                __stcg(&mlpart[gi * 2], gm);
                __stcg(&mlpart[gi * 2 + 1], ssum);
            }
        }
        gbar(target, tid);

        // ===== phase C: combine attn parts + out-proj =====
        if (tid < 64) {
            float m1 = __ldcg(&mlpart[tid * 2]);
            float l1 = __ldcg(&mlpart[tid * 2 + 1]);
            float m2 = __ldcg(&mlpart[(64 + tid) * 2]);
            float l2 = __ldcg(&mlpart[(64 + tid) * 2 + 1]);
            float gm = fmaxf(m1, m2);
            float e1 = __expf(m1 - gm), e2 = __expf(m2 - gm);
            float inv = 1.f / (e1 * l1 + e2 * l2);
            s_comb[tid * 2]     = e1 * inv;
            s_comb[tid * 2 + 1] = e2 * inv;
        }
        __syncthreads();
        for (int i = tid; i < 2048; i += 256) {
            const int b = b0 + (i >> 9);
            const int col = i & 511;
            const int gi = b * 8 + (col >> 6);
            const int d = col & 63;
            xs[i] = s_comb[gi * 2]     * __ldcg(&opart[gi * 64 + d])
                  + s_comb[gi * 2 + 1] * __ldcg(&opart[(64 + gi) * 64 + d]);
        }
        __syncthreads();
        {
            float a0, a1, a2, a3;
            dot4<4>(outW + (size_t)wg * 512, xs, 512, lane, a0, a1, a2, a3);
            if (lane == 0) {
                const float bv = outB[wg];
                __stcg(&t1[(b0 + 0) * 512 + wg], a0 + bv);
                __stcg(&t1[(b0 + 1) * 512 + wg], a1 + bv);
                __stcg(&t1[(b0 + 2) * 512 + wg], a2 + bv);
                __stcg(&t1[(b0 + 3) * 512 + wg], a3 + bv);
            }
        }
        gbar(target, tid);

        // ===== phase E: LN1 (warps 0-3, into s_ln) + FF1 (N=2048, relu) =====
        if (w < 4)
            warp_ln(t1 + (b0 + w) * 512, xt + (b0 + w) * 512,
                    ln1w, ln1b, s_ln + w * 512, lane);
        __syncthreads();
#pragma unroll
        for (int o = 0; o < 4; o++) {
            const int n = wg + o * 512;
            float a0, a1, a2, a3;
            dot4<4>(w1 + (size_t)n * 512, s_ln, 512, lane, a0, a1, a2, a3);
            if (lane == 0) {
                const float bv = b1[n];
                __stcg(&hfft[(b0 + 0) * 2048 + n], fmaxf(a0 + bv, 0.f));
                __stcg(&hfft[(b0 + 1) * 2048 + n], fmaxf(a1 + bv, 0.f));
                __stcg(&hfft[(b0 + 2) * 2048 + n], fmaxf(a2 + bv, 0.f));
                __stcg(&hfft[(b0 + 3) * 2048 + n], fmaxf(a3 + bv, 0.f));
            }
        }
        gbar(target, tid);

        // ===== phase F: FF2 (N=512, K=2048) -> t1 =====
        {
            const float4* src = (const float4*)(hfft + b0 * 2048);
            float4* dst = (float4*)xs;
            for (int i = tid; i < 2048; i += 256) dst[i] = __ldcg(src + i);
        }
        __syncthreads();
        {
            float a0, a1, a2, a3;
            dot4<16>(w2 + (size_t)wg * 2048, xs, 2048, lane, a0, a1, a2, a3);
            if (lane == 0) {
                const float bv = b2[wg];
                __stcg(&t1[(b0 + 0) * 512 + wg], a0 + bv);
                __stcg(&t1[(b0 + 1) * 512 + wg], a1 + bv);
                __stcg(&t1[(b0 + 2) * 512 + wg], a2 + bv);
                __stcg(&t1[(b0 + 3) * 512 + wg], a3 + bv);
            }
        }
        gbar(target, tid);
    }

    // final LN2 for the last step
    if ((bid == 0 || bid == 64) && w < 4)
        warp_ln(t1 + (b0 + w) * 512, s_ln + w * 512, ln2w, ln2b,
                out + ((size_t)(b0 + w) * CAP_ + (S_ + STEPS_ - 1)) * 512, lane);
}

// ---------------- host launcher ----------------
struct ScratchPtrs {
    float *Qkv, *Attn, *Pre, *Hb, *Hff, *Kc, *Vc, *Qt, *Hfft, *T1, *Op, *Ml;
    cudaStream_t sDec;
    cudaEvent_t evQkv, evDec;
};

static const ScratchPtrs& get_scratch() {
    static ScratchPtrs p;
    static bool init = false;
    if (!init) {
        cudaGetSymbolAddress((void**)&p.Qkv,  g_qkv);
        cudaGetSymbolAddress((void**)&p.Attn, g_attn);
        cudaGetSymbolAddress((void**)&p.Pre,  g_pre);
        cudaGetSymbolAddress((void**)&p.Hb,   g_h);
        cudaGetSymbolAddress((void**)&p.Hff,  g_hff);
        cudaGetSymbolAddress((void**)&p.Kc,   g_kc);
        cudaGetSymbolAddress((void**)&p.Vc,   g_vc);
        cudaGetSymbolAddress((void**)&p.Qt,   g_qt);
        cudaGetSymbolAddress((void**)&p.Hfft, g_hfft);
        cudaGetSymbolAddress((void**)&p.T1,   g_t1);
        cudaGetSymbolAddress((void**)&p.Op,   g_op);
        cudaGetSymbolAddress((void**)&p.Ml,   g_ml);
        cudaFuncSetAttribute(attn_prefill,
                             cudaFuncAttributeMaxDynamicSharedMemorySize, 49408);
        cudaFuncSetAttribute(decode_mega,
                             cudaFuncAttributeMaxDynamicSharedMemorySize, 32768);
        cudaStreamCreateWithFlags(&p.sDec, cudaStreamNonBlocking);
        cudaEventCreateWithFlags(&p.evQkv, cudaEventDisableTiming);
        cudaEventCreateWithFlags(&p.evDec, cudaEventDisableTiming);
        init = true;
    }
    return p;
}

extern "C" void kernel_launch(void* const* d_in, const int* in_sizes, int n_in,
                              void* d_out, int out_size)
{
    (void)in_sizes; (void)n_in; (void)out_size;
    const float* x    = (const float*)d_in[0];
    const float* dx   = (const float*)d_in[1];
    // d_in[2] = causal_mask (bool) — unused, causality computed analytically
    const float* qkvW = (const float*)d_in[3];
    const float* qkvB = (const float*)d_in[4];
    const float* outW = (const float*)d_in[5];
    const float* outB = (const float*)d_in[6];
    const float* w1   = (const float*)d_in[7];
    const float* b1   = (const float*)d_in[8];
    const float* w2   = (const float*)d_in[9];
    const float* b2   = (const float*)d_in[10];
    const float* ln1w = (const float*)d_in[11];
    const float* ln1b = (const float*)d_in[12];
    const float* ln2w = (const float*)d_in[13];
    const float* ln2b = (const float*)d_in[14];
    float* out = (float*)d_out;

    const ScratchPtrs& sp = get_scratch();

    // ---- QKV GEMM (also seeds decode K/V caches) on the main stream ----
    sgemm_nt<1,0,0,1><<<dim3(12, 64), 256>>>(x, qkvW, qkvB, nullptr, sp.Qkv,
                                             MTOK, 1536, 512, sp.Kc, sp.Vc);

    // ---- fork: decode runs concurrently with the rest of prefill ----
    cudaEventRecord(sp.evQkv, 0);
    cudaStreamWaitEvent(sp.sDec, sp.evQkv, 0);
    decode_mega<<<NBLK, 256, 32768, sp.sDec>>>(dx, qkvW, qkvB, outW, outB,
                                               w1, b1, w2, b2,
                                               ln1w, ln1b, ln2w, ln2b, out,
                                               sp.Qt, sp.Kc, sp.Vc,
                                               sp.Hfft, sp.T1, sp.Op, sp.Ml);
    cudaEventRecord(sp.evDec, sp.sDec);

    // ---- rest of prefill on the main stream ----
    attn_prefill<<<dim3(16, 64), 256, 49408>>>(sp.Qkv, sp.Attn);
    sgemm_nt<1,0,1,0><<<dim3(4, 64), 256>>>(sp.Attn, outW, outB, x, sp.Pre,
                                            MTOK, 512, 512, nullptr, nullptr);
    ln_rows<<<MTOK, 256>>>(sp.Pre, ln1w, ln1b, sp.Hb, 0);
    sgemm_nt<1,1,0,0><<<dim3(16, 64), 256>>>(sp.Hb, w1, b1, nullptr, sp.Hff,
                                             MTOK, 2048, 512, nullptr, nullptr);
    sgemm_nt<1,0,1,0><<<dim3(4, 64), 256>>>(sp.Hff, w2, b2, sp.Hb, sp.Pre,
                                            MTOK, 512, 2048, nullptr, nullptr);
    ln_rows<<<MTOK, 256>>>(sp.Pre, ln2w, ln2b, out, 64);

    // ---- join: main stream completes only after decode finishes ----
    cudaStreamWaitEvent(0, sp.evDec, 0);
}

// round 9
// speedup vs baseline: 1.1733x; 1.0037x over previous
#include <cuda_runtime.h>
#include <cstdint>

#define B_     8
#define S_     1024
#define D_     512
#define H_     8
#define HD_    64
#define FF_    2048
#define STEPS_ 64
#define CAP_   1088
#define MTOK   (B_*S_)   /* 8192 */
#define NBLK   128

// ---------------- device scratch (no cudaMalloc allowed) ----------------
__device__ float g_qkv [MTOK*1536];
__device__ float g_attn[MTOK*D_];
__device__ float g_pre [MTOK*D_];
__device__ float g_h   [MTOK*D_];
__device__ float g_hff [MTOK*FF_];
__device__ float g_kc  [B_*CAP_*D_];
__device__ float g_vc  [B_*CAP_*D_];
__device__ float g_qt  [B_*D_];
__device__ float g_hfft[B_*FF_];
__device__ float g_t1  [B_*D_];
__device__ float g_op  [2*64*64];
__device__ float g_ml  [2*64*2];
__device__ unsigned g_bar_count;
__device__ unsigned g_bar_sense;

// ---------------- reductions ----------------
__device__ __forceinline__ float warpRedSum(float v) {
#pragma unroll
    for (int o = 16; o; o >>= 1) v += __shfl_xor_sync(0xffffffffu, v, o);
    return v;
}
__device__ __forceinline__ float warpRedMax(float v) {
#pragma unroll
    for (int o = 16; o; o >>= 1) v = fmaxf(v, __shfl_xor_sync(0xffffffffu, v, o));
    return v;
}

// ---------------- fence-free global barrier (.cg data protocol) ----------------
__device__ __forceinline__ unsigned ld_acq(const unsigned* p) {
    unsigned v;
    asm volatile("ld.acquire.gpu.u32 %0, [%1];" : "=r"(v) : "l"(p) : "memory");
    return v;
}
__device__ __forceinline__ void st_rel(unsigned* p, unsigned v) {
    asm volatile("st.release.gpu.u32 [%0], %1;" :: "l"(p), "r"(v) : "memory");
}
__device__ __forceinline__ unsigned atomAddAcqRel(unsigned* p, unsigned v) {
    unsigned old;
    asm volatile("atom.acq_rel.gpu.global.add.u32 %0, [%1], %2;"
                 : "=r"(old) : "l"(p), "r"(v) : "memory");
    return old;
}
__device__ __forceinline__ void gbar(unsigned& target, int tid) {
    __syncthreads();
    target += 1;
    if (tid == 0) {
        unsigned a = atomAddAcqRel(&g_bar_count, 1u) + 1u;
        if (a == (unsigned)NBLK) {
            atomicExch(&g_bar_count, 0u);
            st_rel(&g_bar_sense, target);
        } else {
            while ((int)(ld_acq(&g_bar_sense) - target) < 0) { }
        }
    }
    __syncthreads();
}

// ---------------- 3xTF32 helpers ----------------
__device__ __forceinline__ float tf32_rna(float v) {
    unsigned u;
    asm("cvt.rna.tf32.f32 %0, %1;" : "=r"(u) : "f"(v));
    return __uint_as_float(u);
}

// one tf32 mma pass over an 8-k slice; acc[mt][nt][4]
__device__ __forceinline__ void mma_pass(
    const float (*__restrict__ XA)[132], const float (*__restrict__ XB)[132],
    int ks, int wm0, int wn0, int g, int tq, float acc[4][4][4])
{
    unsigned bb[4][2];
#pragma unroll
    for (int nt = 0; nt < 4; nt++) {
        bb[nt][0] = __float_as_uint(XB[ks + tq][wn0 + nt * 8 + g]);
        bb[nt][1] = __float_as_uint(XB[ks + tq + 4][wn0 + nt * 8 + g]);
    }
#pragma unroll
    for (int mt = 0; mt < 4; mt++) {
        const int mb = wm0 + mt * 16 + g;
        unsigned a0 = __float_as_uint(XA[ks + tq][mb]);
        unsigned a1 = __float_as_uint(XA[ks + tq][mb + 8]);
        unsigned a2 = __float_as_uint(XA[ks + tq + 4][mb]);
        unsigned a3 = __float_as_uint(XA[ks + tq + 4][mb + 8]);
#pragma unroll
        for (int nt = 0; nt < 4; nt++) {
            asm volatile(
                "mma.sync.aligned.m16n8k8.row.col.f32.tf32.tf32.f32 "
                "{%0,%1,%2,%3}, {%4,%5,%6,%7}, {%8,%9}, {%0,%1,%2,%3};"
                : "+f"(acc[mt][nt][0]), "+f"(acc[mt][nt][1]),
                  "+f"(acc[mt][nt][2]), "+f"(acc[mt][nt][3])
                : "r"(a0), "r"(a1), "r"(a2), "r"(a3),
                  "r"(bb[nt][0]), "r"(bb[nt][1]));
        }
    }
}

// ---------------- SGEMM (NT) via 3xTF32 tensor-core mma ----------------
// BM=BN=128, BK=16, 256 threads (8 warps, 2x4), warp tile 64x32.
// C[m,n] = sum_k A[m,k]*B[n,k]; fp32-accurate via Dekker split.
template<int BIAS, int RELU, int RES, int KVOUT>
__global__ void __launch_bounds__(256, 2) sgemm_nt(
    const float* __restrict__ A, const float* __restrict__ Bm,
    const float* __restrict__ bias, const float* __restrict__ R,
    float* __restrict__ C, int M, int N, int K,
    float* __restrict__ kc, float* __restrict__ vc)
{
    __shared__ float Ah[16][132], Al[16][132];
    __shared__ float Bh[16][132], Bl[16][132];
    const int tid = threadIdx.x;
    const int m0 = blockIdx.y * 128;
    const int n0 = blockIdx.x * 128;
    const int w = tid >> 5, lane = tid & 31;
    const int wm0 = (w >> 2) * 64;      // warp row offset (0/64)
    const int wn0 = (w & 3) * 32;       // warp col offset (0/32/64/96)
    const int g = lane >> 2, tq = lane & 3;
    const int lrow = tid >> 2;          // 0..63
    const int lk4  = (tid & 3) * 4;     // 0,4,8,12

    const float* Ap0 = A  + (size_t)(m0 + lrow)      * K + lk4;
    const float* Ap1 = A  + (size_t)(m0 + lrow + 64) * K + lk4;
    const float* Bp0 = Bm + (size_t)(n0 + lrow)      * K + lk4;
    const float* Bp1 = Bm + (size_t)(n0 + lrow + 64) * K + lk4;

    float acc[4][4][4];
#pragma unroll
    for (int i = 0; i < 4; i++)
#pragma unroll
        for (int j = 0; j < 4; j++)
#pragma unroll
            for (int q = 0; q < 4; q++) acc[i][j][q] = 0.f;

    float4 pa0 = *(const float4*)(Ap0);
    float4 pa1 = *(const float4*)(Ap1);
    float4 pb0 = *(const float4*)(Bp0);
    float4 pb1 = *(const float4*)(Bp1);

    for (int k0 = 0; k0 < K; k0 += 16) {
        // split-store staged tiles into hi/lo smem
        {
            const float va[8] = {pa0.x, pa0.y, pa0.z, pa0.w,
                                 pa1.x, pa1.y, pa1.z, pa1.w};
            const float vb[8] = {pb0.x, pb0.y, pb0.z, pb0.w,
                                 pb1.x, pb1.y, pb1.z, pb1.w};
#pragma unroll
            for (int i = 0; i < 4; i++) {
                float h;
                h = tf32_rna(va[i]);
                Ah[lk4 + i][lrow] = h;      Al[lk4 + i][lrow] = va[i] - h;
                h = tf32_rna(va[4 + i]);
                Ah[lk4 + i][lrow + 64] = h; Al[lk4 + i][lrow + 64] = va[4 + i] - h;
                h = tf32_rna(vb[i]);
                Bh[lk4 + i][lrow] = h;      Bl[lk4 + i][lrow] = vb[i] - h;
                h = tf32_rna(vb[4 + i]);
                Bh[lk4 + i][lrow + 64] = h; Bl[lk4 + i][lrow + 64] = vb[4 + i] - h;
            }
        }
        __syncthreads();
        if (k0 + 16 < K) {   // prefetch next tile under compute
            pa0 = *(const float4*)(Ap0 + k0 + 16);
            pa1 = *(const float4*)(Ap1 + k0 + 16);
            pb0 = *(const float4*)(Bp0 + k0 + 16);
            pb1 = *(const float4*)(Bp1 + k0 + 16);
        }
#pragma unroll
        for (int ks = 0; ks < 16; ks += 8) {
            mma_pass(Ah, Bh, ks, wm0, wn0, g, tq, acc);  // hi*hi
            mma_pass(Ah, Bl, ks, wm0, wn0, g, tq, acc);  // hi*lo
            mma_pass(Al, Bh, ks, wm0, wn0, g, tq, acc);  // lo*hi
        }
        __syncthreads();
    }

    // epilogue: pairs (col, col+1) per fragment, rows g and g+8 per 16-tile
#pragma unroll
    for (int nt = 0; nt < 4; nt++) {
        const int col = n0 + wn0 + nt * 8 + tq * 2;
        const float b0v = BIAS ? bias[col] : 0.f;
        const float b1v = BIAS ? bias[col + 1] : 0.f;
#pragma unroll
        for (int mt = 0; mt < 4; mt++) {
#pragma unroll
            for (int rh = 0; rh < 2; rh++) {
                const int row = m0 + wm0 + mt * 16 + g + rh * 8;
                float t0 = acc[mt][nt][rh * 2 + 0] + b0v;
                float t1 = acc[mt][nt][rh * 2 + 1] + b1v;
                if (RES) {
                    float2 r = *(const float2*)(R + (size_t)row * N + col);
                    t0 += r.x; t1 += r.y;
                }
                if (RELU) { t0 = fmaxf(t0, 0.f); t1 = fmaxf(t1, 0.f); }
                float2 v; v.x = t0; v.y = t1;
                *(float2*)(C + (size_t)row * N + col) = v;
                if (KVOUT && col >= 512) {
                    const int bb = row >> 10, ss = row & 1023;
                    float* dst = (col < 1024)
                        ? kc + ((size_t)(bb * CAP_ + ss) * 512 + (col - 512))
                        : vc + ((size_t)(bb * CAP_ + ss) * 512 + (col - 1024));
                    *(float2*)dst = v;
                }
            }
        }
    }
}

// ---------------- prefill flash attention (causal), 64x64 tiles ----------------
__global__ void __launch_bounds__(256) attn_prefill(const float* __restrict__ qkv,
                                                    float* __restrict__ attn)
{
    extern __shared__ float sm[];
    float* Qs = sm;
    float* KP = sm + 64 * 64;
    float* Vs = KP + 64 * 65;

    const int b  = blockIdx.y >> 3;
    const int h  = blockIdx.y & 7;
    const int l0 = blockIdx.x * 64;
    const int tid = threadIdx.x;
    const int tx = tid & 15, ty = tid >> 4;
    const int r0 = ty * 4, c0 = tx * 4;

    const size_t rowbase = (size_t)(b * S_) * 1536;
    const float* qbase = qkv + rowbase + h * 64;
    const float* kbase = qkv + rowbase + 512 + h * 64;
    const float* vbase = qkv + rowbase + 1024 + h * 64;

    const int lt  = tid >> 4;
    const int ld4 = (tid & 15) * 4;

#pragma unroll
    for (int tt = lt; tt < 64; tt += 16) {
        float4 q4 = *(const float4*)(qbase + (size_t)(l0 + tt) * 1536 + ld4);
        Qs[(ld4 + 0) * 64 + tt] = q4.x;
        Qs[(ld4 + 1) * 64 + tt] = q4.y;
        Qs[(ld4 + 2) * 64 + tt] = q4.z;
        Qs[(ld4 + 3) * 64 + tt] = q4.w;
    }

    float o[4][4];
    float mrow[4], lrow[4];
#pragma unroll
    for (int i = 0; i < 4; i++) {
        mrow[i] = -1e30f; lrow[i] = 0.f;
#pragma unroll
        for (int j = 0; j < 4; j++) o[i][j] = 0.f;
    }

    const int ntiles = (l0 >> 6) + 1;
    for (int tile = 0; tile < ntiles; ++tile) {
        const int j0 = tile * 64;
        __syncthreads();
#pragma unroll
        for (int tt = lt; tt < 64; tt += 16) {
            float4 k4 = *(const float4*)(kbase + (size_t)(j0 + tt) * 1536 + ld4);
            KP[(ld4 + 0) * 65 + tt] = k4.x;
            KP[(ld4 + 1) * 65 + tt] = k4.y;
            KP[(ld4 + 2) * 65 + tt] = k4.z;
            KP[(ld4 + 3) * 65 + tt] = k4.w;
            float4 v4 = *(const float4*)(vbase + (size_t)(j0 + tt) * 1536 + ld4);
            *(float4*)(Vs + tt * 64 + ld4) = v4;
        }
        __syncthreads();

        float s[4][4];
#pragma unroll
        for (int i = 0; i < 4; i++)
#pragma unroll
            for (int j = 0; j < 4; j++) s[i][j] = 0.f;

        for (int d = 0; d < 64; d++) {
            float qf[4];
            *(float4*)qf = *(const float4*)(Qs + d * 64 + r0);
            float kf0 = KP[d * 65 + c0 + 0];
            float kf1 = KP[d * 65 + c0 + 1];
            float kf2 = KP[d * 65 + c0 + 2];
            float kf3 = KP[d * 65 + c0 + 3];
#pragma unroll
            for (int i = 0; i < 4; i++) {
                s[i][0] = fmaf(qf[i], kf0, s[i][0]);
                s[i][1] = fmaf(qf[i], kf1, s[i][1]);
                s[i][2] = fmaf(qf[i], kf2, s[i][2]);
                s[i][3] = fmaf(qf[i], kf3, s[i][3]);
            }
        }

        if (j0 == l0) {
#pragma unroll
            for (int i = 0; i < 4; i++)
#pragma unroll
                for (int j = 0; j < 4; j++)
                    s[i][j] = (j0 + c0 + j > l0 + r0 + i) ? -1e30f : s[i][j] * 0.125f;
        } else {
#pragma unroll
            for (int i = 0; i < 4; i++)
#pragma unroll
                for (int j = 0; j < 4; j++) s[i][j] *= 0.125f;
        }

        float p[4][4];
#pragma unroll
        for (int i = 0; i < 4; i++) {
            float rm = fmaxf(fmaxf(s[i][0], s[i][1]), fmaxf(s[i][2], s[i][3]));
#pragma unroll
            for (int off = 8; off; off >>= 1)
                rm = fmaxf(rm, __shfl_xor_sync(0xffffffffu, rm, off));
            float mnew  = fmaxf(mrow[i], rm);
            float alpha = __expf(mrow[i] - mnew);
            float ps = 0.f;
#pragma unroll
            for (int j = 0; j < 4; j++) { p[i][j] = __expf(s[i][j] - mnew); ps += p[i][j]; }
#pragma unroll
            for (int off = 8; off; off >>= 1)
                ps += __shfl_xor_sync(0xffffffffu, ps, off);
            lrow[i] = lrow[i] * alpha + ps;
            mrow[i] = mnew;
#pragma unroll
            for (int j = 0; j < 4; j++) o[i][j] *= alpha;
        }

        __syncthreads();
#pragma unroll
        for (int i = 0; i < 4; i++)
#pragma unroll
            for (int j = 0; j < 4; j++)
                KP[(r0 + i) * 65 + c0 + j] = p[i][j];
        __syncthreads();

        for (int c = 0; c < 64; c++) {
            float vv[4];
            *(float4*)vv = *(const float4*)(Vs + c * 64 + c0);
            float p0 = KP[(r0 + 0) * 65 + c];
            float p1 = KP[(r0 + 1) * 65 + c];
            float p2 = KP[(r0 + 2) * 65 + c];
            float p3 = KP[(r0 + 3) * 65 + c];
#pragma unroll
            for (int j = 0; j < 4; j++) {
                o[0][j] = fmaf(p0, vv[j], o[0][j]);
                o[1][j] = fmaf(p1, vv[j], o[1][j]);
                o[2][j] = fmaf(p2, vv[j], o[2][j]);
                o[3][j] = fmaf(p3, vv[j], o[3][j]);
            }
        }
    }

    float* ob = attn + (size_t)(b * S_ + l0) * 512 + h * 64;
#pragma unroll
    for (int i = 0; i < 4; i++) {
        float inv = 1.f / lrow[i];
        float4 v;
        v.x = o[i][0] * inv; v.y = o[i][1] * inv;
        v.z = o[i][2] * inv; v.w = o[i][3] * inv;
        *(float4*)(ob + (size_t)(r0 + i) * 512 + c0) = v;
    }
}

// ---------------- prefill LayerNorm over rows of 512 ----------------
__global__ void __launch_bounds__(256) ln_rows(const float* __restrict__ in,
                                               const float* __restrict__ g,
                                               const float* __restrict__ be,
                                               float* __restrict__ out, int outExtra)
{
    const int r = blockIdx.x;
    const int tid = threadIdx.x;
    const float* row = in + (size_t)r * 512;
    float v0 = row[tid], v1 = row[tid + 256];
    float s  = warpRedSum(v0 + v1);
    float s2 = warpRedSum(v0 * v0 + v1 * v1);
    __shared__ float r1[8], r2[8];
    __shared__ float smu, srs;
    const int w = tid >> 5, lane = tid & 31;
    if (lane == 0) { r1[w] = s; r2[w] = s2; }
    __syncthreads();
    if (tid == 0) {
        float S = 0.f, S2 = 0.f;
#pragma unroll
        for (int i = 0; i < 8; i++) { S += r1[i]; S2 += r2[i]; }
        float mu  = S * (1.f / 512.f);
        float var = S2 * (1.f / 512.f) - mu * mu;
        smu = mu; srs = rsqrtf(var + 1e-5f);
    }
    __syncthreads();
    const int orow = r + (r >> 10) * outExtra;
    float* od = out + (size_t)orow * 512;
    od[tid]       = (v0 - smu) * srs * g[tid]       + be[tid];
    od[tid + 256] = (v1 - smu) * srs * g[tid + 256] + be[tid + 256];
}

// ---------------- megakernel building blocks ----------------
template<int KP>
__device__ __forceinline__ void dot4(const float* __restrict__ wr,
                                     const float* xs, int Kstride, int lane,
                                     float& a0, float& a1, float& a2, float& a3)
{
    a0 = a1 = a2 = a3 = 0.f;
#pragma unroll
    for (int kp = 0; kp < KP; kp++) {
        const int k4 = kp * 128 + lane * 4;
        float4 wv = *(const float4*)(wr + k4);
        float4 x0 = *(const float4*)(xs + k4);
        float4 x1 = *(const float4*)(xs + Kstride + k4);
        float4 x2 = *(const float4*)(xs + 2 * Kstride + k4);
        float4 x3 = *(const float4*)(xs + 3 * Kstride + k4);
        a0 = fmaf(wv.x, x0.x, fmaf(wv.y, x0.y, fmaf(wv.z, x0.z, fmaf(wv.w, x0.w, a0))));
        a1 = fmaf(wv.x, x1.x, fmaf(wv.y, x1.y, fmaf(wv.z, x1.z, fmaf(wv.w, x1.w, a1))));
        a2 = fmaf(wv.x, x2.x, fmaf(wv.y, x2.y, fmaf(wv.z, x2.z, fmaf(wv.w, x2.w, a2))));
        a3 = fmaf(wv.x, x3.x, fmaf(wv.y, x3.y, fmaf(wv.z, x3.z, fmaf(wv.w, x3.w, a3))));
    }
    a0 = warpRedSum(a0); a1 = warpRedSum(a1);
    a2 = warpRedSum(a2); a3 = warpRedSum(a3);
}

__device__ __forceinline__ void warp_ln(const float* __restrict__ a,
                                        const float* r,
                                        const float* __restrict__ gw,
                                        const float* __restrict__ gb,
                                        float* o, int lane)
{
    float vals[16];
    float sv = 0.f, sq = 0.f;
#pragma unroll
    for (int g = 0; g < 4; g++) {
        const int idx = g * 128 + lane * 4;
        float4 av = __ldcg((const float4*)(a + idx));
        float4 rv = *(const float4*)(r + idx);
        float a0 = av.x + rv.x, a1 = av.y + rv.y;
        float a2 = av.z + rv.z, a3 = av.w + rv.w;
        vals[g * 4 + 0] = a0; vals[g * 4 + 1] = a1;
        vals[g * 4 + 2] = a2; vals[g * 4 + 3] = a3;
        sv += a0 + a1 + a2 + a3;
        sq += a0 * a0 + a1 * a1 + a2 * a2 + a3 * a3;
    }
    sv = warpRedSum(sv); sq = warpRedSum(sq);
    float mu = sv * (1.f / 512.f);
    float rs = rsqrtf(sq * (1.f / 512.f) - mu * mu + 1e-5f);
#pragma unroll
    for (int g = 0; g < 4; g++)
#pragma unroll
        for (int j = 0; j < 4; j++) {
            const int idx = g * 128 + lane * 4 + j;
            o[idx] = (vals[g * 4 + j] - mu) * rs * gw[idx] + gb[idx];
        }
}

// ---------------- decode megakernel ----------------
__global__ void __launch_bounds__(256, 1) decode_mega(
    const float* __restrict__ dx,
    const float* __restrict__ qkvW, const float* __restrict__ qkvB,
    const float* __restrict__ outW, const float* __restrict__ outB,
    const float* __restrict__ w1, const float* __restrict__ b1,
    const float* __restrict__ w2, const float* __restrict__ b2,
    const float* __restrict__ ln1w, const float* __restrict__ ln1b,
    const float* __restrict__ ln2w, const float* __restrict__ ln2b,
    float* __restrict__ out,
    float* __restrict__ qt, float* __restrict__ kc, float* __restrict__ vc,
    float* __restrict__ hfft, float* __restrict__ t1,
    float* __restrict__ opart, float* __restrict__ mlpart)
{
    extern __shared__ float xs[];      // 8192 floats (32KB)
    __shared__ float s_ln[4 * 512];
    __shared__ float s_red[16];
    __shared__ float s_q[64];
    __shared__ float s_part[256];
    __shared__ float s_comb[128];
    __shared__ unsigned s_base;

    const int tid  = threadIdx.x;
    const int bid  = blockIdx.x;
    const int w    = tid >> 5, lane = tid & 31;
    const int half = bid >> 6;
    const int b0   = half * 4;
    const int wg   = (bid & 63) * 8 + w;

    if (tid == 0) s_base = ld_acq(&g_bar_sense);
    __syncthreads();
    unsigned target = s_base;

    for (int step = 0; step < STEPS_; step++) {
        const int cur = S_ + step;
        const float* xt = dx + (size_t)step * (B_ * D_);

        // ===== phase A: LN2(prev) on blocks 0 & 64 + QKV GEMV =====
        if (step > 0 && (bid == 0 || bid == 64) && w < 4)
            warp_ln(t1 + (b0 + w) * 512, s_ln + w * 512, ln2w, ln2b,
                    out + ((size_t)(b0 + w) * CAP_ + (cur - 1)) * 512, lane);
        {
            const float4* src = (const float4*)(xt + b0 * 512);
            float4* dst = (float4*)xs;
            for (int i = tid; i < 512; i += 256) dst[i] = src[i];
        }
        __syncthreads();
#pragma unroll
        for (int o = 0; o < 3; o++) {
            const int n = wg + o * 512;
            float a0, a1, a2, a3;
            dot4<4>(qkvW + (size_t)n * 512, xs, 512, lane, a0, a1, a2, a3);
            if (lane == 0) {
                const float bv = qkvB[n];
                if (o == 0) {
                    __stcg(&qt[(b0 + 0) * 512 + wg], a0 + bv);
                    __stcg(&qt[(b0 + 1) * 512 + wg], a1 + bv);
                    __stcg(&qt[(b0 + 2) * 512 + wg], a2 + bv);
                    __stcg(&qt[(b0 + 3) * 512 + wg], a3 + bv);
                } else if (o == 1) {
                    __stcg(&kc[((size_t)(b0 + 0) * CAP_ + cur) * 512 + wg], a0 + bv);
                    __stcg(&kc[((size_t)(b0 + 1) * CAP_ + cur) * 512 + wg], a1 + bv);
                    __stcg(&kc[((size_t)(b0 + 2) * CAP_ + cur) * 512 + wg], a2 + bv);
                    __stcg(&kc[((size_t)(b0 + 3) * CAP_ + cur) * 512 + wg], a3 + bv);
                } else {
                    __stcg(&vc[((size_t)(b0 + 0) * CAP_ + cur) * 512 + wg], a0 + bv);
                    __stcg(&vc[((size_t)(b0 + 1) * CAP_ + cur) * 512 + wg], a1 + bv);
                    __stcg(&vc[((size_t)(b0 + 2) * CAP_ + cur) * 512 + wg], a2 + bv);
                    __stcg(&vc[((size_t)(b0 + 3) * CAP_ + cur) * 512 + wg], a3 + bv);
                }
            }
        }
        gbar(target, tid);

        // ===== phase B: attention partials, 128 blocks = (part, b, h) =====
        {
            const int part = bid >> 6;
            const int bb = (bid >> 3) & 7;
            const int h  = bid & 7;
            const int kvlen = cur + 1;
            const int hlen  = kvlen >> 1;
            const int tstart = part ? hlen : 0;
            const int tend   = part ? kvlen : hlen;
            if (tid < 64) s_q[tid] = __ldcg(&qt[bb * 512 + h * 64 + tid]);
            __syncthreads();
            const int tl = lane >> 2;
            const int kq = (lane & 3) * 16;
            const float4 qa = *(const float4*)(s_q + kq);
            const float4 qb = *(const float4*)(s_q + kq + 4);
            const float4 qc = *(const float4*)(s_q + kq + 8);
            const float4 qd = *(const float4*)(s_q + kq + 12);
            const float* kb = kc + (size_t)bb * CAP_ * 512 + h * 64;
            for (int t0 = tstart; t0 < tend; t0 += 64) {
                const int t = t0 + w * 8 + tl;
                const bool valid = t < tend;
                const float* kr = kb + (size_t)(valid ? t : tstart) * 512 + kq;
                float4 k0 = __ldcg((const float4*)(kr));
                float4 k1 = __ldcg((const float4*)(kr + 4));
                float4 k2 = __ldcg((const float4*)(kr + 8));
                float4 k3 = __ldcg((const float4*)(kr + 12));
                float s;
                s = k0.x * qa.x;
                s = fmaf(k0.y, qa.y, s); s = fmaf(k0.z, qa.z, s); s = fmaf(k0.w, qa.w, s);
                s = fmaf(k1.x, qb.x, s); s = fmaf(k1.y, qb.y, s);
                s = fmaf(k1.z, qb.z, s); s = fmaf(k1.w, qb.w, s);
                s = fmaf(k2.x, qc.x, s); s = fmaf(k2.y, qc.y, s);
                s = fmaf(k2.z, qc.z, s); s = fmaf(k2.w, qc.w, s);
                s = fmaf(k3.x, qd.x, s); s = fmaf(k3.y, qd.y, s);
                s = fmaf(k3.w, qd.w, s); s = fmaf(k3.z, qd.z, s);
                s += __shfl_xor_sync(0xffffffffu, s, 1);
                s += __shfl_xor_sync(0xffffffffu, s, 2);
                if (valid && (lane & 3) == 0) xs[t] = s * 0.125f;
            }
            __syncthreads();
            float lmax = -1e30f;
            for (int t = tstart + tid; t < tend; t += 256) lmax = fmaxf(lmax, xs[t]);
            lmax = warpRedMax(lmax);
            if (lane == 0) s_red[w] = lmax;
            __syncthreads();
            float gm = s_red[0];
#pragma unroll
            for (int i = 1; i < 8; i++) gm = fmaxf(gm, s_red[i]);
            float ls = 0.f;
            for (int t = tstart + tid; t < tend; t += 256) {
                float p = __expf(xs[t] - gm);
                xs[t] = p;
                ls += p;
            }
            ls = warpRedSum(ls);
            if (lane == 0) s_red[8 + w] = ls;
            __syncthreads();
            float ssum = 0.f;
#pragma unroll
            for (int i = 0; i < 8; i++) ssum += s_red[8 + i];
            const int d = tid & 63, pt = tid >> 6;
            const float* vb = vc + (size_t)bb * CAP_ * 512 + h * 64 + d;
            float vacc = 0.f;
            for (int t = tstart + pt; t < tend; t += 4)
                vacc = fmaf(xs[t], __ldcg(vb + (size_t)t * 512), vacc);
            s_part[tid] = vacc;
            __syncthreads();
            const int gi = part * 64 + bb * 8 + h;
            if (pt == 0)
                __stcg(&opart[gi * 64 + d],
                       s_part[d] + s_part[64 + d] + s_part[128 + d] + s_part[192 + d]);
            if (tid == 0) {
                __stcg(&mlpart[gi * 2], gm);
                __stcg(&mlpart[gi * 2 + 1], ssum);
            }
        }
        gbar(target, tid);

        // ===== phase C: combine attn parts + out-proj =====
        if (tid < 64) {
            float m1 = __ldcg(&mlpart[tid * 2]);
            float l1 = __ldcg(&mlpart[tid * 2 + 1]);
            float m2 = __ldcg(&mlpart[(64 + tid) * 2]);
            float l2 = __ldcg(&mlpart[(64 + tid) * 2 + 1]);
            float gm = fmaxf(m1, m2);
            float e1 = __expf(m1 - gm), e2 = __expf(m2 - gm);
            float inv = 1.f / (e1 * l1 + e2 * l2);
            s_comb[tid * 2]     = e1 * inv;
            s_comb[tid * 2 + 1] = e2 * inv;
        }
        __syncthreads();
        for (int i = tid; i < 2048; i += 256) {
            const int b = b0 + (i >> 9);
            const int col = i & 511;
            const int gi = b * 8 + (col >> 6);
            const int d = col & 63;
            xs[i] = s_comb[gi * 2]     * __ldcg(&opart[gi * 64 + d])
                  + s_comb[gi * 2 + 1] * __ldcg(&opart[(64 + gi) * 64 + d]);
        }
        __syncthreads();
        {
            float a0, a1, a2, a3;
            dot4<4>(outW + (size_t)wg * 512, xs, 512, lane, a0, a1, a2, a3);
            if (lane == 0) {
                const float bv = outB[wg];
                __stcg(&t1[(b0 + 0) * 512 + wg], a0 + bv);
                __stcg(&t1[(b0 + 1) * 512 + wg], a1 + bv);
                __stcg(&t1[(b0 + 2) * 512 + wg], a2 + bv);
                __stcg(&t1[(b0 + 3) * 512 + wg], a3 + bv);
            }
        }
        gbar(target, tid);

        // ===== phase E: LN1 (warps 0-3, into s_ln) + FF1 (N=2048, relu) =====
        if (w < 4)
            warp_ln(t1 + (b0 + w) * 512, xt + (b0 + w) * 512,
                    ln1w, ln1b, s_ln + w * 512, lane);
        __syncthreads();
#pragma unroll
        for (int o = 0; o < 4; o++) {
            const int n = wg + o * 512;
            float a0, a1, a2, a3;
            dot4<4>(w1 + (size_t)n * 512, s_ln, 512, lane, a0, a1, a2, a3);
            if (lane == 0) {
                const float bv = b1[n];
                __stcg(&hfft[(b0 + 0) * 2048 + n], fmaxf(a0 + bv, 0.f));
                __stcg(&hfft[(b0 + 1) * 2048 + n], fmaxf(a1 + bv, 0.f));
                __stcg(&hfft[(b0 + 2) * 2048 + n], fmaxf(a2 + bv, 0.f));
                __stcg(&hfft[(b0 + 3) * 2048 + n], fmaxf(a3 + bv, 0.f));
            }
        }
        gbar(target, tid);

        // ===== phase F: FF2 (N=512, K=2048) -> t1 =====
        {
            const float4* src = (const float4*)(hfft + b0 * 2048);
            float4* dst = (float4*)xs;
            for (int i = tid; i < 2048; i += 256) dst[i] = __ldcg(src + i);
        }
        __syncthreads();
        {
            float a0, a1, a2, a3;
            dot4<16>(w2 + (size_t)wg * 2048, xs, 2048, lane, a0, a1, a2, a3);
            if (lane == 0) {
                const float bv = b2[wg];
                __stcg(&t1[(b0 + 0) * 512 + wg], a0 + bv);
                __stcg(&t1[(b0 + 1) * 512 + wg], a1 + bv);
                __stcg(&t1[(b0 + 2) * 512 + wg], a2 + bv);
                __stcg(&t1[(b0 + 3) * 512 + wg], a3 + bv);
            }
        }
        gbar(target, tid);
    }

    // final LN2 for the last step
    if ((bid == 0 || bid == 64) && w < 4)
        warp_ln(t1 + (b0 + w) * 512, s_ln + w * 512, ln2w, ln2b,
                out + ((size_t)(b0 + w) * CAP_ + (S_ + STEPS_ - 1)) * 512, lane);
}

// ---------------- host launcher ----------------
struct ScratchPtrs {
    float *Qkv, *Attn, *Pre, *Hb, *Hff, *Kc, *Vc, *Qt, *Hfft, *T1, *Op, *Ml;
    cudaStream_t sDec;
    cudaEvent_t evQkv, evDec;
};

static const ScratchPtrs& get_scratch() {
    static ScratchPtrs p;
    static bool init = false;
    if (!init) {
        cudaGetSymbolAddress((void**)&p.Qkv,  g_qkv);
        cudaGetSymbolAddress((void**)&p.Attn, g_attn);
        cudaGetSymbolAddress((void**)&p.Pre,  g_pre);
        cudaGetSymbolAddress((void**)&p.Hb,   g_h);
        cudaGetSymbolAddress((void**)&p.Hff,  g_hff);
        cudaGetSymbolAddress((void**)&p.Kc,   g_kc);
        cudaGetSymbolAddress((void**)&p.Vc,   g_vc);
        cudaGetSymbolAddress((void**)&p.Qt,   g_qt);
        cudaGetSymbolAddress((void**)&p.Hfft, g_hfft);
        cudaGetSymbolAddress((void**)&p.T1,   g_t1);
        cudaGetSymbolAddress((void**)&p.Op,   g_op);
        cudaGetSymbolAddress((void**)&p.Ml,   g_ml);
        cudaFuncSetAttribute(attn_prefill,
                             cudaFuncAttributeMaxDynamicSharedMemorySize, 49408);
        cudaFuncSetAttribute(decode_mega,
                             cudaFuncAttributeMaxDynamicSharedMemorySize, 32768);
        cudaStreamCreateWithFlags(&p.sDec, cudaStreamNonBlocking);
        cudaEventCreateWithFlags(&p.evQkv, cudaEventDisableTiming);
        cudaEventCreateWithFlags(&p.evDec, cudaEventDisableTiming);
        init = true;
    }
    return p;
}

extern "C" void kernel_launch(void* const* d_in, const int* in_sizes, int n_in,
                              void* d_out, int out_size)
{
    (void)in_sizes; (void)n_in; (void)out_size;
    const float* x    = (const float*)d_in[0];
    const float* dx   = (const float*)d_in[1];
    // d_in[2] = causal_mask (bool) — unused, causality computed analytically
    const float* qkvW = (const float*)d_in[3];
    const float* qkvB = (const float*)d_in[4];
    const float* outW = (const float*)d_in[5];
    const float* outB = (const float*)d_in[6];
    const float* w1   = (const float*)d_in[7];
    const float* b1   = (const float*)d_in[8];
    const float* w2   = (const float*)d_in[9];
    const float* b2   = (const float*)d_in[10];
    const float* ln1w = (const float*)d_in[11];
    const float* ln1b = (const float*)d_in[12];
    const float* ln2w = (const float*)d_in[13];
    const float* ln2b = (const float*)d_in[14];
    float* out = (float*)d_out;

    const ScratchPtrs& sp = get_scratch();

    // ---- QKV GEMM (also seeds decode K/V caches) on the main stream ----
    sgemm_nt<1,0,0,1><<<dim3(12, 64), 256>>>(x, qkvW, qkvB, nullptr, sp.Qkv,
                                             MTOK, 1536, 512, sp.Kc, sp.Vc);

    // ---- fork: decode runs concurrently with the rest of prefill ----
    cudaEventRecord(sp.evQkv, 0);
    cudaStreamWaitEvent(sp.sDec, sp.evQkv, 0);
    decode_mega<<<NBLK, 256, 32768, sp.sDec>>>(dx, qkvW, qkvB, outW, outB,
                                               w1, b1, w2, b2,
                                               ln1w, ln1b, ln2w, ln2b, out,
                                               sp.Qt, sp.Kc, sp.Vc,
                                               sp.Hfft, sp.T1, sp.Op, sp.Ml);
    cudaEventRecord(sp.evDec, sp.sDec);

    // ---- rest of prefill on the main stream ----
    attn_prefill<<<dim3(16, 64), 256, 49408>>>(sp.Qkv, sp.Attn);
    sgemm_nt<1,0,1,0><<<dim3(4, 64), 256>>>(sp.Attn, outW, outB, x, sp.Pre,
                                            MTOK, 512, 512, nullptr, nullptr);
    ln_rows<<<MTOK, 256>>>(sp.Pre, ln1w, ln1b, sp.Hb, 0);
    sgemm_nt<1,1,0,0><<<dim3(16, 64), 256>>>(sp.Hb, w1, b1, nullptr, sp.Hff,
                                             MTOK, 2048, 512, nullptr, nullptr);
    sgemm_nt<1,0,1,0><<<dim3(4, 64), 256>>>(sp.Hff, w2, b2, sp.Hb, sp.Pre,
                                            MTOK, 512, 2048, nullptr, nullptr);
    ln_rows<<<MTOK, 256>>>(sp.Pre, ln2w, ln2b, out, 64);

    // ---- join: main stream completes only after decode finishes ----
    cudaStreamWaitEvent(0, sp.evDec, 0);
}

// round 10
// speedup vs baseline: 1.1737x; 1.0004x over previous
#include <cuda_runtime.h>
#include <cstdint>

#define B_     8
#define S_     1024
#define D_     512
#define H_     8
#define HD_    64
#define FF_    2048
#define STEPS_ 64
#define CAP_   1088
#define MTOK   (B_*S_)   /* 8192 */
#define NBLK   128

// ---------------- device scratch (no cudaMalloc allowed) ----------------
__device__ float g_qkv [MTOK*1536];
__device__ float g_attn[MTOK*D_];
__device__ float g_pre [MTOK*D_];
__device__ float g_h   [MTOK*D_];
__device__ float g_hff [MTOK*FF_];
__device__ float g_kc  [B_*CAP_*D_];
__device__ float g_vc  [B_*CAP_*D_];
__device__ float g_qt  [B_*D_];
__device__ float g_hfft[B_*FF_];
__device__ float g_t1  [B_*D_];
__device__ float g_op  [2*64*64];
__device__ float g_ml  [2*64*2];
__device__ unsigned g_bar_count;
__device__ unsigned g_bar_sense;

// ---------------- reductions ----------------
__device__ __forceinline__ float warpRedSum(float v) {
#pragma unroll
    for (int o = 16; o; o >>= 1) v += __shfl_xor_sync(0xffffffffu, v, o);
    return v;
}
__device__ __forceinline__ float warpRedMax(float v) {
#pragma unroll
    for (int o = 16; o; o >>= 1) v = fmaxf(v, __shfl_xor_sync(0xffffffffu, v, o));
    return v;
}

// ---------------- fence-free global barrier (.cg data protocol) ----------------
__device__ __forceinline__ unsigned ld_acq(const unsigned* p) {
    unsigned v;
    asm volatile("ld.acquire.gpu.u32 %0, [%1];" : "=r"(v) : "l"(p) : "memory");
    return v;
}
__device__ __forceinline__ void st_rel(unsigned* p, unsigned v) {
    asm volatile("st.release.gpu.u32 [%0], %1;" :: "l"(p), "r"(v) : "memory");
}
__device__ __forceinline__ unsigned atomAddAcqRel(unsigned* p, unsigned v) {
    unsigned old;
    asm volatile("atom.acq_rel.gpu.global.add.u32 %0, [%1], %2;"
                 : "=r"(old) : "l"(p), "r"(v) : "memory");
    return old;
}
__device__ __forceinline__ void gbar(unsigned& target, int tid) {
    __syncthreads();
    target += 1;
    if (tid == 0) {
        unsigned a = atomAddAcqRel(&g_bar_count, 1u) + 1u;
        if (a == (unsigned)NBLK) {
            atomicExch(&g_bar_count, 0u);
            st_rel(&g_bar_sense, target);
        } else {
            while ((int)(ld_acq(&g_bar_sense) - target) < 0) { }
        }
    }
    __syncthreads();
}

// ---------------- 3xTF32 helpers ----------------
__device__ __forceinline__ float tf32_rna(float v) {
    unsigned u;
    asm("cvt.rna.tf32.f32 %0, %1;" : "=r"(u) : "f"(v));
    return __uint_as_float(u);
}

__device__ __forceinline__ void mma4x4(const unsigned a[4][4],
                                       const unsigned b[4][2],
                                       float acc[4][4][4])
{
#pragma unroll
    for (int mt = 0; mt < 4; mt++)
#pragma unroll
        for (int nt = 0; nt < 4; nt++) {
            asm volatile(
                "mma.sync.aligned.m16n8k8.row.col.f32.tf32.tf32.f32 "
                "{%0,%1,%2,%3}, {%4,%5,%6,%7}, {%8,%9}, {%0,%1,%2,%3};"
                : "+f"(acc[mt][nt][0]), "+f"(acc[mt][nt][1]),
                  "+f"(acc[mt][nt][2]), "+f"(acc[mt][nt][3])
                : "r"(a[mt][0]), "r"(a[mt][1]), "r"(a[mt][2]), "r"(a[mt][3]),
                  "r"(b[nt][0]), "r"(b[nt][1]));
        }
}

// ---------------- SGEMM (NT) via 3xTF32 tensor-core mma, hoisted frags ----------
// BM=BN=128, BK=16, 256 threads (8 warps, 2x4), warp tile 64x32.
template<int BIAS, int RELU, int RES, int KVOUT>
__global__ void __launch_bounds__(256, 2) sgemm_nt(
    const float* __restrict__ A, const float* __restrict__ Bm,
    const float* __restrict__ bias, const float* __restrict__ R,
    float* __restrict__ C, int M, int N, int K,
    float* __restrict__ kc, float* __restrict__ vc)
{
    __shared__ float Ah[16][132], Al[16][132];
    __shared__ float Bh[16][132], Bl[16][132];
    const int tid = threadIdx.x;
    const int m0 = blockIdx.y * 128;
    const int n0 = blockIdx.x * 128;
    const int w = tid >> 5, lane = tid & 31;
    const int wm0 = (w >> 2) * 64;
    const int wn0 = (w & 3) * 32;
    const int g = lane >> 2, tq = lane & 3;
    const int lrow = tid >> 2;
    const int lk4  = (tid & 3) * 4;

    const float* Ap0 = A  + (size_t)(m0 + lrow)      * K + lk4;
    const float* Ap1 = A  + (size_t)(m0 + lrow + 64) * K + lk4;
    const float* Bp0 = Bm + (size_t)(n0 + lrow)      * K + lk4;
    const float* Bp1 = Bm + (size_t)(n0 + lrow + 64) * K + lk4;

    float acc[4][4][4];
#pragma unroll
    for (int i = 0; i < 4; i++)
#pragma unroll
        for (int j = 0; j < 4; j++)
#pragma unroll
            for (int q = 0; q < 4; q++) acc[i][j][q] = 0.f;

    float4 pa0 = *(const float4*)(Ap0);
    float4 pa1 = *(const float4*)(Ap1);
    float4 pb0 = *(const float4*)(Bp0);
    float4 pb1 = *(const float4*)(Bp1);

    for (int k0 = 0; k0 < K; k0 += 16) {
        {
            const float va[8] = {pa0.x, pa0.y, pa0.z, pa0.w,
                                 pa1.x, pa1.y, pa1.z, pa1.w};
            const float vb[8] = {pb0.x, pb0.y, pb0.z, pb0.w,
                                 pb1.x, pb1.y, pb1.z, pb1.w};
#pragma unroll
            for (int i = 0; i < 4; i++) {
                float h;
                h = tf32_rna(va[i]);
                Ah[lk4 + i][lrow] = h;      Al[lk4 + i][lrow] = va[i] - h;
                h = tf32_rna(va[4 + i]);
                Ah[lk4 + i][lrow + 64] = h; Al[lk4 + i][lrow + 64] = va[4 + i] - h;
                h = tf32_rna(vb[i]);
                Bh[lk4 + i][lrow] = h;      Bl[lk4 + i][lrow] = vb[i] - h;
                h = tf32_rna(vb[4 + i]);
                Bh[lk4 + i][lrow + 64] = h; Bl[lk4 + i][lrow + 64] = vb[4 + i] - h;
            }
        }
        __syncthreads();
        if (k0 + 16 < K) {   // prefetch next tile under compute
            pa0 = *(const float4*)(Ap0 + k0 + 16);
            pa1 = *(const float4*)(Ap1 + k0 + 16);
            pb0 = *(const float4*)(Bp0 + k0 + 16);
            pb1 = *(const float4*)(Bp1 + k0 + 16);
        }
#pragma unroll
        for (int ks = 0; ks < 16; ks += 8) {
            // hoisted fragment loads: each smem byte read once per slice
            unsigned ah[4][4], bh[4][2];
#pragma unroll
            for (int mt = 0; mt < 4; mt++) {
                const int mb = wm0 + mt * 16 + g;
                ah[mt][0] = __float_as_uint(Ah[ks + tq][mb]);
                ah[mt][1] = __float_as_uint(Ah[ks + tq][mb + 8]);
                ah[mt][2] = __float_as_uint(Ah[ks + tq + 4][mb]);
                ah[mt][3] = __float_as_uint(Ah[ks + tq + 4][mb + 8]);
            }
#pragma unroll
            for (int nt = 0; nt < 4; nt++) {
                bh[nt][0] = __float_as_uint(Bh[ks + tq][wn0 + nt * 8 + g]);
                bh[nt][1] = __float_as_uint(Bh[ks + tq + 4][wn0 + nt * 8 + g]);
            }
            mma4x4(ah, bh, acc);                    // hi*hi
            {
                unsigned bl[4][2];
#pragma unroll
                for (int nt = 0; nt < 4; nt++) {
                    bl[nt][0] = __float_as_uint(Bl[ks + tq][wn0 + nt * 8 + g]);
                    bl[nt][1] = __float_as_uint(Bl[ks + tq + 4][wn0 + nt * 8 + g]);
                }
                mma4x4(ah, bl, acc);                // hi*lo
            }
            {
                unsigned al[4][4];
#pragma unroll
                for (int mt = 0; mt < 4; mt++) {
                    const int mb = wm0 + mt * 16 + g;
                    al[mt][0] = __float_as_uint(Al[ks + tq][mb]);
                    al[mt][1] = __float_as_uint(Al[ks + tq][mb + 8]);
                    al[mt][2] = __float_as_uint(Al[ks + tq + 4][mb]);
                    al[mt][3] = __float_as_uint(Al[ks + tq + 4][mb + 8]);
                }
                mma4x4(al, bh, acc);                // lo*hi
            }
        }
        __syncthreads();
    }

    // epilogue: pairs (col, col+1) per fragment, rows g and g+8 per 16-tile
#pragma unroll
    for (int nt = 0; nt < 4; nt++) {
        const int col = n0 + wn0 + nt * 8 + tq * 2;
        const float b0v = BIAS ? bias[col] : 0.f;
        const float b1v = BIAS ? bias[col + 1] : 0.f;
#pragma unroll
        for (int mt = 0; mt < 4; mt++) {
#pragma unroll
            for (int rh = 0; rh < 2; rh++) {
                const int row = m0 + wm0 + mt * 16 + g + rh * 8;
                float t0 = acc[mt][nt][rh * 2 + 0] + b0v;
                float t1 = acc[mt][nt][rh * 2 + 1] + b1v;
                if (RES) {
                    float2 r = *(const float2*)(R + (size_t)row * N + col);
                    t0 += r.x; t1 += r.y;
                }
                if (RELU) { t0 = fmaxf(t0, 0.f); t1 = fmaxf(t1, 0.f); }
                float2 v; v.x = t0; v.y = t1;
                *(float2*)(C + (size_t)row * N + col) = v;
                if (KVOUT && col >= 512) {
                    const int bb = row >> 10, ss = row & 1023;
                    float* dst = (col < 1024)
                        ? kc + ((size_t)(bb * CAP_ + ss) * 512 + (col - 512))
                        : vc + ((size_t)(bb * CAP_ + ss) * 512 + (col - 1024));
                    *(float2*)dst = v;
                }
            }
        }
    }
}

// ---------------- prefill flash attention (causal), 64x64 tiles ----------------
__global__ void __launch_bounds__(256) attn_prefill(const float* __restrict__ qkv,
                                                    float* __restrict__ attn)
{
    extern __shared__ float sm[];
    float* Qs = sm;
    float* KP = sm + 64 * 64;
    float* Vs = KP + 64 * 65;

    const int b  = blockIdx.y >> 3;
    const int h  = blockIdx.y & 7;
    const int l0 = blockIdx.x * 64;
    const int tid = threadIdx.x;
    const int tx = tid & 15, ty = tid >> 4;
    const int r0 = ty * 4, c0 = tx * 4;

    const size_t rowbase = (size_t)(b * S_) * 1536;
    const float* qbase = qkv + rowbase + h * 64;
    const float* kbase = qkv + rowbase + 512 + h * 64;
    const float* vbase = qkv + rowbase + 1024 + h * 64;

    const int lt  = tid >> 4;
    const int ld4 = (tid & 15) * 4;

#pragma unroll
    for (int tt = lt; tt < 64; tt += 16) {
        float4 q4 = *(const float4*)(qbase + (size_t)(l0 + tt) * 1536 + ld4);
        Qs[(ld4 + 0) * 64 + tt] = q4.x;
        Qs[(ld4 + 1) * 64 + tt] = q4.y;
        Qs[(ld4 + 2) * 64 + tt] = q4.z;
        Qs[(ld4 + 3) * 64 + tt] = q4.w;
    }

    float o[4][4];
    float mrow[4], lrow[4];
#pragma unroll
    for (int i = 0; i < 4; i++) {
        mrow[i] = -1e30f; lrow[i] = 0.f;
#pragma unroll
        for (int j = 0; j < 4; j++) o[i][j] = 0.f;
    }

    const int ntiles = (l0 >> 6) + 1;
    for (int tile = 0; tile < ntiles; ++tile) {
        const int j0 = tile * 64;
        __syncthreads();
#pragma unroll
        for (int tt = lt; tt < 64; tt += 16) {
            float4 k4 = *(const float4*)(kbase + (size_t)(j0 + tt) * 1536 + ld4);
            KP[(ld4 + 0) * 65 + tt] = k4.x;
            KP[(ld4 + 1) * 65 + tt] = k4.y;
            KP[(ld4 + 2) * 65 + tt] = k4.z;
            KP[(ld4 + 3) * 65 + tt] = k4.w;
            float4 v4 = *(const float4*)(vbase + (size_t)(j0 + tt) * 1536 + ld4);
            *(float4*)(Vs + tt * 64 + ld4) = v4;
        }
        __syncthreads();

        float s[4][4];
#pragma unroll
        for (int i = 0; i < 4; i++)
#pragma unroll
            for (int j = 0; j < 4; j++) s[i][j] = 0.f;

        for (int d = 0; d < 64; d++) {
            float qf[4];
            *(float4*)qf = *(const float4*)(Qs + d * 64 + r0);
            float kf0 = KP[d * 65 + c0 + 0];
            float kf1 = KP[d * 65 + c0 + 1];
            float kf2 = KP[d * 65 + c0 + 2];
            float kf3 = KP[d * 65 + c0 + 3];
#pragma unroll
            for (int i = 0; i < 4; i++) {
                s[i][0] = fmaf(qf[i], kf0, s[i][0]);
                s[i][1] = fmaf(qf[i], kf1, s[i][1]);
                s[i][2] = fmaf(qf[i], kf2, s[i][2]);
                s[i][3] = fmaf(qf[i], kf3, s[i][3]);
            }
        }

        if (j0 == l0) {
#pragma unroll
            for (int i = 0; i < 4; i++)
#pragma unroll
                for (int j = 0; j < 4; j++)
                    s[i][j] = (j0 + c0 + j > l0 + r0 + i) ? -1e30f : s[i][j] * 0.125f;
        } else {
#pragma unroll
            for (int i = 0; i < 4; i++)
#pragma unroll
                for (int j = 0; j < 4; j++) s[i][j] *= 0.125f;
        }

        float p[4][4];
#pragma unroll
        for (int i = 0; i < 4; i++) {
            float rm = fmaxf(fmaxf(s[i][0], s[i][1]), fmaxf(s[i][2], s[i][3]));
#pragma unroll
            for (int off = 8; off; off >>= 1)
                rm = fmaxf(rm, __shfl_xor_sync(0xffffffffu, rm, off));
            float mnew  = fmaxf(mrow[i], rm);
            float alpha = __expf(mrow[i] - mnew);
            float ps = 0.f;
#pragma unroll
            for (int j = 0; j < 4; j++) { p[i][j] = __expf(s[i][j] - mnew); ps += p[i][j]; }
#pragma unroll
            for (int off = 8; off; off >>= 1)
                ps += __shfl_xor_sync(0xffffffffu, ps, off);
            lrow[i] = lrow[i] * alpha + ps;
            mrow[i] = mnew;
#pragma unroll
            for (int j = 0; j < 4; j++) o[i][j] *= alpha;
        }

        __syncthreads();
#pragma unroll
        for (int i = 0; i < 4; i++)
#pragma unroll
            for (int j = 0; j < 4; j++)
                KP[(r0 + i) * 65 + c0 + j] = p[i][j];
        __syncthreads();

        for (int c = 0; c < 64; c++) {
            float vv[4];
            *(float4*)vv = *(const float4*)(Vs + c * 64 + c0);
            float p0 = KP[(r0 + 0) * 65 + c];
            float p1 = KP[(r0 + 1) * 65 + c];
            float p2 = KP[(r0 + 2) * 65 + c];
            float p3 = KP[(r0 + 3) * 65 + c];
#pragma unroll
            for (int j = 0; j < 4; j++) {
                o[0][j] = fmaf(p0, vv[j], o[0][j]);
                o[1][j] = fmaf(p1, vv[j], o[1][j]);
                o[2][j] = fmaf(p2, vv[j], o[2][j]);
                o[3][j] = fmaf(p3, vv[j], o[3][j]);
            }
        }
    }

    float* ob = attn + (size_t)(b * S_ + l0) * 512 + h * 64;
#pragma unroll
    for (int i = 0; i < 4; i++) {
        float inv = 1.f / lrow[i];
        float4 v;
        v.x = o[i][0] * inv; v.y = o[i][1] * inv;
        v.z = o[i][2] * inv; v.w = o[i][3] * inv;
        *(float4*)(ob + (size_t)(r0 + i) * 512 + c0) = v;
    }
}

// ---------------- prefill LayerNorm over rows of 512 ----------------
__global__ void __launch_bounds__(256) ln_rows(const float* __restrict__ in,
                                               const float* __restrict__ g,
                                               const float* __restrict__ be,
                                               float* __restrict__ out, int outExtra)
{
    const int r = blockIdx.x;
    const int tid = threadIdx.x;
    const float* row = in + (size_t)r * 512;
    float v0 = row[tid], v1 = row[tid + 256];
    float s  = warpRedSum(v0 + v1);
    float s2 = warpRedSum(v0 * v0 + v1 * v1);
    __shared__ float r1[8], r2[8];
    __shared__ float smu, srs;
    const int w = tid >> 5, lane = tid & 31;
    if (lane == 0) { r1[w] = s; r2[w] = s2; }
    __syncthreads();
    if (tid == 0) {
        float S = 0.f, S2 = 0.f;
#pragma unroll
        for (int i = 0; i < 8; i++) { S += r1[i]; S2 += r2[i]; }
        float mu  = S * (1.f / 512.f);
        float var = S2 * (1.f / 512.f) - mu * mu;
        smu = mu; srs = rsqrtf(var + 1e-5f);
    }
    __syncthreads();
    const int orow = r + (r >> 10) * outExtra;
    float* od = out + (size_t)orow * 512;
    od[tid]       = (v0 - smu) * srs * g[tid]       + be[tid];
    od[tid + 256] = (v1 - smu) * srs * g[tid + 256] + be[tid + 256];
}

// ---------------- megakernel building blocks ----------------
template<int KP>
__device__ __forceinline__ void dot4(const float* __restrict__ wr,
                                     const float* xs, int Kstride, int lane,
                                     float& a0, float& a1, float& a2, float& a3)
{
    a0 = a1 = a2 = a3 = 0.f;
#pragma unroll
    for (int kp = 0; kp < KP; kp++) {
        const int k4 = kp * 128 + lane * 4;
        float4 wv = *(const float4*)(wr + k4);
        float4 x0 = *(const float4*)(xs + k4);
        float4 x1 = *(const float4*)(xs + Kstride + k4);
        float4 x2 = *(const float4*)(xs + 2 * Kstride + k4);
        float4 x3 = *(const float4*)(xs + 3 * Kstride + k4);
        a0 = fmaf(wv.x, x0.x, fmaf(wv.y, x0.y, fmaf(wv.z, x0.z, fmaf(wv.w, x0.w, a0))));
        a1 = fmaf(wv.x, x1.x, fmaf(wv.y, x1.y, fmaf(wv.z, x1.z, fmaf(wv.w, x1.w, a1))));
        a2 = fmaf(wv.x, x2.x, fmaf(wv.y, x2.y, fmaf(wv.z, x2.z, fmaf(wv.w, x2.w, a2))));
        a3 = fmaf(wv.x, x3.x, fmaf(wv.y, x3.y, fmaf(wv.z, x3.z, fmaf(wv.w, x3.w, a3))));
    }
    a0 = warpRedSum(a0); a1 = warpRedSum(a1);
    a2 = warpRedSum(a2); a3 = warpRedSum(a3);
}

__device__ __forceinline__ void warp_ln(const float* __restrict__ a,
                                        const float* r,
                                        const float* __restrict__ gw,
                                        const float* __restrict__ gb,
                                        float* o, int lane)
{
    float vals[16];
    float sv = 0.f, sq = 0.f;
#pragma unroll
    for (int g = 0; g < 4; g++) {
        const int idx = g * 128 + lane * 4;
        float4 av = __ldcg((const float4*)(a + idx));
        float4 rv = *(const float4*)(r + idx);
        float a0 = av.x + rv.x, a1 = av.y + rv.y;
        float a2 = av.z + rv.z, a3 = av.w + rv.w;
        vals[g * 4 + 0] = a0; vals[g * 4 + 1] = a1;
        vals[g * 4 + 2] = a2; vals[g * 4 + 3] = a3;
        sv += a0 + a1 + a2 + a3;
        sq += a0 * a0 + a1 * a1 + a2 * a2 + a3 * a3;
    }
    sv = warpRedSum(sv); sq = warpRedSum(sq);
    float mu = sv * (1.f / 512.f);
    float rs = rsqrtf(sq * (1.f / 512.f) - mu * mu + 1e-5f);
#pragma unroll
    for (int g = 0; g < 4; g++)
#pragma unroll
        for (int j = 0; j < 4; j++) {
            const int idx = g * 128 + lane * 4 + j;
            o[idx] = (vals[g * 4 + j] - mu) * rs * gw[idx] + gb[idx];
        }
}

// ---------------- decode megakernel ----------------
__global__ void __launch_bounds__(256, 1) decode_mega(
    const float* __restrict__ dx,
    const float* __restrict__ qkvW, const float* __restrict__ qkvB,
    const float* __restrict__ outW, const float* __restrict__ outB,
    const float* __restrict__ w1, const float* __restrict__ b1,
    const float* __restrict__ w2, const float* __restrict__ b2,
    const float* __restrict__ ln1w, const float* __restrict__ ln1b,
    const float* __restrict__ ln2w, const float* __restrict__ ln2b,
    float* __restrict__ out,
    float* __restrict__ qt, float* __restrict__ kc, float* __restrict__ vc,
    float* __restrict__ hfft, float* __restrict__ t1,
    float* __restrict__ opart, float* __restrict__ mlpart)
{
    extern __shared__ float xs[];      // 8192 floats (32KB)
    __shared__ float s_ln[4 * 512];
    __shared__ float s_red[16];
    __shared__ float s_q[64];
    __shared__ float s_part[256];
    __shared__ float s_comb[128];
    __shared__ unsigned s_base;

    const int tid  = threadIdx.x;
    const int bid  = blockIdx.x;
    const int w    = tid >> 5, lane = tid & 31;
    const int half = bid >> 6;
    const int b0   = half * 4;
    const int wg   = (bid & 63) * 8 + w;

    if (tid == 0) s_base = ld_acq(&g_bar_sense);
    __syncthreads();
    unsigned target = s_base;

    for (int step = 0; step < STEPS_; step++) {
        const int cur = S_ + step;
        const float* xt = dx + (size_t)step * (B_ * D_);

        // ===== phase A: LN2(prev) on blocks 0 & 64 + QKV GEMV =====
        if (step > 0 && (bid == 0 || bid == 64) && w < 4)
            warp_ln(t1 + (b0 + w) * 512, s_ln + w * 512, ln2w, ln2b,
                    out + ((size_t)(b0 + w) * CAP_ + (cur - 1)) * 512, lane);
        {
            const float4* src = (const float4*)(xt + b0 * 512);
            float4* dst = (float4*)xs;
            for (int i = tid; i < 512; i += 256) dst[i] = src[i];
        }
        __syncthreads();
#pragma unroll
        for (int o = 0; o < 3; o++) {
            const int n = wg + o * 512;
            float a0, a1, a2, a3;
            dot4<4>(qkvW + (size_t)n * 512, xs, 512, lane, a0, a1, a2, a3);
            if (lane == 0) {
                const float bv = qkvB[n];
                if (o == 0) {
                    __stcg(&qt[(b0 + 0) * 512 + wg], a0 + bv);
                    __stcg(&qt[(b0 + 1) * 512 + wg], a1 + bv);
                    __stcg(&qt[(b0 + 2) * 512 + wg], a2 + bv);
                    __stcg(&qt[(b0 + 3) * 512 + wg], a3 + bv);
                } else if (o == 1) {
                    __stcg(&kc[((size_t)(b0 + 0) * CAP_ + cur) * 512 + wg], a0 + bv);
                    __stcg(&kc[((size_t)(b0 + 1) * CAP_ + cur) * 512 + wg], a1 + bv);
                    __stcg(&kc[((size_t)(b0 + 2) * CAP_ + cur) * 512 + wg], a2 + bv);
                    __stcg(&kc[((size_t)(b0 + 3) * CAP_ + cur) * 512 + wg], a3 + bv);
                } else {
                    __stcg(&vc[((size_t)(b0 + 0) * CAP_ + cur) * 512 + wg], a0 + bv);
                    __stcg(&vc[((size_t)(b0 + 1) * CAP_ + cur) * 512 + wg], a1 + bv);
                    __stcg(&vc[((size_t)(b0 + 2) * CAP_ + cur) * 512 + wg], a2 + bv);
                    __stcg(&vc[((size_t)(b0 + 3) * CAP_ + cur) * 512 + wg], a3 + bv);
                }
            }
        }
        gbar(target, tid);

        // ===== phase B: attention partials, 128 blocks = (part, b, h) =====
        {
            const int part = bid >> 6;
            const int bb = (bid >> 3) & 7;
            const int h  = bid & 7;
            const int kvlen = cur + 1;
            const int hlen  = kvlen >> 1;
            const int tstart = part ? hlen : 0;
            const int tend   = part ? kvlen : hlen;
            if (tid < 64) s_q[tid] = __ldcg(&qt[bb * 512 + h * 64 + tid]);
            __syncthreads();
            const int tl = lane >> 2;
            const int kq = (lane & 3) * 16;
            const float4 qa = *(const float4*)(s_q + kq);
            const float4 qb = *(const float4*)(s_q + kq + 4);
            const float4 qc = *(const float4*)(s_q + kq + 8);
            const float4 qd = *(const float4*)(s_q + kq + 12);
            const float* kb = kc + (size_t)bb * CAP_ * 512 + h * 64;
            for (int t0 = tstart; t0 < tend; t0 += 64) {
                const int t = t0 + w * 8 + tl;
                const bool valid = t < tend;
                const float* kr = kb + (size_t)(valid ? t : tstart) * 512 + kq;
                float4 k0 = __ldcg((const float4*)(kr));
                float4 k1 = __ldcg((const float4*)(kr + 4));
                float4 k2 = __ldcg((const float4*)(kr + 8));
                float4 k3 = __ldcg((const float4*)(kr + 12));
                float s;
                s = k0.x * qa.x;
                s = fmaf(k0.y, qa.y, s); s = fmaf(k0.z, qa.z, s); s = fmaf(k0.w, qa.w, s);
                s = fmaf(k1.x, qb.x, s); s = fmaf(k1.y, qb.y, s);
                s = fmaf(k1.z, qb.z, s); s = fmaf(k1.w, qb.w, s);
                s = fmaf(k2.x, qc.x, s); s = fmaf(k2.y, qc.y, s);
                s = fmaf(k2.z, qc.z, s); s = fmaf(k2.w, qc.w, s);
                s = fmaf(k3.x, qd.x, s); s = fmaf(k3.y, qd.y, s);
                s = fmaf(k3.z, qd.z, s); s = fmaf(k3.w, qd.w, s);
                s += __shfl_xor_sync(0xffffffffu, s, 1);
                s += __shfl_xor_sync(0xffffffffu, s, 2);
                if (valid && (lane & 3) == 0) xs[t] = s * 0.125f;
            }
            __syncthreads();
            float lmax = -1e30f;
            for (int t = tstart + tid; t < tend; t += 256) lmax = fmaxf(lmax, xs[t]);
            lmax = warpRedMax(lmax);
            if (lane == 0) s_red[w] = lmax;
            __syncthreads();
            float gm = s_red[0];
#pragma unroll
            for (int i = 1; i < 8; i++) gm = fmaxf(gm, s_red[i]);
            float ls = 0.f;
            for (int t = tstart + tid; t < tend; t += 256) {
                float p = __expf(xs[t] - gm);
                xs[t] = p;
                ls += p;
            }
            ls = warpRedSum(ls);
            if (lane == 0) s_red[8 + w] = ls;
            __syncthreads();
            float ssum = 0.f;
#pragma unroll
            for (int i = 0; i < 8; i++) ssum += s_red[8 + i];
            const int d = tid & 63, pt = tid >> 6;
            const float* vb = vc + (size_t)bb * CAP_ * 512 + h * 64 + d;
            float vacc = 0.f;
            for (int t = tstart + pt; t < tend; t += 4)
                vacc = fmaf(xs[t], __ldcg(vb + (size_t)t * 512), vacc);
            s_part[tid] = vacc;
            __syncthreads();
            const int gi = part * 64 + bb * 8 + h;
            if (pt == 0)
                __stcg(&opart[gi * 64 + d],
                       s_part[d] + s_part[64 + d] + s_part[128 + d] + s_part[192 + d]);
            if (tid == 0) {
                __stcg(&mlpart[gi * 2], gm);
                __stcg(&mlpart[gi * 2 + 1], ssum);
            }
        }
        gbar(target, tid);

        // ===== phase C: combine attn parts + out-proj =====
        if (tid < 64) {
            float m1 = __ldcg(&mlpart[tid * 2]);
            float l1 = __ldcg(&mlpart[tid * 2 + 1]);
            float m2 = __ldcg(&mlpart[(64 + tid) * 2]);
            float l2 = __ldcg(&mlpart[(64 + tid) * 2 + 1]);
            float gm = fmaxf(m1, m2);
            float e1 = __expf(m1 - gm), e2 = __expf(m2 - gm);
            float inv = 1.f / (e1 * l1 + e2 * l2);
            s_comb[tid * 2]     = e1 * inv;
            s_comb[tid * 2 + 1] = e2 * inv;
        }
        __syncthreads();
        for (int i = tid; i < 2048; i += 256) {
            const int b = b0 + (i >> 9);
            const int col = i & 511;
            const int gi = b * 8 + (col >> 6);
            const int d = col & 63;
            xs[i] = s_comb[gi * 2]     * __ldcg(&opart[gi * 64 + d])
                  + s_comb[gi * 2 + 1] * __ldcg(&opart[(64 + gi) * 64 + d]);
        }
        __syncthreads();
        {
            float a0, a1, a2, a3;
            dot4<4>(outW + (size_t)wg * 512, xs, 512, lane, a0, a1, a2, a3);
            if (lane == 0) {
                const float bv = outB[wg];
                __stcg(&t1[(b0 + 0) * 512 + wg], a0 + bv);
                __stcg(&t1[(b0 + 1) * 512 + wg], a1 + bv);
                __stcg(&t1[(b0 + 2) * 512 + wg], a2 + bv);
                __stcg(&t1[(b0 + 3) * 512 + wg], a3 + bv);
            }
        }
        gbar(target, tid);

        // ===== phase E: LN1 (warps 0-3, into s_ln) + FF1 (N=2048, relu) =====
        if (w < 4)
            warp_ln(t1 + (b0 + w) * 512, xt + (b0 + w) * 512,
                    ln1w, ln1b, s_ln + w * 512, lane);
        __syncthreads();
#pragma unroll
        for (int o = 0; o < 4; o++) {
            const int n = wg + o * 512;
            float a0, a1, a2, a3;
            dot4<4>(w1 + (size_t)n * 512, s_ln, 512, lane, a0, a1, a2, a3);
            if (lane == 0) {
                const float bv = b1[n];
                __stcg(&hfft[(b0 + 0) * 2048 + n], fmaxf(a0 + bv, 0.f));
                __stcg(&hfft[(b0 + 1) * 2048 + n], fmaxf(a1 + bv, 0.f));
                __stcg(&hfft[(b0 + 2) * 2048 + n], fmaxf(a2 + bv, 0.f));
                __stcg(&hfft[(b0 + 3) * 2048 + n], fmaxf(a3 + bv, 0.f));
            }
        }
        gbar(target, tid);

        // ===== phase F: FF2 (N=512, K=2048) -> t1 =====
        {
            const float4* src = (const float4*)(hfft + b0 * 2048);
            float4* dst = (float4*)xs;
            for (int i = tid; i < 2048; i += 256) dst[i] = __ldcg(src + i);
        }
        __syncthreads();
        {
            float a0, a1, a2, a3;
            dot4<16>(w2 + (size_t)wg * 2048, xs, 2048, lane, a0, a1, a2, a3);
            if (lane == 0) {
                const float bv = b2[wg];
                __stcg(&t1[(b0 + 0) * 512 + wg], a0 + bv);
                __stcg(&t1[(b0 + 1) * 512 + wg], a1 + bv);
                __stcg(&t1[(b0 + 2) * 512 + wg], a2 + bv);
                __stcg(&t1[(b0 + 3) * 512 + wg], a3 + bv);
            }
        }
        gbar(target, tid);
    }

    // final LN2 for the last step
    if ((bid == 0 || bid == 64) && w < 4)
        warp_ln(t1 + (b0 + w) * 512, s_ln + w * 512, ln2w, ln2b,
                out + ((size_t)(b0 + w) * CAP_ + (S_ + STEPS_ - 1)) * 512, lane);
}

// ---------------- host launcher ----------------
struct ScratchPtrs {
    float *Qkv, *Attn, *Pre, *Hb, *Hff, *Kc, *Vc, *Qt, *Hfft, *T1, *Op, *Ml;
    cudaStream_t sDec;
    cudaEvent_t evQkv, evDec;
};

static const ScratchPtrs& get_scratch() {
    static ScratchPtrs p;
    static bool init = false;
    if (!init) {
        cudaGetSymbolAddress((void**)&p.Qkv,  g_qkv);
        cudaGetSymbolAddress((void**)&p.Attn, g_attn);
        cudaGetSymbolAddress((void**)&p.Pre,  g_pre);
        cudaGetSymbolAddress((void**)&p.Hb,   g_h);
        cudaGetSymbolAddress((void**)&p.Hff,  g_hff);
        cudaGetSymbolAddress((void**)&p.Kc,   g_kc);
        cudaGetSymbolAddress((void**)&p.Vc,   g_vc);
        cudaGetSymbolAddress((void**)&p.Qt,   g_qt);
        cudaGetSymbolAddress((void**)&p.Hfft, g_hfft);
        cudaGetSymbolAddress((void**)&p.T1,   g_t1);
        cudaGetSymbolAddress((void**)&p.Op,   g_op);
        cudaGetSymbolAddress((void**)&p.Ml,   g_ml);
        cudaFuncSetAttribute(attn_prefill,
                             cudaFuncAttributeMaxDynamicSharedMemorySize, 49408);
        cudaFuncSetAttribute(decode_mega,
                             cudaFuncAttributeMaxDynamicSharedMemorySize, 32768);
        cudaStreamCreateWithFlags(&p.sDec, cudaStreamNonBlocking);
        cudaEventCreateWithFlags(&p.evQkv, cudaEventDisableTiming);
        cudaEventCreateWithFlags(&p.evDec, cudaEventDisableTiming);
        init = true;
    }
    return p;
}

extern "C" void kernel_launch(void* const* d_in, const int* in_sizes, int n_in,
                              void* d_out, int out_size)
{
    (void)in_sizes; (void)n_in; (void)out_size;
    const float* x    = (const float*)d_in[0];
    const float* dx   = (const float*)d_in[1];
    // d_in[2] = causal_mask (bool) — unused, causality computed analytically
    const float* qkvW = (const float*)d_in[3];
    const float* qkvB = (const float*)d_in[4];
    const float* outW = (const float*)d_in[5];
    const float* outB = (const float*)d_in[6];
    const float* w1   = (const float*)d_in[7];
    const float* b1   = (const float*)d_in[8];
    const float* w2   = (const float*)d_in[9];
    const float* b2   = (const float*)d_in[10];
    const float* ln1w = (const float*)d_in[11];
    const float* ln1b = (const float*)d_in[12];
    const float* ln2w = (const float*)d_in[13];
    const float* ln2b = (const float*)d_in[14];
    float* out = (float*)d_out;

    const ScratchPtrs& sp = get_scratch();

    // ---- QKV GEMM (also seeds decode K/V caches) on the main stream ----
    sgemm_nt<1,0,0,1><<<dim3(12, 64), 256>>>(x, qkvW, qkvB, nullptr, sp.Qkv,
                                             MTOK, 1536, 512, sp.Kc, sp.Vc);

    // ---- fork: decode runs concurrently with the rest of prefill ----
    cudaEventRecord(sp.evQkv, 0);
    cudaStreamWaitEvent(sp.sDec, sp.evQkv, 0);
    decode_mega<<<NBLK, 256, 32768, sp.sDec>>>(dx, qkvW, qkvB, outW, outB,
                                               w1, b1, w2, b2,
                                               ln1w, ln1b, ln2w, ln2b, out,
                                               sp.Qt, sp.Kc, sp.Vc,
                                               sp.Hfft, sp.T1, sp.Op, sp.Ml);
    cudaEventRecord(sp.evDec, sp.sDec);

    // ---- rest of prefill on the main stream ----
    attn_prefill<<<dim3(16, 64), 256, 49408>>>(sp.Qkv, sp.Attn);
    sgemm_nt<1,0,1,0><<<dim3(4, 64), 256>>>(sp.Attn, outW, outB, x, sp.Pre,
                                            MTOK, 512, 512, nullptr, nullptr);
    ln_rows<<<MTOK, 256>>>(sp.Pre, ln1w, ln1b, sp.Hb, 0);
    sgemm_nt<1,1,0,0><<<dim3(16, 64), 256>>>(sp.Hb, w1, b1, nullptr, sp.Hff,
                                             MTOK, 2048, 512, nullptr, nullptr);
    sgemm_nt<1,0,1,0><<<dim3(4, 64), 256>>>(sp.Hff, w2, b2, sp.Hb, sp.Pre,
                                            MTOK, 512, 2048, nullptr, nullptr);
    ln_rows<<<MTOK, 256>>>(sp.Pre, ln2w, ln2b, out, 64);

    // ---- join: main stream completes only after decode finishes ----
    cudaStreamWaitEvent(0, sp.evDec, 0);
}

// round 11
// speedup vs baseline: 1.1846x; 1.0092x over previous
#include <cuda_runtime.h>
#include <cstdint>

#define B_     8
#define S_     1024
#define D_     512
#define H_     8
#define HD_    64
#define FF_    2048
#define STEPS_ 64
#define CAP_   1088
#define MTOK   (B_*S_)   /* 8192 */
#define NBLK   128

// ---------------- device scratch (no cudaMalloc allowed) ----------------
__device__ float g_qkv [MTOK*1536];       // prefill QKV
__device__ float g_qkvdec[STEPS_*B_*1536];// decode QKV (precomputed, row=step*8+b)
__device__ float g_attn[MTOK*D_];
__device__ float g_pre [MTOK*D_];
__device__ float g_h   [MTOK*D_];
__device__ float g_hff [MTOK*FF_];
__device__ float g_kc  [B_*CAP_*D_];
__device__ float g_vc  [B_*CAP_*D_];
__device__ float g_hfft[B_*FF_];
__device__ float g_t1  [B_*D_];
__device__ float g_op  [2*64*64];
__device__ float g_ml  [2*64*2];
__device__ unsigned g_bar_count;
__device__ unsigned g_bar_sense;

// ---------------- reductions ----------------
__device__ __forceinline__ float warpRedSum(float v) {
#pragma unroll
    for (int o = 16; o; o >>= 1) v += __shfl_xor_sync(0xffffffffu, v, o);
    return v;
}
__device__ __forceinline__ float warpRedMax(float v) {
#pragma unroll
    for (int o = 16; o; o >>= 1) v = fmaxf(v, __shfl_xor_sync(0xffffffffu, v, o));
    return v;
}

// ---------------- fence-free global barrier (.cg data protocol) ----------------
__device__ __forceinline__ unsigned ld_acq(const unsigned* p) {
    unsigned v;
    asm volatile("ld.acquire.gpu.u32 %0, [%1];" : "=r"(v) : "l"(p) : "memory");
    return v;
}
__device__ __forceinline__ void st_rel(unsigned* p, unsigned v) {
    asm volatile("st.release.gpu.u32 [%0], %1;" :: "l"(p), "r"(v) : "memory");
}
__device__ __forceinline__ unsigned atomAddAcqRel(unsigned* p, unsigned v) {
    unsigned old;
    asm volatile("atom.acq_rel.gpu.global.add.u32 %0, [%1], %2;"
                 : "=r"(old) : "l"(p), "r"(v) : "memory");
    return old;
}
__device__ __forceinline__ void gbar(unsigned& target, int tid) {
    __syncthreads();
    target += 1;
    if (tid == 0) {
        unsigned a = atomAddAcqRel(&g_bar_count, 1u) + 1u;
        if (a == (unsigned)NBLK) {
            atomicExch(&g_bar_count, 0u);
            st_rel(&g_bar_sense, target);
        } else {
            while ((int)(ld_acq(&g_bar_sense) - target) < 0) { }
        }
    }
    __syncthreads();
}

// ---------------- 3xTF32 helpers ----------------
__device__ __forceinline__ float tf32_rna(float v) {
    unsigned u;
    asm("cvt.rna.tf32.f32 %0, %1;" : "=r"(u) : "f"(v));
    return __uint_as_float(u);
}

__device__ __forceinline__ void mma4x4(const unsigned a[4][4],
                                       const unsigned b[4][2],
                                       float acc[4][4][4])
{
#pragma unroll
    for (int mt = 0; mt < 4; mt++)
#pragma unroll
        for (int nt = 0; nt < 4; nt++) {
            asm volatile(
                "mma.sync.aligned.m16n8k8.row.col.f32.tf32.tf32.f32 "
                "{%0,%1,%2,%3}, {%4,%5,%6,%7}, {%8,%9}, {%0,%1,%2,%3};"
                : "+f"(acc[mt][nt][0]), "+f"(acc[mt][nt][1]),
                  "+f"(acc[mt][nt][2]), "+f"(acc[mt][nt][3])
                : "r"(a[mt][0]), "r"(a[mt][1]), "r"(a[mt][2]), "r"(a[mt][3]),
                  "r"(b[nt][0]), "r"(b[nt][1]));
        }
}

// ---------------- SGEMM (NT) via 3xTF32 tensor-core mma ----------------
// KVOUT: 0 none; 1 prefill row map (b=row>>10, s=row&1023); 2 decode map
// (b=row&7, s=S_+(row>>3)). K/V columns 512..1535 scatter into kc/vc.
template<int BIAS, int RELU, int RES, int KVOUT>
__global__ void __launch_bounds__(256, 2) sgemm_nt(
    const float* __restrict__ A, const float* __restrict__ Bm,
    const float* __restrict__ bias, const float* __restrict__ R,
    float* __restrict__ C, int M, int N, int K,
    float* __restrict__ kc, float* __restrict__ vc)
{
    __shared__ float Ah[16][132], Al[16][132];
    __shared__ float Bh[16][132], Bl[16][132];
    const int tid = threadIdx.x;
    const int m0 = blockIdx.y * 128;
    const int n0 = blockIdx.x * 128;
    const int w = tid >> 5, lane = tid & 31;
    const int wm0 = (w >> 2) * 64;
    const int wn0 = (w & 3) * 32;
    const int g = lane >> 2, tq = lane & 3;
    const int lrow = tid >> 2;
    const int lk4  = (tid & 3) * 4;

    const float* Ap0 = A  + (size_t)(m0 + lrow)      * K + lk4;
    const float* Ap1 = A  + (size_t)(m0 + lrow + 64) * K + lk4;
    const float* Bp0 = Bm + (size_t)(n0 + lrow)      * K + lk4;
    const float* Bp1 = Bm + (size_t)(n0 + lrow + 64) * K + lk4;

    float acc[4][4][4];
#pragma unroll
    for (int i = 0; i < 4; i++)
#pragma unroll
        for (int j = 0; j < 4; j++)
#pragma unroll
            for (int q = 0; q < 4; q++) acc[i][j][q] = 0.f;

    float4 pa0 = *(const float4*)(Ap0);
    float4 pa1 = *(const float4*)(Ap1);
    float4 pb0 = *(const float4*)(Bp0);
    float4 pb1 = *(const float4*)(Bp1);

    for (int k0 = 0; k0 < K; k0 += 16) {
        {
            const float va[8] = {pa0.x, pa0.y, pa0.z, pa0.w,
                                 pa1.x, pa1.y, pa1.z, pa1.w};
            const float vb[8] = {pb0.x, pb0.y, pb0.z, pb0.w,
                                 pb1.x, pb1.y, pb1.z, pb1.w};
#pragma unroll
            for (int i = 0; i < 4; i++) {
                float h;
                h = tf32_rna(va[i]);
                Ah[lk4 + i][lrow] = h;      Al[lk4 + i][lrow] = va[i] - h;
                h = tf32_rna(va[4 + i]);
                Ah[lk4 + i][lrow + 64] = h; Al[lk4 + i][lrow + 64] = va[4 + i] - h;
                h = tf32_rna(vb[i]);
                Bh[lk4 + i][lrow] = h;      Bl[lk4 + i][lrow] = vb[i] - h;
                h = tf32_rna(vb[4 + i]);
                Bh[lk4 + i][lrow + 64] = h; Bl[lk4 + i][lrow + 64] = vb[4 + i] - h;
            }
        }
        __syncthreads();
        if (k0 + 16 < K) {
            pa0 = *(const float4*)(Ap0 + k0 + 16);
            pa1 = *(const float4*)(Ap1 + k0 + 16);
            pb0 = *(const float4*)(Bp0 + k0 + 16);
            pb1 = *(const float4*)(Bp1 + k0 + 16);
        }
#pragma unroll
        for (int ks = 0; ks < 16; ks += 8) {
            unsigned ah[4][4], bh[4][2];
#pragma unroll
            for (int mt = 0; mt < 4; mt++) {
                const int mb = wm0 + mt * 16 + g;
                ah[mt][0] = __float_as_uint(Ah[ks + tq][mb]);
                ah[mt][1] = __float_as_uint(Ah[ks + tq][mb + 8]);
                ah[mt][2] = __float_as_uint(Ah[ks + tq + 4][mb]);
                ah[mt][3] = __float_as_uint(Ah[ks + tq + 4][mb + 8]);
            }
#pragma unroll
            for (int nt = 0; nt < 4; nt++) {
                bh[nt][0] = __float_as_uint(Bh[ks + tq][wn0 + nt * 8 + g]);
                bh[nt][1] = __float_as_uint(Bh[ks + tq + 4][wn0 + nt * 8 + g]);
            }
            mma4x4(ah, bh, acc);
            {
                unsigned bl[4][2];
#pragma unroll
                for (int nt = 0; nt < 4; nt++) {
                    bl[nt][0] = __float_as_uint(Bl[ks + tq][wn0 + nt * 8 + g]);
                    bl[nt][1] = __float_as_uint(Bl[ks + tq + 4][wn0 + nt * 8 + g]);
                }
                mma4x4(ah, bl, acc);
            }
            {
                unsigned al[4][4];
#pragma unroll
                for (int mt = 0; mt < 4; mt++) {
                    const int mb = wm0 + mt * 16 + g;
                    al[mt][0] = __float_as_uint(Al[ks + tq][mb]);
                    al[mt][1] = __float_as_uint(Al[ks + tq][mb + 8]);
                    al[mt][2] = __float_as_uint(Al[ks + tq + 4][mb]);
                    al[mt][3] = __float_as_uint(Al[ks + tq + 4][mb + 8]);
                }
                mma4x4(al, bh, acc);
            }
        }
        __syncthreads();
    }

#pragma unroll
    for (int nt = 0; nt < 4; nt++) {
        const int col = n0 + wn0 + nt * 8 + tq * 2;
        const float b0v = BIAS ? bias[col] : 0.f;
        const float b1v = BIAS ? bias[col + 1] : 0.f;
#pragma unroll
        for (int mt = 0; mt < 4; mt++) {
#pragma unroll
            for (int rh = 0; rh < 2; rh++) {
                const int row = m0 + wm0 + mt * 16 + g + rh * 8;
                float t0 = acc[mt][nt][rh * 2 + 0] + b0v;
                float t1 = acc[mt][nt][rh * 2 + 1] + b1v;
                if (RES) {
                    float2 r = *(const float2*)(R + (size_t)row * N + col);
                    t0 += r.x; t1 += r.y;
                }
                if (RELU) { t0 = fmaxf(t0, 0.f); t1 = fmaxf(t1, 0.f); }
                float2 v; v.x = t0; v.y = t1;
                *(float2*)(C + (size_t)row * N + col) = v;
                if (KVOUT && col >= 512) {
                    int bb, ss;
                    if (KVOUT == 1) { bb = row >> 10; ss = row & 1023; }
                    else            { bb = row & 7;   ss = S_ + (row >> 3); }
                    float* dst = (col < 1024)
                        ? kc + ((size_t)(bb * CAP_ + ss) * 512 + (col - 512))
                        : vc + ((size_t)(bb * CAP_ + ss) * 512 + (col - 1024));
                    *(float2*)dst = v;
                }
            }
        }
    }
}

// ---------------- prefill flash attention (causal), 64x64 tiles ----------------
__global__ void __launch_bounds__(256) attn_prefill(const float* __restrict__ qkv,
                                                    float* __restrict__ attn)
{
    extern __shared__ float sm[];
    float* Qs = sm;
    float* KP = sm + 64 * 64;
    float* Vs = KP + 64 * 65;

    const int b  = blockIdx.y >> 3;
    const int h  = blockIdx.y & 7;
    const int l0 = blockIdx.x * 64;
    const int tid = threadIdx.x;
    const int tx = tid & 15, ty = tid >> 4;
    const int r0 = ty * 4, c0 = tx * 4;

    const size_t rowbase = (size_t)(b * S_) * 1536;
    const float* qbase = qkv + rowbase + h * 64;
    const float* kbase = qkv + rowbase + 512 + h * 64;
    const float* vbase = qkv + rowbase + 1024 + h * 64;

    const int lt  = tid >> 4;
    const int ld4 = (tid & 15) * 4;

#pragma unroll
    for (int tt = lt; tt < 64; tt += 16) {
        float4 q4 = *(const float4*)(qbase + (size_t)(l0 + tt) * 1536 + ld4);
        Qs[(ld4 + 0) * 64 + tt] = q4.x;
        Qs[(ld4 + 1) * 64 + tt] = q4.y;
        Qs[(ld4 + 2) * 64 + tt] = q4.z;
        Qs[(ld4 + 3) * 64 + tt] = q4.w;
    }

    float o[4][4];
    float mrow[4], lrow[4];
#pragma unroll
    for (int i = 0; i < 4; i++) {
        mrow[i] = -1e30f; lrow[i] = 0.f;
#pragma unroll
        for (int j = 0; j < 4; j++) o[i][j] = 0.f;
    }

    const int ntiles = (l0 >> 6) + 1;
    for (int tile = 0; tile < ntiles; ++tile) {
        const int j0 = tile * 64;
        __syncthreads();
#pragma unroll
        for (int tt = lt; tt < 64; tt += 16) {
            float4 k4 = *(const float4*)(kbase + (size_t)(j0 + tt) * 1536 + ld4);
            KP[(ld4 + 0) * 65 + tt] = k4.x;
            KP[(ld4 + 1) * 65 + tt] = k4.y;
            KP[(ld4 + 2) * 65 + tt] = k4.z;
            KP[(ld4 + 3) * 65 + tt] = k4.w;
            float4 v4 = *(const float4*)(vbase + (size_t)(j0 + tt) * 1536 + ld4);
            *(float4*)(Vs + tt * 64 + ld4) = v4;
        }
        __syncthreads();

        float s[4][4];
#pragma unroll
        for (int i = 0; i < 4; i++)
#pragma unroll
            for (int j = 0; j < 4; j++) s[i][j] = 0.f;

        for (int d = 0; d < 64; d++) {
            float qf[4];
            *(float4*)qf = *(const float4*)(Qs + d * 64 + r0);
            float kf0 = KP[d * 65 + c0 + 0];
            float kf1 = KP[d * 65 + c0 + 1];
            float kf2 = KP[d * 65 + c0 + 2];
            float kf3 = KP[d * 65 + c0 + 3];
#pragma unroll
            for (int i = 0; i < 4; i++) {
                s[i][0] = fmaf(qf[i], kf0, s[i][0]);
                s[i][1] = fmaf(qf[i], kf1, s[i][1]);
                s[i][2] = fmaf(qf[i], kf2, s[i][2]);
                s[i][3] = fmaf(qf[i], kf3, s[i][3]);
            }
        }

        if (j0 == l0) {
#pragma unroll
            for (int i = 0; i < 4; i++)
#pragma unroll
                for (int j = 0; j < 4; j++)
                    s[i][j] = (j0 + c0 + j > l0 + r0 + i) ? -1e30f : s[i][j] * 0.125f;
        } else {
#pragma unroll
            for (int i = 0; i < 4; i++)
#pragma unroll
                for (int j = 0; j < 4; j++) s[i][j] *= 0.125f;
        }

        float p[4][4];
#pragma unroll
        for (int i = 0; i < 4; i++) {
            float rm = fmaxf(fmaxf(s[i][0], s[i][1]), fmaxf(s[i][2], s[i][3]));
#pragma unroll
            for (int off = 8; off; off >>= 1)
                rm = fmaxf(rm, __shfl_xor_sync(0xffffffffu, rm, off));
            float mnew  = fmaxf(mrow[i], rm);
            float alpha = __expf(mrow[i] - mnew);
            float ps = 0.f;
#pragma unroll
            for (int j = 0; j < 4; j++) { p[i][j] = __expf(s[i][j] - mnew); ps += p[i][j]; }
#pragma unroll
            for (int off = 8; off; off >>= 1)
                ps += __shfl_xor_sync(0xffffffffu, ps, off);
            lrow[i] = lrow[i] * alpha + ps;
            mrow[i] = mnew;
#pragma unroll
            for (int j = 0; j < 4; j++) o[i][j] *= alpha;
        }

        __syncthreads();
#pragma unroll
        for (int i = 0; i < 4; i++)
#pragma unroll
            for (int j = 0; j < 4; j++)
                KP[(r0 + i) * 65 + c0 + j] = p[i][j];
        __syncthreads();

        for (int c = 0; c < 64; c++) {
            float vv[4];
            *(float4*)vv = *(const float4*)(Vs + c * 64 + c0);
            float p0 = KP[(r0 + 0) * 65 + c];
            float p1 = KP[(r0 + 1) * 65 + c];
            float p2 = KP[(r0 + 2) * 65 + c];
            float p3 = KP[(r0 + 3) * 65 + c];
#pragma unroll
            for (int j = 0; j < 4; j++) {
                o[0][j] = fmaf(p0, vv[j], o[0][j]);
                o[1][j] = fmaf(p1, vv[j], o[1][j]);
                o[2][j] = fmaf(p2, vv[j], o[2][j]);
                o[3][j] = fmaf(p3, vv[j], o[3][j]);
            }
        }
    }

    float* ob = attn + (size_t)(b * S_ + l0) * 512 + h * 64;
#pragma unroll
    for (int i = 0; i < 4; i++) {
        float inv = 1.f / lrow[i];
        float4 v;
        v.x = o[i][0] * inv; v.y = o[i][1] * inv;
        v.z = o[i][2] * inv; v.w = o[i][3] * inv;
        *(float4*)(ob + (size_t)(r0 + i) * 512 + c0) = v;
    }
}

// ---------------- prefill LayerNorm over rows of 512 ----------------
__global__ void __launch_bounds__(256) ln_rows(const float* __restrict__ in,
                                               const float* __restrict__ g,
                                               const float* __restrict__ be,
                                               float* __restrict__ out, int outExtra)
{
    const int r = blockIdx.x;
    const int tid = threadIdx.x;
    const float* row = in + (size_t)r * 512;
    float v0 = row[tid], v1 = row[tid + 256];
    float s  = warpRedSum(v0 + v1);
    float s2 = warpRedSum(v0 * v0 + v1 * v1);
    __shared__ float r1[8], r2[8];
    __shared__ float smu, srs;
    const int w = tid >> 5, lane = tid & 31;
    if (lane == 0) { r1[w] = s; r2[w] = s2; }
    __syncthreads();
    if (tid == 0) {
        float S = 0.f, S2 = 0.f;
#pragma unroll
        for (int i = 0; i < 8; i++) { S += r1[i]; S2 += r2[i]; }
        float mu  = S * (1.f / 512.f);
        float var = S2 * (1.f / 512.f) - mu * mu;
        smu = mu; srs = rsqrtf(var + 1e-5f);
    }
    __syncthreads();
    const int orow = r + (r >> 10) * outExtra;
    float* od = out + (size_t)orow * 512;
    od[tid]       = (v0 - smu) * srs * g[tid]       + be[tid];
    od[tid + 256] = (v1 - smu) * srs * g[tid + 256] + be[tid + 256];
}

// ---------------- megakernel building blocks ----------------
template<int KP>
__device__ __forceinline__ void dot4(const float* __restrict__ wr,
                                     const float* xs, int Kstride, int lane,
                                     float& a0, float& a1, float& a2, float& a3)
{
    a0 = a1 = a2 = a3 = 0.f;
#pragma unroll
    for (int kp = 0; kp < KP; kp++) {
        const int k4 = kp * 128 + lane * 4;
        float4 wv = *(const float4*)(wr + k4);
        float4 x0 = *(const float4*)(xs + k4);
        float4 x1 = *(const float4*)(xs + Kstride + k4);
        float4 x2 = *(const float4*)(xs + 2 * Kstride + k4);
        float4 x3 = *(const float4*)(xs + 3 * Kstride + k4);
        a0 = fmaf(wv.x, x0.x, fmaf(wv.y, x0.y, fmaf(wv.z, x0.z, fmaf(wv.w, x0.w, a0))));
        a1 = fmaf(wv.x, x1.x, fmaf(wv.y, x1.y, fmaf(wv.z, x1.z, fmaf(wv.w, x1.w, a1))));
        a2 = fmaf(wv.x, x2.x, fmaf(wv.y, x2.y, fmaf(wv.z, x2.z, fmaf(wv.w, x2.w, a2))));
        a3 = fmaf(wv.x, x3.x, fmaf(wv.y, x3.y, fmaf(wv.z, x3.z, fmaf(wv.w, x3.w, a3))));
    }
    a0 = warpRedSum(a0); a1 = warpRedSum(a1);
    a2 = warpRedSum(a2); a3 = warpRedSum(a3);
}

__device__ __forceinline__ void warp_ln(const float* __restrict__ a,
                                        const float* r,
                                        const float* __restrict__ gw,
                                        const float* __restrict__ gb,
                                        float* o, int lane)
{
    float vals[16];
    float sv = 0.f, sq = 0.f;
#pragma unroll
    for (int g = 0; g < 4; g++) {
        const int idx = g * 128 + lane * 4;
        float4 av = __ldcg((const float4*)(a + idx));
        float4 rv = *(const float4*)(r + idx);
        float a0 = av.x + rv.x, a1 = av.y + rv.y;
        float a2 = av.z + rv.z, a3 = av.w + rv.w;
        vals[g * 4 + 0] = a0; vals[g * 4 + 1] = a1;
        vals[g * 4 + 2] = a2; vals[g * 4 + 3] = a3;
        sv += a0 + a1 + a2 + a3;
        sq += a0 * a0 + a1 * a1 + a2 * a2 + a3 * a3;
    }
    sv = warpRedSum(sv); sq = warpRedSum(sq);
    float mu = sv * (1.f / 512.f);
    float rs = rsqrtf(sq * (1.f / 512.f) - mu * mu + 1e-5f);
#pragma unroll
    for (int g = 0; g < 4; g++)
#pragma unroll
        for (int j = 0; j < 4; j++) {
            const int idx = g * 128 + lane * 4 + j;
            o[idx] = (vals[g * 4 + j] - mu) * rs * gw[idx] + gb[idx];
        }
}

// ---------------- decode megakernel: QKV precomputed, 4 barriers/step --------
__global__ void __launch_bounds__(256, 1) decode_mega(
    const float* __restrict__ dx,
    const float* __restrict__ qdec,           // [STEPS*8][1536] precomputed QKV
    const float* __restrict__ outW, const float* __restrict__ outB,
    const float* __restrict__ w1, const float* __restrict__ b1,
    const float* __restrict__ w2, const float* __restrict__ b2,
    const float* __restrict__ ln1w, const float* __restrict__ ln1b,
    const float* __restrict__ ln2w, const float* __restrict__ ln2b,
    float* __restrict__ out,
    float* __restrict__ kc, float* __restrict__ vc,
    float* __restrict__ hfft, float* __restrict__ t1,
    float* __restrict__ opart, float* __restrict__ mlpart)
{
    extern __shared__ float xs[];      // 8192 floats (32KB)
    __shared__ float s_ln[4 * 512];
    __shared__ float s_red[16];
    __shared__ float s_q[64];
    __shared__ float s_part[256];
    __shared__ float s_comb[128];
    __shared__ unsigned s_base;

    const int tid  = threadIdx.x;
    const int bid  = blockIdx.x;
    const int w    = tid >> 5, lane = tid & 31;
    const int half = bid >> 6;
    const int b0   = half * 4;
    const int wg   = (bid & 63) * 8 + w;

    if (tid == 0) s_base = ld_acq(&g_bar_sense);
    __syncthreads();
    unsigned target = s_base;

    for (int step = 0; step < STEPS_; step++) {
        const int cur = S_ + step;
        const float* xt = dx + (size_t)step * (B_ * D_);

        // ===== slot B: LN2(prev) on blocks 0 & 64 + attention partials =====
        if (step > 0 && (bid == 0 || bid == 64) && w < 4)
            warp_ln(t1 + (b0 + w) * 512, s_ln + w * 512, ln2w, ln2b,
                    out + ((size_t)(b0 + w) * CAP_ + (cur - 1)) * 512, lane);
        {
            const int part = bid >> 6;
            const int bb = (bid >> 3) & 7;
            const int h  = bid & 7;
            const int kvlen = cur + 1;
            const int hlen  = kvlen >> 1;
            const int tstart = part ? hlen : 0;
            const int tend   = part ? kvlen : hlen;
            if (tid < 64)
                s_q[tid] = __ldg(&qdec[(size_t)(step * 8 + bb) * 1536 + h * 64 + tid]);
            __syncthreads();
            const int tl = lane >> 2;
            const int kq = (lane & 3) * 16;
            const float4 qa = *(const float4*)(s_q + kq);
            const float4 qb = *(const float4*)(s_q + kq + 4);
            const float4 qc = *(const float4*)(s_q + kq + 8);
            const float4 qd = *(const float4*)(s_q + kq + 12);
            const float* kb = kc + (size_t)bb * CAP_ * 512 + h * 64;
            for (int t0 = tstart; t0 < tend; t0 += 64) {
                const int t = t0 + w * 8 + tl;
                const bool valid = t < tend;
                const float* kr = kb + (size_t)(valid ? t : tstart) * 512 + kq;
                float4 k0 = __ldcg((const float4*)(kr));
                float4 k1 = __ldcg((const float4*)(kr + 4));
                float4 k2 = __ldcg((const float4*)(kr + 8));
                float4 k3 = __ldcg((const float4*)(kr + 12));
                float s;
                s = k0.x * qa.x;
                s = fmaf(k0.y, qa.y, s); s = fmaf(k0.z, qa.z, s); s = fmaf(k0.w, qa.w, s);
                s = fmaf(k1.x, qb.x, s); s = fmaf(k1.y, qb.y, s);
                s = fmaf(k1.z, qb.z, s); s = fmaf(k1.w, qb.w, s);
                s = fmaf(k2.x, qc.x, s); s = fmaf(k2.y, qc.y, s);
                s = fmaf(k2.z, qc.z, s); s = fmaf(k2.w, qc.w, s);
                s = fmaf(k3.x, qd.x, s); s = fmaf(k3.y, qd.y, s);
                s = fmaf(k3.z, qd.z, s); s = fmaf(k3.w, qd.w, s);
                s += __shfl_xor_sync(0xffffffffu, s, 1);
                s += __shfl_xor_sync(0xffffffffu, s, 2);
                if (valid && (lane & 3) == 0) xs[t] = s * 0.125f;
            }
            __syncthreads();
            float lmax = -1e30f;
            for (int t = tstart + tid; t < tend; t += 256) lmax = fmaxf(lmax, xs[t]);
            lmax = warpRedMax(lmax);
            if (lane == 0) s_red[w] = lmax;
            __syncthreads();
            float gm = s_red[0];
#pragma unroll
            for (int i = 1; i < 8; i++) gm = fmaxf(gm, s_red[i]);
            float ls = 0.f;
            for (int t = tstart + tid; t < tend; t += 256) {
                float p = __expf(xs[t] - gm);
                xs[t] = p;
                ls += p;
            }
            ls = warpRedSum(ls);
            if (lane == 0) s_red[8 + w] = ls;
            __syncthreads();
            float ssum = 0.f;
#pragma unroll
            for (int i = 0; i < 8; i++) ssum += s_red[8 + i];
            const int d = tid & 63, pt = tid >> 6;
            const float* vb = vc + (size_t)bb * CAP_ * 512 + h * 64 + d;
            float vacc = 0.f;
            for (int t = tstart + pt; t < tend; t += 4)
                vacc = fmaf(xs[t], __ldcg(vb + (size_t)t * 512), vacc);
            s_part[tid] = vacc;
            __syncthreads();
            const int gi = part * 64 + bb * 8 + h;
            if (pt == 0)
                __stcg(&opart[gi * 64 + d],
                       s_part[d] + s_part[64 + d] + s_part[128 + d] + s_part[192 + d]);
            if (tid == 0) {
                __stcg(&mlpart[gi * 2], gm);
                __stcg(&mlpart[gi * 2 + 1], ssum);
            }
        }
        gbar(target, tid);

        // ===== phase C: combine attn parts + out-proj =====
        if (tid < 64) {
            float m1 = __ldcg(&mlpart[tid * 2]);
            float l1 = __ldcg(&mlpart[tid * 2 + 1]);
            float m2 = __ldcg(&mlpart[(64 + tid) * 2]);
            float l2 = __ldcg(&mlpart[(64 + tid) * 2 + 1]);
            float gm = fmaxf(m1, m2);
            float e1 = __expf(m1 - gm), e2 = __expf(m2 - gm);
            float inv = 1.f / (e1 * l1 + e2 * l2);
            s_comb[tid * 2]     = e1 * inv;
            s_comb[tid * 2 + 1] = e2 * inv;
        }
        __syncthreads();
        for (int i = tid; i < 2048; i += 256) {
            const int b = b0 + (i >> 9);
            const int col = i & 511;
            const int gi = b * 8 + (col >> 6);
            const int d = col & 63;
            xs[i] = s_comb[gi * 2]     * __ldcg(&opart[gi * 64 + d])
                  + s_comb[gi * 2 + 1] * __ldcg(&opart[(64 + gi) * 64 + d]);
        }
        __syncthreads();
        {
            float a0, a1, a2, a3;
            dot4<4>(outW + (size_t)wg * 512, xs, 512, lane, a0, a1, a2, a3);
            if (lane == 0) {
                const float bv = outB[wg];
                __stcg(&t1[(b0 + 0) * 512 + wg], a0 + bv);
                __stcg(&t1[(b0 + 1) * 512 + wg], a1 + bv);
                __stcg(&t1[(b0 + 2) * 512 + wg], a2 + bv);
                __stcg(&t1[(b0 + 3) * 512 + wg], a3 + bv);
            }
        }
        gbar(target, tid);

        // ===== phase E: LN1 (warps 0-3, into s_ln) + FF1 (N=2048, relu) =====
        if (w < 4)
            warp_ln(t1 + (b0 + w) * 512, xt + (b0 + w) * 512,
                    ln1w, ln1b, s_ln + w * 512, lane);
        __syncthreads();
#pragma unroll
        for (int o = 0; o < 4; o++) {
            const int n = wg + o * 512;
            float a0, a1, a2, a3;
            dot4<4>(w1 + (size_t)n * 512, s_ln, 512, lane, a0, a1, a2, a3);
            if (lane == 0) {
                const float bv = b1[n];
                __stcg(&hfft[(b0 + 0) * 2048 + n], fmaxf(a0 + bv, 0.f));
                __stcg(&hfft[(b0 + 1) * 2048 + n], fmaxf(a1 + bv, 0.f));
                __stcg(&hfft[(b0 + 2) * 2048 + n], fmaxf(a2 + bv, 0.f));
                __stcg(&hfft[(b0 + 3) * 2048 + n], fmaxf(a3 + bv, 0.f));
            }
        }
        gbar(target, tid);

        // ===== phase F: FF2 (N=512, K=2048) -> t1 =====
        {
            const float4* src = (const float4*)(hfft + b0 * 2048);
            float4* dst = (float4*)xs;
            for (int i = tid; i < 2048; i += 256) dst[i] = __ldcg(src + i);
        }
        __syncthreads();
        {
            float a0, a1, a2, a3;
            dot4<16>(w2 + (size_t)wg * 2048, xs, 2048, lane, a0, a1, a2, a3);
            if (lane == 0) {
                const float bv = b2[wg];
                __stcg(&t1[(b0 + 0) * 512 + wg], a0 + bv);
                __stcg(&t1[(b0 + 1) * 512 + wg], a1 + bv);
                __stcg(&t1[(b0 + 2) * 512 + wg], a2 + bv);
                __stcg(&t1[(b0 + 3) * 512 + wg], a3 + bv);
            }
        }
        gbar(target, tid);
    }

    // final LN2 for the last step
    if ((bid == 0 || bid == 64) && w < 4)
        warp_ln(t1 + (b0 + w) * 512, s_ln + w * 512, ln2w, ln2b,
                out + ((size_t)(b0 + w) * CAP_ + (S_ + STEPS_ - 1)) * 512, lane);
}

// ---------------- host launcher ----------------
struct ScratchPtrs {
    float *Qkv, *Qdec, *Attn, *Pre, *Hb, *Hff, *Kc, *Vc, *Hfft, *T1, *Op, *Ml;
    cudaStream_t sDec;
    cudaEvent_t evQkv, evDec;
};

static const ScratchPtrs& get_scratch() {
    static ScratchPtrs p;
    static bool init = false;
    if (!init) {
        cudaGetSymbolAddress((void**)&p.Qkv,  g_qkv);
        cudaGetSymbolAddress((void**)&p.Qdec, g_qkvdec);
        cudaGetSymbolAddress((void**)&p.Attn, g_attn);
        cudaGetSymbolAddress((void**)&p.Pre,  g_pre);
        cudaGetSymbolAddress((void**)&p.Hb,   g_h);
        cudaGetSymbolAddress((void**)&p.Hff,  g_hff);
        cudaGetSymbolAddress((void**)&p.Kc,   g_kc);
        cudaGetSymbolAddress((void**)&p.Vc,   g_vc);
        cudaGetSymbolAddress((void**)&p.Hfft, g_hfft);
        cudaGetSymbolAddress((void**)&p.T1,   g_t1);
        cudaGetSymbolAddress((void**)&p.Op,   g_op);
        cudaGetSymbolAddress((void**)&p.Ml,   g_ml);
        cudaFuncSetAttribute(attn_prefill,
                             cudaFuncAttributeMaxDynamicSharedMemorySize, 49408);
        cudaFuncSetAttribute(decode_mega,
                             cudaFuncAttributeMaxDynamicSharedMemorySize, 32768);
        cudaStreamCreateWithFlags(&p.sDec, cudaStreamNonBlocking);
        cudaEventCreateWithFlags(&p.evQkv, cudaEventDisableTiming);
        cudaEventCreateWithFlags(&p.evDec, cudaEventDisableTiming);
        init = true;
    }
    return p;
}

extern "C" void kernel_launch(void* const* d_in, const int* in_sizes, int n_in,
                              void* d_out, int out_size)
{
    (void)in_sizes; (void)n_in; (void)out_size;
    const float* x    = (const float*)d_in[0];
    const float* dx   = (const float*)d_in[1];
    // d_in[2] = causal_mask (bool) — unused, causality computed analytically
    const float* qkvW = (const float*)d_in[3];
    const float* qkvB = (const float*)d_in[4];
    const float* outW = (const float*)d_in[5];
    const float* outB = (const float*)d_in[6];
    const float* w1   = (const float*)d_in[7];
    const float* b1   = (const float*)d_in[8];
    const float* w2   = (const float*)d_in[9];
    const float* b2   = (const float*)d_in[10];
    const float* ln1w = (const float*)d_in[11];
    const float* ln1b = (const float*)d_in[12];
    const float* ln2w = (const float*)d_in[13];
    const float* ln2b = (const float*)d_in[14];
    float* out = (float*)d_out;

    const ScratchPtrs& sp = get_scratch();

    // ---- QKV GEMMs: prefill (seeds KV rows 0..1023) + ALL decode steps ----
    sgemm_nt<1,0,0,1><<<dim3(12, 64), 256>>>(x, qkvW, qkvB, nullptr, sp.Qkv,
                                             MTOK, 1536, 512, sp.Kc, sp.Vc);
    sgemm_nt<1,0,0,2><<<dim3(12, 4), 256>>>(dx, qkvW, qkvB, nullptr, sp.Qdec,
                                            STEPS_ * B_, 1536, 512, sp.Kc, sp.Vc);

    // ---- fork: decode runs concurrently with the rest of prefill ----
    cudaEventRecord(sp.evQkv, 0);
    cudaStreamWaitEvent(sp.sDec, sp.evQkv, 0);
    decode_mega<<<NBLK, 256, 32768, sp.sDec>>>(dx, sp.Qdec, outW, outB,
                                               w1, b1, w2, b2,
                                               ln1w, ln1b, ln2w, ln2b, out,
                                               sp.Kc, sp.Vc,
                                               sp.Hfft, sp.T1, sp.Op, sp.Ml);
    cudaEventRecord(sp.evDec, sp.sDec);

    // ---- rest of prefill on the main stream ----
    attn_prefill<<<dim3(16, 64), 256, 49408>>>(sp.Qkv, sp.Attn);
    sgemm_nt<1,0,1,0><<<dim3(4, 64), 256>>>(sp.Attn, outW, outB, x, sp.Pre,
                                            MTOK, 512, 512, nullptr, nullptr);
    ln_rows<<<MTOK, 256>>>(sp.Pre, ln1w, ln1b, sp.Hb, 0);
    sgemm_nt<1,1,0,0><<<dim3(16, 64), 256>>>(sp.Hb, w1, b1, nullptr, sp.Hff,
                                             MTOK, 2048, 512, nullptr, nullptr);
    sgemm_nt<1,0,1,0><<<dim3(4, 64), 256>>>(sp.Hff, w2, b2, sp.Hb, sp.Pre,
                                            MTOK, 512, 2048, nullptr, nullptr);
    ln_rows<<<MTOK, 256>>>(sp.Pre, ln2w, ln2b, out, 64);

    // ---- join: main stream completes only after decode finishes ----
    cudaStreamWaitEvent(0, sp.evDec, 0);
}

// round 12
// speedup vs baseline: 1.4412x; 1.2166x over previous
#include <cuda_runtime.h>
#include <cuda_bf16.h>
#include <cstdint>

#define B_     8
#define S_     1024
#define D_     512
#define H_     8
#define HD_    64
#define FF_    2048
#define STEPS_ 64
#define CAP_   1088
#define MTOK   (B_*S_)   /* 8192 */
#define NBLK   128

// ---------------- device scratch (no cudaMalloc allowed) ----------------
__device__ float g_qkv [MTOK*1536];       // prefill QKV
__device__ float g_qkvdec[STEPS_*B_*1536];// decode QKV (precomputed)
__device__ float g_attn[MTOK*D_];
__device__ float g_pre [MTOK*D_];
__device__ float g_h   [MTOK*D_];
__device__ float g_hff [MTOK*FF_];
__device__ float g_kc  [B_*CAP_*D_];
__device__ float g_vc  [B_*CAP_*D_];
__device__ float g_hfft[B_*FF_];
__device__ float g_t1  [B_*D_];
__device__ float g_op  [2*64*64];
__device__ float g_ml  [2*64*2];
__device__ unsigned g_bar_count;
__device__ unsigned g_bar_sense;

// ---------------- reductions ----------------
__device__ __forceinline__ float warpRedSum(float v) {
#pragma unroll
    for (int o = 16; o; o >>= 1) v += __shfl_xor_sync(0xffffffffu, v, o);
    return v;
}
__device__ __forceinline__ float warpRedMax(float v) {
#pragma unroll
    for (int o = 16; o; o >>= 1) v = fmaxf(v, __shfl_xor_sync(0xffffffffu, v, o));
    return v;
}

// ---------------- fence-free global barrier (.cg data protocol) ----------------
__device__ __forceinline__ unsigned ld_acq(const unsigned* p) {
    unsigned v;
    asm volatile("ld.acquire.gpu.u32 %0, [%1];" : "=r"(v) : "l"(p) : "memory");
    return v;
}
__device__ __forceinline__ void st_rel(unsigned* p, unsigned v) {
    asm volatile("st.release.gpu.u32 [%0], %1;" :: "l"(p), "r"(v) : "memory");
}
__device__ __forceinline__ unsigned atomAddAcqRel(unsigned* p, unsigned v) {
    unsigned old;
    asm volatile("atom.acq_rel.gpu.global.add.u32 %0, [%1], %2;"
                 : "=r"(old) : "l"(p), "r"(v) : "memory");
    return old;
}
__device__ __forceinline__ void gbar(unsigned& target, int tid) {
    __syncthreads();
    target += 1;
    if (tid == 0) {
        unsigned a = atomAddAcqRel(&g_bar_count, 1u) + 1u;
        if (a == (unsigned)NBLK) {
            atomicExch(&g_bar_count, 0u);
            st_rel(&g_bar_sense, target);
        } else {
            while ((int)(ld_acq(&g_bar_sense) - target) < 0) { }
        }
    }
    __syncthreads();
}

// ---------------- bf16x3 helpers ----------------
// pack two floats (lo element, hi element) into a bf16x2 word (lo -> bits 0..15)
__device__ __forceinline__ unsigned pack_bf2(float lo, float hi) {
    unsigned r;
    asm("cvt.rn.bf16x2.f32 %0, %1, %2;" : "=r"(r) : "f"(hi), "f"(lo));
    return r;
}
__device__ __forceinline__ float2 unpack_bf2(unsigned u) {
    __nv_bfloat162 t;
    *(unsigned*)&t = u;
    return make_float2(__bfloat162float(t.x), __bfloat162float(t.y));
}

__device__ __forceinline__ void mma_bf(const unsigned a[4][4],
                                       const unsigned b[4][2],
                                       float acc[4][4][4])
{
#pragma unroll
    for (int mt = 0; mt < 4; mt++)
#pragma unroll
        for (int nt = 0; nt < 4; nt++) {
            asm volatile(
                "mma.sync.aligned.m16n8k16.row.col.f32.bf16.bf16.f32 "
                "{%0,%1,%2,%3}, {%4,%5,%6,%7}, {%8,%9}, {%0,%1,%2,%3};"
                : "+f"(acc[mt][nt][0]), "+f"(acc[mt][nt][1]),
                  "+f"(acc[mt][nt][2]), "+f"(acc[mt][nt][3])
                : "r"(a[mt][0]), "r"(a[mt][1]), "r"(a[mt][2]), "r"(a[mt][3]),
                  "r"(b[nt][0]), "r"(b[nt][1]));
        }
}

// ---------------- SGEMM (NT) via bf16x3 tensor-core mma ----------------
// BM=BN=128, BK=16, 256 threads (8 warps, 2x4), warp tile 64x32.
// C = A*B^T with fp32-near accuracy: A=Ah+Al, C ~= Ah*Bh + Ah*Bl + Al*Bh.
// Smem: packed bf16 pairs along k; [row][kpair] word, row stride 12 words.
// KVOUT: 0 none; 1 prefill map (b=row>>10, s=row&1023); 2 decode map
// (b=row&7, s=S_+(row>>3)).
template<int BIAS, int RELU, int RES, int KVOUT>
__global__ void __launch_bounds__(256, 2) sgemm_nt(
    const float* __restrict__ A, const float* __restrict__ Bm,
    const float* __restrict__ bias, const float* __restrict__ R,
    float* __restrict__ C, int M, int N, int K,
    float* __restrict__ kc, float* __restrict__ vc)
{
    __shared__ unsigned AhS[128][12], AlS[128][12];
    __shared__ unsigned BhS[128][12], BlS[128][12];
    const int tid = threadIdx.x;
    const int m0 = blockIdx.y * 128;
    const int n0 = blockIdx.x * 128;
    const int w = tid >> 5, lane = tid & 31;
    const int wm0 = (w >> 2) * 64;      // warp row offset (0/64)
    const int wn0 = (w & 3) * 32;       // warp col offset
    const int g = lane >> 2, tq = lane & 3;
    const int lrow = tid >> 2;          // 0..63
    const int lk4  = (tid & 3) * 4;     // k offset 0,4,8,12
    const int lk2  = (tid & 3) * 2;     // kpair word offset 0,2,4,6

    const float* Ap0 = A  + (size_t)(m0 + lrow)      * K + lk4;
    const float* Ap1 = A  + (size_t)(m0 + lrow + 64) * K + lk4;
    const float* Bp0 = Bm + (size_t)(n0 + lrow)      * K + lk4;
    const float* Bp1 = Bm + (size_t)(n0 + lrow + 64) * K + lk4;

    float acc[4][4][4];
#pragma unroll
    for (int i = 0; i < 4; i++)
#pragma unroll
        for (int j = 0; j < 4; j++)
#pragma unroll
            for (int q = 0; q < 4; q++) acc[i][j][q] = 0.f;

    float4 pa0 = *(const float4*)(Ap0);
    float4 pa1 = *(const float4*)(Ap1);
    float4 pb0 = *(const float4*)(Bp0);
    float4 pb1 = *(const float4*)(Bp1);

    for (int k0 = 0; k0 < K; k0 += 16) {
        // ---- stage: split each fp32 into bf16 hi + bf16 lo, packed pairs ----
        {
            unsigned h; float2 f;
            h = pack_bf2(pa0.x, pa0.y); f = unpack_bf2(h);
            AhS[lrow][lk2] = h;
            AlS[lrow][lk2] = pack_bf2(pa0.x - f.x, pa0.y - f.y);
            h = pack_bf2(pa0.z, pa0.w); f = unpack_bf2(h);
            AhS[lrow][lk2 + 1] = h;
            AlS[lrow][lk2 + 1] = pack_bf2(pa0.z - f.x, pa0.w - f.y);
            h = pack_bf2(pa1.x, pa1.y); f = unpack_bf2(h);
            AhS[lrow + 64][lk2] = h;
            AlS[lrow + 64][lk2] = pack_bf2(pa1.x - f.x, pa1.y - f.y);
            h = pack_bf2(pa1.z, pa1.w); f = unpack_bf2(h);
            AhS[lrow + 64][lk2 + 1] = h;
            AlS[lrow + 64][lk2 + 1] = pack_bf2(pa1.z - f.x, pa1.w - f.y);
            h = pack_bf2(pb0.x, pb0.y); f = unpack_bf2(h);
            BhS[lrow][lk2] = h;
            BlS[lrow][lk2] = pack_bf2(pb0.x - f.x, pb0.y - f.y);
            h = pack_bf2(pb0.z, pb0.w); f = unpack_bf2(h);
            BhS[lrow][lk2 + 1] = h;
            BlS[lrow][lk2 + 1] = pack_bf2(pb0.z - f.x, pb0.w - f.y);
            h = pack_bf2(pb1.x, pb1.y); f = unpack_bf2(h);
            BhS[lrow + 64][lk2] = h;
            BlS[lrow + 64][lk2] = pack_bf2(pb1.x - f.x, pb1.y - f.y);
            h = pack_bf2(pb1.z, pb1.w); f = unpack_bf2(h);
            BhS[lrow + 64][lk2 + 1] = h;
            BlS[lrow + 64][lk2 + 1] = pack_bf2(pb1.z - f.x, pb1.w - f.y);
        }
        __syncthreads();
        if (k0 + 16 < K) {   // prefetch next tile under compute
            pa0 = *(const float4*)(Ap0 + k0 + 16);
            pa1 = *(const float4*)(Ap1 + k0 + 16);
            pb0 = *(const float4*)(Bp0 + k0 + 16);
            pb1 = *(const float4*)(Bp1 + k0 + 16);
        }
        // ---- fragments + 3 mma passes (k16 covers the whole tile) ----
        {
            unsigned ah[4][4], bh[4][2];
#pragma unroll
            for (int mt = 0; mt < 4; mt++) {
                const int rA = wm0 + mt * 16 + g;
                ah[mt][0] = AhS[rA][tq];
                ah[mt][1] = AhS[rA + 8][tq];
                ah[mt][2] = AhS[rA][4 + tq];
                ah[mt][3] = AhS[rA + 8][4 + tq];
            }
#pragma unroll
            for (int nt = 0; nt < 4; nt++) {
                const int rB = wn0 + nt * 8 + g;
                bh[nt][0] = BhS[rB][tq];
                bh[nt][1] = BhS[rB][4 + tq];
            }
            mma_bf(ah, bh, acc);                    // hi*hi
            {
                unsigned bl[4][2];
#pragma unroll
                for (int nt = 0; nt < 4; nt++) {
                    const int rB = wn0 + nt * 8 + g;
                    bl[nt][0] = BlS[rB][tq];
                    bl[nt][1] = BlS[rB][4 + tq];
                }
                mma_bf(ah, bl, acc);                // hi*lo
            }
            {
                unsigned al[4][4];
#pragma unroll
                for (int mt = 0; mt < 4; mt++) {
                    const int rA = wm0 + mt * 16 + g;
                    al[mt][0] = AlS[rA][tq];
                    al[mt][1] = AlS[rA + 8][tq];
                    al[mt][2] = AlS[rA][4 + tq];
                    al[mt][3] = AlS[rA + 8][4 + tq];
                }
                mma_bf(al, bh, acc);                // lo*hi
            }
        }
        __syncthreads();
    }

    // epilogue: pairs (col, col+1) per fragment, rows g and g+8 per 16-tile
#pragma unroll
    for (int nt = 0; nt < 4; nt++) {
        const int col = n0 + wn0 + nt * 8 + tq * 2;
        const float b0v = BIAS ? bias[col] : 0.f;
        const float b1v = BIAS ? bias[col + 1] : 0.f;
#pragma unroll
        for (int mt = 0; mt < 4; mt++) {
#pragma unroll
            for (int rh = 0; rh < 2; rh++) {
                const int row = m0 + wm0 + mt * 16 + g + rh * 8;
                float t0 = acc[mt][nt][rh * 2 + 0] + b0v;
                float t1 = acc[mt][nt][rh * 2 + 1] + b1v;
                if (RES) {
                    float2 r = *(const float2*)(R + (size_t)row * N + col);
                    t0 += r.x; t1 += r.y;
                }
                if (RELU) { t0 = fmaxf(t0, 0.f); t1 = fmaxf(t1, 0.f); }
                float2 v; v.x = t0; v.y = t1;
                *(float2*)(C + (size_t)row * N + col) = v;
                if (KVOUT && col >= 512) {
                    int bb, ss;
                    if (KVOUT == 1) { bb = row >> 10; ss = row & 1023; }
                    else            { bb = row & 7;   ss = S_ + (row >> 3); }
                    float* dst = (col < 1024)
                        ? kc + ((size_t)(bb * CAP_ + ss) * 512 + (col - 512))
                        : vc + ((size_t)(bb * CAP_ + ss) * 512 + (col - 1024));
                    *(float2*)dst = v;
                }
            }
        }
    }
}

// ---------------- prefill flash attention (causal), 64x64 tiles ----------------
__global__ void __launch_bounds__(256) attn_prefill(const float* __restrict__ qkv,
                                                    float* __restrict__ attn)
{
    extern __shared__ float sm[];
    float* Qs = sm;
    float* KP = sm + 64 * 64;
    float* Vs = KP + 64 * 65;

    const int b  = blockIdx.y >> 3;
    const int h  = blockIdx.y & 7;
    const int l0 = blockIdx.x * 64;
    const int tid = threadIdx.x;
    const int tx = tid & 15, ty = tid >> 4;
    const int r0 = ty * 4, c0 = tx * 4;

    const size_t rowbase = (size_t)(b * S_) * 1536;
    const float* qbase = qkv + rowbase + h * 64;
    const float* kbase = qkv + rowbase + 512 + h * 64;
    const float* vbase = qkv + rowbase + 1024 + h * 64;

    const int lt  = tid >> 4;
    const int ld4 = (tid & 15) * 4;

#pragma unroll
    for (int tt = lt; tt < 64; tt += 16) {
        float4 q4 = *(const float4*)(qbase + (size_t)(l0 + tt) * 1536 + ld4);
        Qs[(ld4 + 0) * 64 + tt] = q4.x;
        Qs[(ld4 + 1) * 64 + tt] = q4.y;
        Qs[(ld4 + 2) * 64 + tt] = q4.z;
        Qs[(ld4 + 3) * 64 + tt] = q4.w;
    }

    float o[4][4];
    float mrow[4], lrow[4];
#pragma unroll
    for (int i = 0; i < 4; i++) {
        mrow[i] = -1e30f; lrow[i] = 0.f;
#pragma unroll
        for (int j = 0; j < 4; j++) o[i][j] = 0.f;
    }

    const int ntiles = (l0 >> 6) + 1;
    for (int tile = 0; tile < ntiles; ++tile) {
        const int j0 = tile * 64;
        __syncthreads();
#pragma unroll
        for (int tt = lt; tt < 64; tt += 16) {
            float4 k4 = *(const float4*)(kbase + (size_t)(j0 + tt) * 1536 + ld4);
            KP[(ld4 + 0) * 65 + tt] = k4.x;
            KP[(ld4 + 1) * 65 + tt] = k4.y;
            KP[(ld4 + 2) * 65 + tt] = k4.z;
            KP[(ld4 + 3) * 65 + tt] = k4.w;
            float4 v4 = *(const float4*)(vbase + (size_t)(j0 + tt) * 1536 + ld4);
            *(float4*)(Vs + tt * 64 + ld4) = v4;
        }
        __syncthreads();

        float s[4][4];
#pragma unroll
        for (int i = 0; i < 4; i++)
#pragma unroll
            for (int j = 0; j < 4; j++) s[i][j] = 0.f;

        for (int d = 0; d < 64; d++) {
            float qf[4];
            *(float4*)qf = *(const float4*)(Qs + d * 64 + r0);
            float kf0 = KP[d * 65 + c0 + 0];
            float kf1 = KP[d * 65 + c0 + 1];
            float kf2 = KP[d * 65 + c0 + 2];
            float kf3 = KP[d * 65 + c0 + 3];
#pragma unroll
            for (int i = 0; i < 4; i++) {
                s[i][0] = fmaf(qf[i], kf0, s[i][0]);
                s[i][1] = fmaf(qf[i], kf1, s[i][1]);
                s[i][2] = fmaf(qf[i], kf2, s[i][2]);
                s[i][3] = fmaf(qf[i], kf3, s[i][3]);
            }
        }

        if (j0 == l0) {
#pragma unroll
            for (int i = 0; i < 4; i++)
#pragma unroll
                for (int j = 0; j < 4; j++)
                    s[i][j] = (j0 + c0 + j > l0 + r0 + i) ? -1e30f : s[i][j] * 0.125f;
        } else {
#pragma unroll
            for (int i = 0; i < 4; i++)
#pragma unroll
                for (int j = 0; j < 4; j++) s[i][j] *= 0.125f;
        }

        float p[4][4];
#pragma unroll
        for (int i = 0; i < 4; i++) {
            float rm = fmaxf(fmaxf(s[i][0], s[i][1]), fmaxf(s[i][2], s[i][3]));
#pragma unroll
            for (int off = 8; off; off >>= 1)
                rm = fmaxf(rm, __shfl_xor_sync(0xffffffffu, rm, off));
            float mnew  = fmaxf(mrow[i], rm);
            float alpha = __expf(mrow[i] - mnew);
            float ps = 0.f;
#pragma unroll
            for (int j = 0; j < 4; j++) { p[i][j] = __expf(s[i][j] - mnew); ps += p[i][j]; }
#pragma unroll
            for (int off = 8; off; off >>= 1)
                ps += __shfl_xor_sync(0xffffffffu, ps, off);
            lrow[i] = lrow[i] * alpha + ps;
            mrow[i] = mnew;
#pragma unroll
            for (int j = 0; j < 4; j++) o[i][j] *= alpha;
        }

        __syncthreads();
#pragma unroll
        for (int i = 0; i < 4; i++)
#pragma unroll
            for (int j = 0; j < 4; j++)
                KP[(r0 + i) * 65 + c0 + j] = p[i][j];
        __syncthreads();

        for (int c = 0; c < 64; c++) {
            float vv[4];
            *(float4*)vv = *(const float4*)(Vs + c * 64 + c0);
            float p0 = KP[(r0 + 0) * 65 + c];
            float p1 = KP[(r0 + 1) * 65 + c];
            float p2 = KP[(r0 + 2) * 65 + c];
            float p3 = KP[(r0 + 3) * 65 + c];
#pragma unroll
            for (int j = 0; j < 4; j++) {
                o[0][j] = fmaf(p0, vv[j], o[0][j]);
                o[1][j] = fmaf(p1, vv[j], o[1][j]);
                o[2][j] = fmaf(p2, vv[j], o[2][j]);
                o[3][j] = fmaf(p3, vv[j], o[3][j]);
            }
        }
    }

    float* ob = attn + (size_t)(b * S_ + l0) * 512 + h * 64;
#pragma unroll
    for (int i = 0; i < 4; i++) {
        float inv = 1.f / lrow[i];
        float4 v;
        v.x = o[i][0] * inv; v.y = o[i][1] * inv;
        v.z = o[i][2] * inv; v.w = o[i][3] * inv;
        *(float4*)(ob + (size_t)(r0 + i) * 512 + c0) = v;
    }
}

// ---------------- prefill LayerNorm over rows of 512 ----------------
__global__ void __launch_bounds__(256) ln_rows(const float* __restrict__ in,
                                               const float* __restrict__ g,
                                               const float* __restrict__ be,
                                               float* __restrict__ out, int outExtra)
{
    const int r = blockIdx.x;
    const int tid = threadIdx.x;
    const float* row = in + (size_t)r * 512;
    float v0 = row[tid], v1 = row[tid + 256];
    float s  = warpRedSum(v0 + v1);
    float s2 = warpRedSum(v0 * v0 + v1 * v1);
    __shared__ float r1[8], r2[8];
    __shared__ float smu, srs;
    const int w = tid >> 5, lane = tid & 31;
    if (lane == 0) { r1[w] = s; r2[w] = s2; }
    __syncthreads();
    if (tid == 0) {
        float S = 0.f, S2 = 0.f;
#pragma unroll
        for (int i = 0; i < 8; i++) { S += r1[i]; S2 += r2[i]; }
        float mu  = S * (1.f / 512.f);
        float var = S2 * (1.f / 512.f) - mu * mu;
        smu = mu; srs = rsqrtf(var + 1e-5f);
    }
    __syncthreads();
    const int orow = r + (r >> 10) * outExtra;
    float* od = out + (size_t)orow * 512;
    od[tid]       = (v0 - smu) * srs * g[tid]       + be[tid];
    od[tid + 256] = (v1 - smu) * srs * g[tid + 256] + be[tid + 256];
}

// ---------------- megakernel building blocks ----------------
template<int KP>
__device__ __forceinline__ void dot4(const float* __restrict__ wr,
                                     const float* xs, int Kstride, int lane,
                                     float& a0, float& a1, float& a2, float& a3)
{
    a0 = a1 = a2 = a3 = 0.f;
#pragma unroll
    for (int kp = 0; kp < KP; kp++) {
        const int k4 = kp * 128 + lane * 4;
        float4 wv = *(const float4*)(wr + k4);
        float4 x0 = *(const float4*)(xs + k4);
        float4 x1 = *(const float4*)(xs + Kstride + k4);
        float4 x2 = *(const float4*)(xs + 2 * Kstride + k4);
        float4 x3 = *(const float4*)(xs + 3 * Kstride + k4);
        a0 = fmaf(wv.x, x0.x, fmaf(wv.y, x0.y, fmaf(wv.z, x0.z, fmaf(wv.w, x0.w, a0))));
        a1 = fmaf(wv.x, x1.x, fmaf(wv.y, x1.y, fmaf(wv.z, x1.z, fmaf(wv.w, x1.w, a1))));
        a2 = fmaf(wv.x, x2.x, fmaf(wv.y, x2.y, fmaf(wv.z, x2.z, fmaf(wv.w, x2.w, a2))));
        a3 = fmaf(wv.x, x3.x, fmaf(wv.y, x3.y, fmaf(wv.z, x3.z, fmaf(wv.w, x3.w, a3))));
    }
    a0 = warpRedSum(a0); a1 = warpRedSum(a1);
    a2 = warpRedSum(a2); a3 = warpRedSum(a3);
}

__device__ __forceinline__ void warp_ln(const float* __restrict__ a,
                                        const float* r,
                                        const float* __restrict__ gw,
                                        const float* __restrict__ gb,
                                        float* o, int lane)
{
    float vals[16];
    float sv = 0.f, sq = 0.f;
#pragma unroll
    for (int g = 0; g < 4; g++) {
        const int idx = g * 128 + lane * 4;
        float4 av = __ldcg((const float4*)(a + idx));
        float4 rv = *(const float4*)(r + idx);
        float a0 = av.x + rv.x, a1 = av.y + rv.y;
        float a2 = av.z + rv.z, a3 = av.w + rv.w;
        vals[g * 4 + 0] = a0; vals[g * 4 + 1] = a1;
        vals[g * 4 + 2] = a2; vals[g * 4 + 3] = a3;
        sv += a0 + a1 + a2 + a3;
        sq += a0 * a0 + a1 * a1 + a2 * a2 + a3 * a3;
    }
    sv = warpRedSum(sv); sq = warpRedSum(sq);
    float mu = sv * (1.f / 512.f);
    float rs = rsqrtf(sq * (1.f / 512.f) - mu * mu + 1e-5f);
#pragma unroll
    for (int g = 0; g < 4; g++)
#pragma unroll
        for (int j = 0; j < 4; j++) {
            const int idx = g * 128 + lane * 4 + j;
            o[idx] = (vals[g * 4 + j] - mu) * rs * gw[idx] + gb[idx];
        }
}

// ---------------- decode megakernel: QKV precomputed, 4 barriers/step --------
__global__ void __launch_bounds__(256, 1) decode_mega(
    const float* __restrict__ dx,
    const float* __restrict__ qdec,
    const float* __restrict__ outW, const float* __restrict__ outB,
    const float* __restrict__ w1, const float* __restrict__ b1,
    const float* __restrict__ w2, const float* __restrict__ b2,
    const float* __restrict__ ln1w, const float* __restrict__ ln1b,
    const float* __restrict__ ln2w, const float* __restrict__ ln2b,
    float* __restrict__ out,
    float* __restrict__ kc, float* __restrict__ vc,
    float* __restrict__ hfft, float* __restrict__ t1,
    float* __restrict__ opart, float* __restrict__ mlpart)
{
    extern __shared__ float xs[];      // 8192 floats (32KB)
    __shared__ float s_ln[4 * 512];
    __shared__ float s_red[16];
    __shared__ float s_q[64];
    __shared__ float s_part[256];
    __shared__ float s_comb[128];
    __shared__ unsigned s_base;

    const int tid  = threadIdx.x;
    const int bid  = blockIdx.x;
    const int w    = tid >> 5, lane = tid & 31;
    const int half = bid >> 6;
    const int b0   = half * 4;
    const int wg   = (bid & 63) * 8 + w;

    if (tid == 0) s_base = ld_acq(&g_bar_sense);
    __syncthreads();
    unsigned target = s_base;

    for (int step = 0; step < STEPS_; step++) {
        const int cur = S_ + step;
        const float* xt = dx + (size_t)step * (B_ * D_);

        // ===== slot B: LN2(prev) on blocks 0 & 64 + attention partials =====
        if (step > 0 && (bid == 0 || bid == 64) && w < 4)
            warp_ln(t1 + (b0 + w) * 512, s_ln + w * 512, ln2w, ln2b,
                    out + ((size_t)(b0 + w) * CAP_ + (cur - 1)) * 512, lane);
        {
            const int part = bid >> 6;
            const int bb = (bid >> 3) & 7;
            const int h  = bid & 7;
            const int kvlen = cur + 1;
            const int hlen  = kvlen >> 1;
            const int tstart = part ? hlen : 0;
            const int tend   = part ? kvlen : hlen;
            if (tid < 64)
                s_q[tid] = __ldg(&qdec[(size_t)(step * 8 + bb) * 1536 + h * 64 + tid]);
            __syncthreads();
            const int tl = lane >> 2;
            const int kq = (lane & 3) * 16;
            const float4 qa = *(const float4*)(s_q + kq);
            const float4 qb = *(const float4*)(s_q + kq + 4);
            const float4 qc = *(const float4*)(s_q + kq + 8);
            const float4 qd = *(const float4*)(s_q + kq + 12);
            const float* kb = kc + (size_t)bb * CAP_ * 512 + h * 64;
            for (int t0 = tstart; t0 < tend; t0 += 64) {
                const int t = t0 + w * 8 + tl;
                const bool valid = t < tend;
                const float* kr = kb + (size_t)(valid ? t : tstart) * 512 + kq;
                float4 k0 = __ldcg((const float4*)(kr));
                float4 k1 = __ldcg((const float4*)(kr + 4));
                float4 k2 = __ldcg((const float4*)(kr + 8));
                float4 k3 = __ldcg((const float4*)(kr + 12));
                float s;
                s = k0.x * qa.x;
                s = fmaf(k0.y, qa.y, s); s = fmaf(k0.z, qa.z, s); s = fmaf(k0.w, qa.w, s);
                s = fmaf(k1.x, qb.x, s); s = fmaf(k1.y, qb.y, s);
                s = fmaf(k1.z, qb.z, s); s = fmaf(k1.w, qb.w, s);
                s = fmaf(k2.x, qc.x, s); s = fmaf(k2.y, qc.y, s);
                s = fmaf(k2.z, qc.z, s); s = fmaf(k2.w, qc.w, s);
                s = fmaf(k3.x, qd.x, s); s = fmaf(k3.y, qd.y, s);
                s = fmaf(k3.z, qd.z, s); s = fmaf(k3.w, qd.w, s);
                s += __shfl_xor_sync(0xffffffffu, s, 1);
                s += __shfl_xor_sync(0xffffffffu, s, 2);
                if (valid && (lane & 3) == 0) xs[t] = s * 0.125f;
            }
            __syncthreads();
            float lmax = -1e30f;
            for (int t = tstart + tid; t < tend; t += 256) lmax = fmaxf(lmax, xs[t]);
            lmax = warpRedMax(lmax);
            if (lane == 0) s_red[w] = lmax;
            __syncthreads();
            float gm = s_red[0];
#pragma unroll
            for (int i = 1; i < 8; i++) gm = fmaxf(gm, s_red[i]);
            float ls = 0.f;
            for (int t = tstart + tid; t < tend; t += 256) {
                float p = __expf(xs[t] - gm);
                xs[t] = p;
                ls += p;
            }
            ls = warpRedSum(ls);
            if (lane == 0) s_red[8 + w] = ls;
            __syncthreads();
            float ssum = 0.f;
#pragma unroll
            for (int i = 0; i < 8; i++) ssum += s_red[8 + i];
            const int d = tid & 63, pt = tid >> 6;
            const float* vb = vc + (size_t)bb * CAP_ * 512 + h * 64 + d;
            float vacc = 0.f;
            for (int t = tstart + pt; t < tend; t += 4)
                vacc = fmaf(xs[t], __ldcg(vb + (size_t)t * 512), vacc);
            s_part[tid] = vacc;
            __syncthreads();
            const int gi = part * 64 + bb * 8 + h;
            if (pt == 0)
                __stcg(&opart[gi * 64 + d],
                       s_part[d] + s_part[64 + d] + s_part[128 + d] + s_part[192 + d]);
            if (tid == 0) {
                __stcg(&mlpart[gi * 2], gm);
                __stcg(&mlpart[gi * 2 + 1], ssum);
            }
        }
        gbar(target, tid);

        // ===== phase C: combine attn parts + out-proj =====
        if (tid < 64) {
            float m1 = __ldcg(&mlpart[tid * 2]);
            float l1 = __ldcg(&mlpart[tid * 2 + 1]);
            float m2 = __ldcg(&mlpart[(64 + tid) * 2]);
            float l2 = __ldcg(&mlpart[(64 + tid) * 2 + 1]);
            float gm = fmaxf(m1, m2);
            float e1 = __expf(m1 - gm), e2 = __expf(m2 - gm);
            float inv = 1.f / (e1 * l1 + e2 * l2);
            s_comb[tid * 2]     = e1 * inv;
            s_comb[tid * 2 + 1] = e2 * inv;
        }
        __syncthreads();
        for (int i = tid; i < 2048; i += 256) {
            const int b = b0 + (i >> 9);
            const int col = i & 511;
            const int gi = b * 8 + (col >> 6);
            const int d = col & 63;
            xs[i] = s_comb[gi * 2]     * __ldcg(&opart[gi * 64 + d])
                  + s_comb[gi * 2 + 1] * __ldcg(&opart[(64 + gi) * 64 + d]);
        }
        __syncthreads();
        {
            float a0, a1, a2, a3;
            dot4<4>(outW + (size_t)wg * 512, xs, 512, lane, a0, a1, a2, a3);
            if (lane == 0) {
                const float bv = outB[wg];
                __stcg(&t1[(b0 + 0) * 512 + wg], a0 + bv);
                __stcg(&t1[(b0 + 1) * 512 + wg], a1 + bv);
                __stcg(&t1[(b0 + 2) * 512 + wg], a2 + bv);
                __stcg(&t1[(b0 + 3) * 512 + wg], a3 + bv);
            }
        }
        gbar(target, tid);

        // ===== phase E: LN1 (warps 0-3, into s_ln) + FF1 (N=2048, relu) =====
        if (w < 4)
            warp_ln(t1 + (b0 + w) * 512, xt + (b0 + w) * 512,
                    ln1w, ln1b, s_ln + w * 512, lane);
        __syncthreads();
#pragma unroll
        for (int o = 0; o < 4; o++) {
            const int n = wg + o * 512;
            float a0, a1, a2, a3;
            dot4<4>(w1 + (size_t)n * 512, s_ln, 512, lane, a0, a1, a2, a3);
            if (lane == 0) {
                const float bv = b1[n];
                __stcg(&hfft[(b0 + 0) * 2048 + n], fmaxf(a0 + bv, 0.f));
                __stcg(&hfft[(b0 + 1) * 2048 + n], fmaxf(a1 + bv, 0.f));
                __stcg(&hfft[(b0 + 2) * 2048 + n], fmaxf(a2 + bv, 0.f));
                __stcg(&hfft[(b0 + 3) * 2048 + n], fmaxf(a3 + bv, 0.f));
            }
        }
        gbar(target, tid);

        // ===== phase F: FF2 (N=512, K=2048) -> t1 =====
        {
            const float4* src = (const float4*)(hfft + b0 * 2048);
            float4* dst = (float4*)xs;
            for (int i = tid; i < 2048; i += 256) dst[i] = __ldcg(src + i);
        }
        __syncthreads();
        {
            float a0, a1, a2, a3;
            dot4<16>(w2 + (size_t)wg * 2048, xs, 2048, lane, a0, a1, a2, a3);
            if (lane == 0) {
                const float bv = b2[wg];
                __stcg(&t1[(b0 + 0) * 512 + wg], a0 + bv);
                __stcg(&t1[(b0 + 1) * 512 + wg], a1 + bv);
                __stcg(&t1[(b0 + 2) * 512 + wg], a2 + bv);
                __stcg(&t1[(b0 + 3) * 512 + wg], a3 + bv);
            }
        }
        gbar(target, tid);
    }

    // final LN2 for the last step
    if ((bid == 0 || bid == 64) && w < 4)
        warp_ln(t1 + (b0 + w) * 512, s_ln + w * 512, ln2w, ln2b,
                out + ((size_t)(b0 + w) * CAP_ + (S_ + STEPS_ - 1)) * 512, lane);
}

// ---------------- host launcher ----------------
struct ScratchPtrs {
    float *Qkv, *Qdec, *Attn, *Pre, *Hb, *Hff, *Kc, *Vc, *Hfft, *T1, *Op, *Ml;
    cudaStream_t sDec;
    cudaEvent_t evQkv, evDec;
};

static const ScratchPtrs& get_scratch() {
    static ScratchPtrs p;
    static bool init = false;
    if (!init) {
        cudaGetSymbolAddress((void**)&p.Qkv,  g_qkv);
        cudaGetSymbolAddress((void**)&p.Qdec, g_qkvdec);
        cudaGetSymbolAddress((void**)&p.Attn, g_attn);
        cudaGetSymbolAddress((void**)&p.Pre,  g_pre);
        cudaGetSymbolAddress((void**)&p.Hb,   g_h);
        cudaGetSymbolAddress((void**)&p.Hff,  g_hff);
        cudaGetSymbolAddress((void**)&p.Kc,   g_kc);
        cudaGetSymbolAddress((void**)&p.Vc,   g_vc);
        cudaGetSymbolAddress((void**)&p.Hfft, g_hfft);
        cudaGetSymbolAddress((void**)&p.T1,   g_t1);
        cudaGetSymbolAddress((void**)&p.Op,   g_op);
        cudaGetSymbolAddress((void**)&p.Ml,   g_ml);
        cudaFuncSetAttribute(attn_prefill,
                             cudaFuncAttributeMaxDynamicSharedMemorySize, 49408);
        cudaFuncSetAttribute(decode_mega,
                             cudaFuncAttributeMaxDynamicSharedMemorySize, 32768);
        cudaStreamCreateWithFlags(&p.sDec, cudaStreamNonBlocking);
        cudaEventCreateWithFlags(&p.evQkv, cudaEventDisableTiming);
        cudaEventCreateWithFlags(&p.evDec, cudaEventDisableTiming);
        init = true;
    }
    return p;
}

extern "C" void kernel_launch(void* const* d_in, const int* in_sizes, int n_in,
                              void* d_out, int out_size)
{
    (void)in_sizes; (void)n_in; (void)out_size;
    const float* x    = (const float*)d_in[0];
    const float* dx   = (const float*)d_in[1];
    // d_in[2] = causal_mask (bool) — unused, causality computed analytically
    const float* qkvW = (const float*)d_in[3];
    const float* qkvB = (const float*)d_in[4];
    const float* outW = (const float*)d_in[5];
    const float* outB = (const float*)d_in[6];
    const float* w1   = (const float*)d_in[7];
    const float* b1   = (const float*)d_in[8];
    const float* w2   = (const float*)d_in[9];
    const float* b2   = (const float*)d_in[10];
    const float* ln1w = (const float*)d_in[11];
    const float* ln1b = (const float*)d_in[12];
    const float* ln2w = (const float*)d_in[13];
    const float* ln2b = (const float*)d_in[14];
    float* out = (float*)d_out;

    const ScratchPtrs& sp = get_scratch();

    // ---- QKV GEMMs: prefill (seeds KV rows 0..1023) + ALL decode steps ----
    sgemm_nt<1,0,0,1><<<dim3(12, 64), 256>>>(x, qkvW, qkvB, nullptr, sp.Qkv,
                                             MTOK, 1536, 512, sp.Kc, sp.Vc);
    sgemm_nt<1,0,0,2><<<dim3(12, 4), 256>>>(dx, qkvW, qkvB, nullptr, sp.Qdec,
                                            STEPS_ * B_, 1536, 512, sp.Kc, sp.Vc);

    // ---- fork: decode runs concurrently with the rest of prefill ----
    cudaEventRecord(sp.evQkv, 0);
    cudaStreamWaitEvent(sp.sDec, sp.evQkv, 0);
    decode_mega<<<NBLK, 256, 32768, sp.sDec>>>(dx, sp.Qdec, outW, outB,
                                               w1, b1, w2, b2,
                                               ln1w, ln1b, ln2w, ln2b, out,
                                               sp.Kc, sp.Vc,
                                               sp.Hfft, sp.T1, sp.Op, sp.Ml);
    cudaEventRecord(sp.evDec, sp.sDec);

    // ---- rest of prefill on the main stream ----
    attn_prefill<<<dim3(16, 64), 256, 49408>>>(sp.Qkv, sp.Attn);
    sgemm_nt<1,0,1,0><<<dim3(4, 64), 256>>>(sp.Attn, outW, outB, x, sp.Pre,
                                            MTOK, 512, 512, nullptr, nullptr);
    ln_rows<<<MTOK, 256>>>(sp.Pre, ln1w, ln1b, sp.Hb, 0);
    sgemm_nt<1,1,0,0><<<dim3(16, 64), 256>>>(sp.Hb, w1, b1, nullptr, sp.Hff,
                                             MTOK, 2048, 512, nullptr, nullptr);
    sgemm_nt<1,0,1,0><<<dim3(4, 64), 256>>>(sp.Hff, w2, b2, sp.Hb, sp.Pre,
                                            MTOK, 512, 2048, nullptr, nullptr);
    ln_rows<<<MTOK, 256>>>(sp.Pre, ln2w, ln2b, out, 64);

    // ---- join: main stream completes only after decode finishes ----
    cudaStreamWaitEvent(0, sp.evDec, 0);
}

// round 13
// speedup vs baseline: 3.2005x; 2.2208x over previous
#include <cuda_runtime.h>
#include <cuda_bf16.h>
#include <cstdint>

#define B_     8
#define S_     1024
#define D_     512
#define H_     8
#define HD_    64
#define FF_    2048
#define STEPS_ 64
#define CAP_   1088
#define MTOK   (B_*S_)   /* 8192 */
#define MDEC   (STEPS_*B_) /* 512 */

// ---------------- device scratch (no cudaMalloc allowed) ----------------
__device__ float g_qkv [MTOK*1536];       // prefill QKV
__device__ float g_qkvdec[MDEC*1536];     // decode QKV (row = step*8+b)
__device__ float g_attn[MTOK*D_];
__device__ float g_pre [MTOK*D_];
__device__ float g_h   [MTOK*D_];
__device__ float g_hff [MTOK*FF_];
__device__ float g_kc  [B_*CAP_*D_];
__device__ float g_vc  [B_*CAP_*D_];
__device__ float g_dattn[MDEC*D_];        // decode attention out
__device__ float g_dpre [MDEC*D_];
__device__ float g_dhb  [MDEC*D_];
__device__ float g_dhff [MDEC*FF_];

// ---------------- reductions ----------------
__device__ __forceinline__ float warpRedSum(float v) {
#pragma unroll
    for (int o = 16; o; o >>= 1) v += __shfl_xor_sync(0xffffffffu, v, o);
    return v;
}

// ---------------- bf16x3 helpers ----------------
__device__ __forceinline__ unsigned pack_bf2(float lo, float hi) {
    unsigned r;
    asm("cvt.rn.bf16x2.f32 %0, %1, %2;" : "=r"(r) : "f"(hi), "f"(lo));
    return r;
}
__device__ __forceinline__ float2 unpack_bf2(unsigned u) {
    __nv_bfloat162 t;
    *(unsigned*)&t = u;
    return make_float2(__bfloat162float(t.x), __bfloat162float(t.y));
}

__device__ __forceinline__ void mma_bf(const unsigned a[4][4],
                                       const unsigned b[4][2],
                                       float acc[4][4][4])
{
#pragma unroll
    for (int mt = 0; mt < 4; mt++)
#pragma unroll
        for (int nt = 0; nt < 4; nt++) {
            asm volatile(
                "mma.sync.aligned.m16n8k16.row.col.f32.bf16.bf16.f32 "
                "{%0,%1,%2,%3}, {%4,%5,%6,%7}, {%8,%9}, {%0,%1,%2,%3};"
                : "+f"(acc[mt][nt][0]), "+f"(acc[mt][nt][1]),
                  "+f"(acc[mt][nt][2]), "+f"(acc[mt][nt][3])
                : "r"(a[mt][0]), "r"(a[mt][1]), "r"(a[mt][2]), "r"(a[mt][3]),
                  "r"(b[nt][0]), "r"(b[nt][1]));
        }
}

// ---------------- SGEMM (NT) via bf16x3 tensor-core mma ----------------
// BM=BN=128, BK=16, 256 threads (8 warps 2x4), warp tile 64x32.
// KVOUT: 0 none; 1 prefill map (b=row>>10,s=row&1023); 2 decode map
// (b=row&7, s=S_+(row>>3)).
template<int BIAS, int RELU, int RES, int KVOUT>
__global__ void __launch_bounds__(256, 2) sgemm_nt(
    const float* __restrict__ A, const float* __restrict__ Bm,
    const float* __restrict__ bias, const float* __restrict__ R,
    float* __restrict__ C, int M, int N, int K,
    float* __restrict__ kc, float* __restrict__ vc)
{
    __shared__ unsigned AhS[128][12], AlS[128][12];
    __shared__ unsigned BhS[128][12], BlS[128][12];
    const int tid = threadIdx.x;
    const int m0 = blockIdx.y * 128;
    const int n0 = blockIdx.x * 128;
    const int w = tid >> 5, lane = tid & 31;
    const int wm0 = (w >> 2) * 64;
    const int wn0 = (w & 3) * 32;
    const int g = lane >> 2, tq = lane & 3;
    const int lrow = tid >> 2;
    const int lk4  = (tid & 3) * 4;
    const int lk2  = (tid & 3) * 2;

    const float* Ap0 = A  + (size_t)(m0 + lrow)      * K + lk4;
    const float* Ap1 = A  + (size_t)(m0 + lrow + 64) * K + lk4;
    const float* Bp0 = Bm + (size_t)(n0 + lrow)      * K + lk4;
    const float* Bp1 = Bm + (size_t)(n0 + lrow + 64) * K + lk4;

    float acc[4][4][4];
#pragma unroll
    for (int i = 0; i < 4; i++)
#pragma unroll
        for (int j = 0; j < 4; j++)
#pragma unroll
            for (int q = 0; q < 4; q++) acc[i][j][q] = 0.f;

    float4 pa0 = *(const float4*)(Ap0);
    float4 pa1 = *(const float4*)(Ap1);
    float4 pb0 = *(const float4*)(Bp0);
    float4 pb1 = *(const float4*)(Bp1);

    for (int k0 = 0; k0 < K; k0 += 16) {
        {
            unsigned h; float2 f;
            h = pack_bf2(pa0.x, pa0.y); f = unpack_bf2(h);
            AhS[lrow][lk2] = h;
            AlS[lrow][lk2] = pack_bf2(pa0.x - f.x, pa0.y - f.y);
            h = pack_bf2(pa0.z, pa0.w); f = unpack_bf2(h);
            AhS[lrow][lk2 + 1] = h;
            AlS[lrow][lk2 + 1] = pack_bf2(pa0.z - f.x, pa0.w - f.y);
            h = pack_bf2(pa1.x, pa1.y); f = unpack_bf2(h);
            AhS[lrow + 64][lk2] = h;
            AlS[lrow + 64][lk2] = pack_bf2(pa1.x - f.x, pa1.y - f.y);
            h = pack_bf2(pa1.z, pa1.w); f = unpack_bf2(h);
            AhS[lrow + 64][lk2 + 1] = h;
            AlS[lrow + 64][lk2 + 1] = pack_bf2(pa1.z - f.x, pa1.w - f.y);
            h = pack_bf2(pb0.x, pb0.y); f = unpack_bf2(h);
            BhS[lrow][lk2] = h;
            BlS[lrow][lk2] = pack_bf2(pb0.x - f.x, pb0.y - f.y);
            h = pack_bf2(pb0.z, pb0.w); f = unpack_bf2(h);
            BhS[lrow][lk2 + 1] = h;
            BlS[lrow][lk2 + 1] = pack_bf2(pb0.z - f.x, pb0.w - f.y);
            h = pack_bf2(pb1.x, pb1.y); f = unpack_bf2(h);
            BhS[lrow + 64][lk2] = h;
            BlS[lrow + 64][lk2] = pack_bf2(pb1.x - f.x, pb1.y - f.y);
            h = pack_bf2(pb1.z, pb1.w); f = unpack_bf2(h);
            BhS[lrow + 64][lk2 + 1] = h;
            BlS[lrow + 64][lk2 + 1] = pack_bf2(pb1.z - f.x, pb1.w - f.y);
        }
        __syncthreads();
        if (k0 + 16 < K) {
            pa0 = *(const float4*)(Ap0 + k0 + 16);
            pa1 = *(const float4*)(Ap1 + k0 + 16);
            pb0 = *(const float4*)(Bp0 + k0 + 16);
            pb1 = *(const float4*)(Bp1 + k0 + 16);
        }
        {
            unsigned ah[4][4], bh[4][2];
#pragma unroll
            for (int mt = 0; mt < 4; mt++) {
                const int rA = wm0 + mt * 16 + g;
                ah[mt][0] = AhS[rA][tq];
                ah[mt][1] = AhS[rA + 8][tq];
                ah[mt][2] = AhS[rA][4 + tq];
                ah[mt][3] = AhS[rA + 8][4 + tq];
            }
#pragma unroll
            for (int nt = 0; nt < 4; nt++) {
                const int rB = wn0 + nt * 8 + g;
                bh[nt][0] = BhS[rB][tq];
                bh[nt][1] = BhS[rB][4 + tq];
            }
            mma_bf(ah, bh, acc);
            {
                unsigned bl[4][2];
#pragma unroll
                for (int nt = 0; nt < 4; nt++) {
                    const int rB = wn0 + nt * 8 + g;
                    bl[nt][0] = BlS[rB][tq];
                    bl[nt][1] = BlS[rB][4 + tq];
                }
                mma_bf(ah, bl, acc);
            }
            {
                unsigned al[4][4];
#pragma unroll
                for (int mt = 0; mt < 4; mt++) {
                    const int rA = wm0 + mt * 16 + g;
                    al[mt][0] = AlS[rA][tq];
                    al[mt][1] = AlS[rA + 8][tq];
                    al[mt][2] = AlS[rA][4 + tq];
                    al[mt][3] = AlS[rA + 8][4 + tq];
                }
                mma_bf(al, bh, acc);
            }
        }
        __syncthreads();
    }

#pragma unroll
    for (int nt = 0; nt < 4; nt++) {
        const int col = n0 + wn0 + nt * 8 + tq * 2;
        const float b0v = BIAS ? bias[col] : 0.f;
        const float b1v = BIAS ? bias[col + 1] : 0.f;
#pragma unroll
        for (int mt = 0; mt < 4; mt++) {
#pragma unroll
            for (int rh = 0; rh < 2; rh++) {
                const int row = m0 + wm0 + mt * 16 + g + rh * 8;
                float t0 = acc[mt][nt][rh * 2 + 0] + b0v;
                float t1 = acc[mt][nt][rh * 2 + 1] + b1v;
                if (RES) {
                    float2 r = *(const float2*)(R + (size_t)row * N + col);
                    t0 += r.x; t1 += r.y;
                }
                if (RELU) { t0 = fmaxf(t0, 0.f); t1 = fmaxf(t1, 0.f); }
                float2 v; v.x = t0; v.y = t1;
                *(float2*)(C + (size_t)row * N + col) = v;
                if (KVOUT && col >= 512) {
                    int bb, ss;
                    if (KVOUT == 1) { bb = row >> 10; ss = row & 1023; }
                    else            { bb = row & 7;   ss = S_ + (row >> 3); }
                    float* dst = (col < 1024)
                        ? kc + ((size_t)(bb * CAP_ + ss) * 512 + (col - 512))
                        : vc + ((size_t)(bb * CAP_ + ss) * 512 + (col - 1024));
                    *(float2*)dst = v;
                }
            }
        }
    }
}

// ---------------- flash attention core (shared by prefill and decode) --------
// Computes 64 queries vs ntiles KV tiles with diagonal mask on the last tile.
// Q/K/V/O addressing passed via pointers + strides.
__device__ __forceinline__ void flash64(
    const float* __restrict__ qbase, size_t qstride,   // q row i at qbase + i*qstride
    const float* __restrict__ kbase, size_t kstride,
    const float* __restrict__ vbase, size_t vstride,
    float* __restrict__ obase, size_t ostride,
    int ntiles, int diagTile, float* sm, int tid)
{
    float* Qs = sm;            // [d][r] pitch 64
    float* KP = sm + 64 * 64;  // K: [d][c] pitch 65; then P
    float* Vs = KP + 64 * 65;  // [t][d] pitch 64

    const int tx = tid & 15, ty = tid >> 4;
    const int r0 = ty * 4, c0 = tx * 4;
    const int lt  = tid >> 4;
    const int ld4 = (tid & 15) * 4;

#pragma unroll
    for (int tt = lt; tt < 64; tt += 16) {
        float4 q4 = *(const float4*)(qbase + (size_t)tt * qstride + ld4);
        Qs[(ld4 + 0) * 64 + tt] = q4.x;
        Qs[(ld4 + 1) * 64 + tt] = q4.y;
        Qs[(ld4 + 2) * 64 + tt] = q4.z;
        Qs[(ld4 + 3) * 64 + tt] = q4.w;
    }

    float o[4][4];
    float mrow[4], lrow[4];
#pragma unroll
    for (int i = 0; i < 4; i++) {
        mrow[i] = -1e30f; lrow[i] = 0.f;
#pragma unroll
        for (int j = 0; j < 4; j++) o[i][j] = 0.f;
    }

    for (int tile = 0; tile < ntiles; ++tile) {
        const int j0 = tile * 64;
        __syncthreads();
#pragma unroll
        for (int tt = lt; tt < 64; tt += 16) {
            float4 k4 = *(const float4*)(kbase + (size_t)(j0 + tt) * kstride + ld4);
            KP[(ld4 + 0) * 65 + tt] = k4.x;
            KP[(ld4 + 1) * 65 + tt] = k4.y;
            KP[(ld4 + 2) * 65 + tt] = k4.z;
            KP[(ld4 + 3) * 65 + tt] = k4.w;
            float4 v4 = *(const float4*)(vbase + (size_t)(j0 + tt) * vstride + ld4);
            *(float4*)(Vs + tt * 64 + ld4) = v4;
        }
        __syncthreads();

        float s[4][4];
#pragma unroll
        for (int i = 0; i < 4; i++)
#pragma unroll
            for (int j = 0; j < 4; j++) s[i][j] = 0.f;

        for (int d = 0; d < 64; d++) {
            float qf[4];
            *(float4*)qf = *(const float4*)(Qs + d * 64 + r0);
            float kf0 = KP[d * 65 + c0 + 0];
            float kf1 = KP[d * 65 + c0 + 1];
            float kf2 = KP[d * 65 + c0 + 2];
            float kf3 = KP[d * 65 + c0 + 3];
#pragma unroll
            for (int i = 0; i < 4; i++) {
                s[i][0] = fmaf(qf[i], kf0, s[i][0]);
                s[i][1] = fmaf(qf[i], kf1, s[i][1]);
                s[i][2] = fmaf(qf[i], kf2, s[i][2]);
                s[i][3] = fmaf(qf[i], kf3, s[i][3]);
            }
        }

        if (tile == diagTile) {
#pragma unroll
            for (int i = 0; i < 4; i++)
#pragma unroll
                for (int j = 0; j < 4; j++)
                    s[i][j] = (c0 + j > r0 + i) ? -1e30f : s[i][j] * 0.125f;
        } else {
#pragma unroll
            for (int i = 0; i < 4; i++)
#pragma unroll
                for (int j = 0; j < 4; j++) s[i][j] *= 0.125f;
        }

        float p[4][4];
#pragma unroll
        for (int i = 0; i < 4; i++) {
            float rm = fmaxf(fmaxf(s[i][0], s[i][1]), fmaxf(s[i][2], s[i][3]));
#pragma unroll
            for (int off = 8; off; off >>= 1)
                rm = fmaxf(rm, __shfl_xor_sync(0xffffffffu, rm, off));
            float mnew  = fmaxf(mrow[i], rm);
            float alpha = __expf(mrow[i] - mnew);
            float ps = 0.f;
#pragma unroll
            for (int j = 0; j < 4; j++) { p[i][j] = __expf(s[i][j] - mnew); ps += p[i][j]; }
#pragma unroll
            for (int off = 8; off; off >>= 1)
                ps += __shfl_xor_sync(0xffffffffu, ps, off);
            lrow[i] = lrow[i] * alpha + ps;
            mrow[i] = mnew;
#pragma unroll
            for (int j = 0; j < 4; j++) o[i][j] *= alpha;
        }

        __syncthreads();
#pragma unroll
        for (int i = 0; i < 4; i++)
#pragma unroll
            for (int j = 0; j < 4; j++)
                KP[(r0 + i) * 65 + c0 + j] = p[i][j];
        __syncthreads();

        for (int c = 0; c < 64; c++) {
            float vv[4];
            *(float4*)vv = *(const float4*)(Vs + c * 64 + c0);
            float p0 = KP[(r0 + 0) * 65 + c];
            float p1 = KP[(r0 + 1) * 65 + c];
            float p2 = KP[(r0 + 2) * 65 + c];
            float p3 = KP[(r0 + 3) * 65 + c];
#pragma unroll
            for (int j = 0; j < 4; j++) {
                o[0][j] = fmaf(p0, vv[j], o[0][j]);
                o[1][j] = fmaf(p1, vv[j], o[1][j]);
                o[2][j] = fmaf(p2, vv[j], o[2][j]);
                o[3][j] = fmaf(p3, vv[j], o[3][j]);
            }
        }
    }

#pragma unroll
    for (int i = 0; i < 4; i++) {
        float inv = 1.f / lrow[i];
        float4 v;
        v.x = o[i][0] * inv; v.y = o[i][1] * inv;
        v.z = o[i][2] * inv; v.w = o[i][3] * inv;
        *(float4*)(obase + (size_t)(r0 + i) * ostride + c0) = v;
    }
}

// prefill: grid (S/64, B*H)
__global__ void __launch_bounds__(256) attn_prefill(const float* __restrict__ qkv,
                                                    float* __restrict__ attn)
{
    extern __shared__ float sm[];
    const int b  = blockIdx.y >> 3;
    const int h  = blockIdx.y & 7;
    const int l0 = blockIdx.x * 64;
    const size_t rowbase = (size_t)(b * S_) * 1536;
    flash64(qkv + rowbase + (size_t)l0 * 1536 + h * 64, 1536,
            qkv + rowbase + 512 + h * 64, 1536,
            qkv + rowbase + 1024 + h * 64, 1536,
            attn + (size_t)(b * S_ + l0) * 512 + h * 64, 512,
            (l0 >> 6) + 1, l0 >> 6, sm, threadIdx.x);
}

// decode: grid (B*H); 64 queries (= steps) per (b,h); 17 KV tiles, diag at 16
__global__ void __launch_bounds__(256) attn_decode(const float* __restrict__ qdec,
                                                   const float* __restrict__ kc,
                                                   const float* __restrict__ vc,
                                                   float* __restrict__ dattn)
{
    extern __shared__ float sm[];
    const int b = blockIdx.x >> 3;
    const int h = blockIdx.x & 7;
    flash64(qdec + (size_t)b * 1536 + h * 64, 8 * 1536,      // q row i = step i
            kc + (size_t)b * CAP_ * 512 + h * 64, 512,
            vc + (size_t)b * CAP_ * 512 + h * 64, 512,
            dattn + (size_t)b * 512 + h * 64, 8 * 512,       // out row i = step i
            CAP_ / 64, (CAP_ / 64) - 1, sm, threadIdx.x);
}

// ---------------- LayerNorm over rows of 512 ----------------
// MODE 0: orow = r; 1: prefill out map; 2: decode out map
template<int MODE>
__global__ void __launch_bounds__(256) ln_rows(const float* __restrict__ in,
                                               const float* __restrict__ g,
                                               const float* __restrict__ be,
                                               float* __restrict__ out)
{
    const int r = blockIdx.x;
    const int tid = threadIdx.x;
    const float* row = in + (size_t)r * 512;
    float v0 = row[tid], v1 = row[tid + 256];
    float s  = warpRedSum(v0 + v1);
    float s2 = warpRedSum(v0 * v0 + v1 * v1);
    __shared__ float r1[8], r2[8];
    __shared__ float smu, srs;
    const int w = tid >> 5, lane = tid & 31;
    if (lane == 0) { r1[w] = s; r2[w] = s2; }
    __syncthreads();
    if (tid == 0) {
        float S = 0.f, S2 = 0.f;
#pragma unroll
        for (int i = 0; i < 8; i++) { S += r1[i]; S2 += r2[i]; }
        float mu  = S * (1.f / 512.f);
        float var = S2 * (1.f / 512.f) - mu * mu;
        smu = mu; srs = rsqrtf(var + 1e-5f);
    }
    __syncthreads();
    int orow;
    if (MODE == 0)      orow = r;
    else if (MODE == 1) orow = r + (r >> 10) * 64;
    else                orow = (r & 7) * CAP_ + S_ + (r >> 3);
    float* od = out + (size_t)orow * 512;
    od[tid]       = (v0 - smu) * srs * g[tid]       + be[tid];
    od[tid + 256] = (v1 - smu) * srs * g[tid + 256] + be[tid + 256];
}

// ---------------- host launcher ----------------
struct ScratchPtrs {
    float *Qkv, *Qdec, *Attn, *Pre, *Hb, *Hff, *Kc, *Vc;
    float *Dattn, *Dpre, *Dhb, *Dhff;
    cudaStream_t sDec;
    cudaEvent_t evQkv, evDec;
};

static const ScratchPtrs& get_scratch() {
    static ScratchPtrs p;
    static bool init = false;
    if (!init) {
        cudaGetSymbolAddress((void**)&p.Qkv,  g_qkv);
        cudaGetSymbolAddress((void**)&p.Qdec, g_qkvdec);
        cudaGetSymbolAddress((void**)&p.Attn, g_attn);
        cudaGetSymbolAddress((void**)&p.Pre,  g_pre);
        cudaGetSymbolAddress((void**)&p.Hb,   g_h);
        cudaGetSymbolAddress((void**)&p.Hff,  g_hff);
        cudaGetSymbolAddress((void**)&p.Kc,   g_kc);
        cudaGetSymbolAddress((void**)&p.Vc,   g_vc);
        cudaGetSymbolAddress((void**)&p.Dattn, g_dattn);
        cudaGetSymbolAddress((void**)&p.Dpre,  g_dpre);
        cudaGetSymbolAddress((void**)&p.Dhb,   g_dhb);
        cudaGetSymbolAddress((void**)&p.Dhff,  g_dhff);
        cudaFuncSetAttribute(attn_prefill,
                             cudaFuncAttributeMaxDynamicSharedMemorySize, 49408);
        cudaFuncSetAttribute(attn_decode,
                             cudaFuncAttributeMaxDynamicSharedMemorySize, 49408);
        cudaStreamCreateWithFlags(&p.sDec, cudaStreamNonBlocking);
        cudaEventCreateWithFlags(&p.evQkv, cudaEventDisableTiming);
        cudaEventCreateWithFlags(&p.evDec, cudaEventDisableTiming);
        init = true;
    }
    return p;
}

extern "C" void kernel_launch(void* const* d_in, const int* in_sizes, int n_in,
                              void* d_out, int out_size)
{
    (void)in_sizes; (void)n_in; (void)out_size;
    const float* x    = (const float*)d_in[0];
    const float* dx   = (const float*)d_in[1];
    // d_in[2] = causal_mask (bool) — unused, causality computed analytically
    const float* qkvW = (const float*)d_in[3];
    const float* qkvB = (const float*)d_in[4];
    const float* outW = (const float*)d_in[5];
    const float* outB = (const float*)d_in[6];
    const float* w1   = (const float*)d_in[7];
    const float* b1   = (const float*)d_in[8];
    const float* w2   = (const float*)d_in[9];
    const float* b2   = (const float*)d_in[10];
    const float* ln1w = (const float*)d_in[11];
    const float* ln1b = (const float*)d_in[12];
    const float* ln2w = (const float*)d_in[13];
    const float* ln2b = (const float*)d_in[14];
    float* out = (float*)d_out;

    const ScratchPtrs& sp = get_scratch();

    // ---- QKV GEMMs: prefill (seeds KV rows 0..1023) + all decode steps ----
    sgemm_nt<1,0,0,1><<<dim3(12, 64), 256>>>(x, qkvW, qkvB, nullptr, sp.Qkv,
                                             MTOK, 1536, 512, sp.Kc, sp.Vc);
    sgemm_nt<1,0,0,2><<<dim3(12, 4), 256>>>(dx, qkvW, qkvB, nullptr, sp.Qdec,
                                            MDEC, 1536, 512, sp.Kc, sp.Vc);

    // ---- fork: decode chain (all batched, M=512) on a second stream ----
    cudaEventRecord(sp.evQkv, 0);
    cudaStreamWaitEvent(sp.sDec, sp.evQkv, 0);
    attn_decode<<<64, 256, 49408, sp.sDec>>>(sp.Qdec, sp.Kc, sp.Vc, sp.Dattn);
    sgemm_nt<1,0,1,0><<<dim3(4, 4), 256, 0, sp.sDec>>>(
        sp.Dattn, outW, outB, dx, sp.Dpre, MDEC, 512, 512, nullptr, nullptr);
    ln_rows<0><<<MDEC, 256, 0, sp.sDec>>>(sp.Dpre, ln1w, ln1b, sp.Dhb);
    sgemm_nt<1,1,0,0><<<dim3(16, 4), 256, 0, sp.sDec>>>(
        sp.Dhb, w1, b1, nullptr, sp.Dhff, MDEC, 2048, 512, nullptr, nullptr);
    sgemm_nt<1,0,1,0><<<dim3(4, 4), 256, 0, sp.sDec>>>(
        sp.Dhff, w2, b2, sp.Dhb, sp.Dpre, MDEC, 512, 2048, nullptr, nullptr);
    ln_rows<2><<<MDEC, 256, 0, sp.sDec>>>(sp.Dpre, ln2w, ln2b, out);
    cudaEventRecord(sp.evDec, sp.sDec);

    // ---- prefill chain on the main stream ----
    attn_prefill<<<dim3(16, 64), 256, 49408>>>(sp.Qkv, sp.Attn);
    sgemm_nt<1,0,1,0><<<dim3(4, 64), 256>>>(sp.Attn, outW, outB, x, sp.Pre,
                                            MTOK, 512, 512, nullptr, nullptr);
    ln_rows<0><<<MTOK, 256>>>(sp.Pre, ln1w, ln1b, sp.Hb);
    sgemm_nt<1,1,0,0><<<dim3(16, 64), 256>>>(sp.Hb, w1, b1, nullptr, sp.Hff,
                                             MTOK, 2048, 512, nullptr, nullptr);
    sgemm_nt<1,0,1,0><<<dim3(4, 64), 256>>>(sp.Hff, w2, b2, sp.Hb, sp.Pre,
                                            MTOK, 512, 2048, nullptr, nullptr);
    ln_rows<1><<<MTOK, 256>>>(sp.Pre, ln2w, ln2b, out);

    // ---- join ----
    cudaStreamWaitEvent(0, sp.evDec, 0);
}

// round 14
// speedup vs baseline: 3.8551x; 1.2045x over previous
#include <cuda_runtime.h>
#include <cuda_bf16.h>
#include <cstdint>

#define B_     8
#define S_     1024
#define D_     512
#define H_     8
#define HD_    64
#define FF_    2048
#define STEPS_ 64
#define CAP_   1088
#define MTOK   (B_*S_)     /* 8192 */
#define MDEC   (STEPS_*B_) /* 512 */
#define KPITCH 36          /* smem row pitch in words (conflict-free frags) */
#define ATTN_SMEM (4*64*KPITCH*4)

// ---------------- device scratch (no cudaMalloc allowed) ----------------
__device__ float g_qkv [MTOK*1536];
__device__ float g_qkvdec[MDEC*1536];
__device__ float g_attn[MTOK*D_];
__device__ float g_pre [MTOK*D_];
__device__ float g_h   [MTOK*D_];
__device__ float g_hff [MTOK*FF_];
__device__ float g_kc  [B_*CAP_*D_];
__device__ float g_vc  [B_*CAP_*D_];
__device__ float g_dattn[MDEC*D_];
__device__ float g_dpre [MDEC*D_];
__device__ float g_dhb  [MDEC*D_];
__device__ float g_dhff [MDEC*FF_];

// ---------------- reductions ----------------
__device__ __forceinline__ float warpRedSum(float v) {
#pragma unroll
    for (int o = 16; o; o >>= 1) v += __shfl_xor_sync(0xffffffffu, v, o);
    return v;
}

// ---------------- bf16x3 helpers ----------------
__device__ __forceinline__ unsigned pack_bf2(float lo, float hi) {
    unsigned r;
    asm("cvt.rn.bf16x2.f32 %0, %1, %2;" : "=r"(r) : "f"(hi), "f"(lo));
    return r;
}
__device__ __forceinline__ float2 unpack_bf2(unsigned u) {
    __nv_bfloat162 t;
    *(unsigned*)&t = u;
    return make_float2(__bfloat162float(t.x), __bfloat162float(t.y));
}

__device__ __forceinline__ void mma1(unsigned a0, unsigned a1, unsigned a2, unsigned a3,
                                     unsigned b0, unsigned b1, float c[4]) {
    asm volatile(
        "mma.sync.aligned.m16n8k16.row.col.f32.bf16.bf16.f32 "
        "{%0,%1,%2,%3}, {%4,%5,%6,%7}, {%8,%9}, {%0,%1,%2,%3};"
        : "+f"(c[0]), "+f"(c[1]), "+f"(c[2]), "+f"(c[3])
        : "r"(a0), "r"(a1), "r"(a2), "r"(a3), "r"(b0), "r"(b1));
}

__device__ __forceinline__ void mma_bf(const unsigned a[4][4],
                                       const unsigned b[4][2],
                                       float acc[4][4][4])
{
#pragma unroll
    for (int mt = 0; mt < 4; mt++)
#pragma unroll
        for (int nt = 0; nt < 4; nt++)
            mma1(a[mt][0], a[mt][1], a[mt][2], a[mt][3],
                 b[nt][0], b[nt][1], acc[mt][nt]);
}

// ---------------- SGEMM (NT) via bf16x3 tensor-core mma ----------------
template<int BIAS, int RELU, int RES, int KVOUT>
__global__ void __launch_bounds__(256, 2) sgemm_nt(
    const float* __restrict__ A, const float* __restrict__ Bm,
    const float* __restrict__ bias, const float* __restrict__ R,
    float* __restrict__ C, int M, int N, int K,
    float* __restrict__ kc, float* __restrict__ vc)
{
    __shared__ unsigned AhS[128][12], AlS[128][12];
    __shared__ unsigned BhS[128][12], BlS[128][12];
    const int tid = threadIdx.x;
    const int m0 = blockIdx.y * 128;
    const int n0 = blockIdx.x * 128;
    const int w = tid >> 5, lane = tid & 31;
    const int wm0 = (w >> 2) * 64;
    const int wn0 = (w & 3) * 32;
    const int g = lane >> 2, tq = lane & 3;
    const int lrow = tid >> 2;
    const int lk4  = (tid & 3) * 4;
    const int lk2  = (tid & 3) * 2;

    const float* Ap0 = A  + (size_t)(m0 + lrow)      * K + lk4;
    const float* Ap1 = A  + (size_t)(m0 + lrow + 64) * K + lk4;
    const float* Bp0 = Bm + (size_t)(n0 + lrow)      * K + lk4;
    const float* Bp1 = Bm + (size_t)(n0 + lrow + 64) * K + lk4;

    float acc[4][4][4];
#pragma unroll
    for (int i = 0; i < 4; i++)
#pragma unroll
        for (int j = 0; j < 4; j++)
#pragma unroll
            for (int q = 0; q < 4; q++) acc[i][j][q] = 0.f;

    float4 pa0 = *(const float4*)(Ap0);
    float4 pa1 = *(const float4*)(Ap1);
    float4 pb0 = *(const float4*)(Bp0);
    float4 pb1 = *(const float4*)(Bp1);

    for (int k0 = 0; k0 < K; k0 += 16) {
        {
            unsigned h; float2 f;
            h = pack_bf2(pa0.x, pa0.y); f = unpack_bf2(h);
            AhS[lrow][lk2] = h;
            AlS[lrow][lk2] = pack_bf2(pa0.x - f.x, pa0.y - f.y);
            h = pack_bf2(pa0.z, pa0.w); f = unpack_bf2(h);
            AhS[lrow][lk2 + 1] = h;
            AlS[lrow][lk2 + 1] = pack_bf2(pa0.z - f.x, pa0.w - f.y);
            h = pack_bf2(pa1.x, pa1.y); f = unpack_bf2(h);
            AhS[lrow + 64][lk2] = h;
            AlS[lrow + 64][lk2] = pack_bf2(pa1.x - f.x, pa1.y - f.y);
            h = pack_bf2(pa1.z, pa1.w); f = unpack_bf2(h);
            AhS[lrow + 64][lk2 + 1] = h;
            AlS[lrow + 64][lk2 + 1] = pack_bf2(pa1.z - f.x, pa1.w - f.y);
            h = pack_bf2(pb0.x, pb0.y); f = unpack_bf2(h);
            BhS[lrow][lk2] = h;
            BlS[lrow][lk2] = pack_bf2(pb0.x - f.x, pb0.y - f.y);
            h = pack_bf2(pb0.z, pb0.w); f = unpack_bf2(h);
            BhS[lrow][lk2 + 1] = h;
            BlS[lrow][lk2 + 1] = pack_bf2(pb0.z - f.x, pb0.w - f.y);
            h = pack_bf2(pb1.x, pb1.y); f = unpack_bf2(h);
            BhS[lrow + 64][lk2] = h;
            BlS[lrow + 64][lk2] = pack_bf2(pb1.x - f.x, pb1.y - f.y);
            h = pack_bf2(pb1.z, pb1.w); f = unpack_bf2(h);
            BhS[lrow + 64][lk2 + 1] = h;
            BlS[lrow + 64][lk2 + 1] = pack_bf2(pb1.z - f.x, pb1.w - f.y);
        }
        __syncthreads();
        if (k0 + 16 < K) {
            pa0 = *(const float4*)(Ap0 + k0 + 16);
            pa1 = *(const float4*)(Ap1 + k0 + 16);
            pb0 = *(const float4*)(Bp0 + k0 + 16);
            pb1 = *(const float4*)(Bp1 + k0 + 16);
        }
        {
            unsigned ah[4][4], bh[4][2];
#pragma unroll
            for (int mt = 0; mt < 4; mt++) {
                const int rA = wm0 + mt * 16 + g;
                ah[mt][0] = AhS[rA][tq];
                ah[mt][1] = AhS[rA + 8][tq];
                ah[mt][2] = AhS[rA][4 + tq];
                ah[mt][3] = AhS[rA + 8][4 + tq];
            }
#pragma unroll
            for (int nt = 0; nt < 4; nt++) {
                const int rB = wn0 + nt * 8 + g;
                bh[nt][0] = BhS[rB][tq];
                bh[nt][1] = BhS[rB][4 + tq];
            }
            mma_bf(ah, bh, acc);
            {
                unsigned bl[4][2];
#pragma unroll
                for (int nt = 0; nt < 4; nt++) {
                    const int rB = wn0 + nt * 8 + g;
                    bl[nt][0] = BlS[rB][tq];
                    bl[nt][1] = BlS[rB][4 + tq];
                }
                mma_bf(ah, bl, acc);
            }
            {
                unsigned al[4][4];
#pragma unroll
                for (int mt = 0; mt < 4; mt++) {
                    const int rA = wm0 + mt * 16 + g;
                    al[mt][0] = AlS[rA][tq];
                    al[mt][1] = AlS[rA + 8][tq];
                    al[mt][2] = AlS[rA][4 + tq];
                    al[mt][3] = AlS[rA + 8][4 + tq];
                }
                mma_bf(al, bh, acc);
            }
        }
        __syncthreads();
    }

#pragma unroll
    for (int nt = 0; nt < 4; nt++) {
        const int col = n0 + wn0 + nt * 8 + tq * 2;
        const float b0v = BIAS ? bias[col] : 0.f;
        const float b1v = BIAS ? bias[col + 1] : 0.f;
#pragma unroll
        for (int mt = 0; mt < 4; mt++) {
#pragma unroll
            for (int rh = 0; rh < 2; rh++) {
                const int row = m0 + wm0 + mt * 16 + g + rh * 8;
                float t0 = acc[mt][nt][rh * 2 + 0] + b0v;
                float t1 = acc[mt][nt][rh * 2 + 1] + b1v;
                if (RES) {
                    float2 r = *(const float2*)(R + (size_t)row * N + col);
                    t0 += r.x; t1 += r.y;
                }
                if (RELU) { t0 = fmaxf(t0, 0.f); t1 = fmaxf(t1, 0.f); }
                float2 v; v.x = t0; v.y = t1;
                *(float2*)(C + (size_t)row * N + col) = v;
                if (KVOUT && col >= 512) {
                    int bb, ss;
                    if (KVOUT == 1) { bb = row >> 10; ss = row & 1023; }
                    else            { bb = row & 7;   ss = S_ + (row >> 3); }
                    float* dst = (col < 1024)
                        ? kc + ((size_t)(bb * CAP_ + ss) * 512 + (col - 512))
                        : vc + ((size_t)(bb * CAP_ + ss) * 512 + (col - 1024));
                    *(float2*)dst = v;
                }
            }
        }
    }
}

// ---------------- tensor-core flash attention core ----------------
// 128 threads / 4 warps; warp w owns query rows w*16..w*16+15 (full 64-col
// stripes so softmax rows stay inside one warp quad).
__device__ __forceinline__ void flash64_mma(
    const float* __restrict__ qbase, size_t qstride,
    const float* __restrict__ kbase, size_t kstride,
    const float* __restrict__ vbase, size_t vstride,
    float* __restrict__ obase, size_t ostride,
    int ntiles, int diagTile, unsigned* sm, int tid)
{
    unsigned* Kh = sm;                    // [64][KPITCH] words, [t][dpair]
    unsigned* Kl = Kh + 64 * KPITCH;
    unsigned* Vh = Kl + 64 * KPITCH;      // [d][tpair] (transposed)
    unsigned* Vl = Vh + 64 * KPITCH;
    __nv_bfloat16* vhh = (__nv_bfloat16*)Vh;
    __nv_bfloat16* vlh = (__nv_bfloat16*)Vl;

    const int w = tid >> 5, lane = tid & 31;
    const int g = lane >> 2, tq = lane & 3;
    const int wq0 = w * 16;
    const int strow = tid >> 1, sths = tid & 1;   // staging: row, 32-col half

    // Q fragments (x 0.125), split hi/lo: [kstep][a0..a3]
    unsigned qh[4][4], ql[4][4];
    {
        const float* r0p = qbase + (size_t)(wq0 + g) * qstride;
        const float* r1p = qbase + (size_t)(wq0 + g + 8) * qstride;
#pragma unroll
        for (int s = 0; s < 4; s++)
#pragma unroll
            for (int part = 0; part < 4; part++) {
                const float* rp = (part & 1) ? r1p : r0p;
                const int col = 16 * s + ((part >> 1) ? 8 : 0) + 2 * tq;
                float2 v = *(const float2*)(rp + col);
                float x0 = v.x * 0.125f, x1 = v.y * 0.125f;
                unsigned h = pack_bf2(x0, x1);
                float2 f = unpack_bf2(h);
                qh[s][part] = h;
                ql[s][part] = pack_bf2(x0 - f.x, x1 - f.y);
            }
    }

    float oacc[8][4];
#pragma unroll
    for (int j = 0; j < 8; j++)
#pragma unroll
        for (int q = 0; q < 4; q++) oacc[j][q] = 0.f;
    float mrow0 = -1e30f, mrow1 = -1e30f, lrow0 = 0.f, lrow1 = 0.f;

    for (int tile = 0; tile < ntiles; ++tile) {
        const int j0 = tile * 64;
        __syncthreads();
        // ---- stage K (natural) and V (transposed), bf16 hi/lo ----
#pragma unroll
        for (int i = 0; i < 8; i++) {
            float4 kv = *(const float4*)(kbase + (size_t)(j0 + strow) * kstride
                                         + sths * 32 + i * 4);
            unsigned h0 = pack_bf2(kv.x, kv.y); float2 f0 = unpack_bf2(h0);
            unsigned h1 = pack_bf2(kv.z, kv.w); float2 f1 = unpack_bf2(h1);
            const int wi = strow * KPITCH + sths * 16 + i * 2;
            Kh[wi] = h0; Kh[wi + 1] = h1;
            Kl[wi]     = pack_bf2(kv.x - f0.x, kv.y - f0.y);
            Kl[wi + 1] = pack_bf2(kv.z - f1.x, kv.w - f1.y);
            float4 vv = *(const float4*)(vbase + (size_t)(j0 + strow) * vstride
                                         + sths * 32 + i * 4);
            const float* vp = (const float*)&vv;
#pragma unroll
            for (int jj = 0; jj < 4; jj++) {
                const int d = sths * 32 + i * 4 + jj;
                __nv_bfloat16 hb = __float2bfloat16(vp[jj]);
                vhh[d * (2 * KPITCH) + strow] = hb;
                vlh[d * (2 * KPITCH) + strow] =
                    __float2bfloat16(vp[jj] - __bfloat162float(hb));
            }
        }
        __syncthreads();

        // ---- S = (Q/8) K^T, bf16x3 ----
        float sacc[8][4];
#pragma unroll
        for (int j = 0; j < 8; j++)
#pragma unroll
            for (int q = 0; q < 4; q++) sacc[j][q] = 0.f;
#pragma unroll
        for (int s = 0; s < 4; s++)
#pragma unroll
            for (int j = 0; j < 8; j++) {
                const int base = (8 * j + g) * KPITCH + 8 * s + tq;
                unsigned kb0 = Kh[base], kb1 = Kh[base + 4];
                mma1(qh[s][0], qh[s][1], qh[s][2], qh[s][3], kb0, kb1, sacc[j]);
                mma1(ql[s][0], ql[s][1], ql[s][2], ql[s][3], kb0, kb1, sacc[j]);
                unsigned lb0 = Kl[base], lb1 = Kl[base + 4];
                mma1(qh[s][0], qh[s][1], qh[s][2], qh[s][3], lb0, lb1, sacc[j]);
            }

        if (tile == diagTile) {
            const int row0 = wq0 + g, row1 = row0 + 8;
#pragma unroll
            for (int j = 0; j < 8; j++) {
                const int c = 8 * j + 2 * tq;
                if (c > row0)     sacc[j][0] = -1e30f;
                if (c + 1 > row0) sacc[j][1] = -1e30f;
                if (c > row1)     sacc[j][2] = -1e30f;
                if (c + 1 > row1) sacc[j][3] = -1e30f;
            }
        }

        // ---- online softmax (rows wq0+g and wq0+g+8) ----
        float m0 = -1e30f, m1 = -1e30f;
#pragma unroll
        for (int j = 0; j < 8; j++) {
            m0 = fmaxf(m0, fmaxf(sacc[j][0], sacc[j][1]));
            m1 = fmaxf(m1, fmaxf(sacc[j][2], sacc[j][3]));
        }
        m0 = fmaxf(m0, __shfl_xor_sync(0xffffffffu, m0, 1));
        m0 = fmaxf(m0, __shfl_xor_sync(0xffffffffu, m0, 2));
        m1 = fmaxf(m1, __shfl_xor_sync(0xffffffffu, m1, 1));
        m1 = fmaxf(m1, __shfl_xor_sync(0xffffffffu, m1, 2));
        const float mn0 = fmaxf(mrow0, m0), mn1 = fmaxf(mrow1, m1);
        const float al0 = __expf(mrow0 - mn0), al1 = __expf(mrow1 - mn1);
        float ls0 = 0.f, ls1 = 0.f;
        unsigned ph0[8], ph1[8], pl0[8], pl1[8];
#pragma unroll
        for (int j = 0; j < 8; j++) {
            float p0 = __expf(sacc[j][0] - mn0);
            float p1 = __expf(sacc[j][1] - mn0);
            float p2 = __expf(sacc[j][2] - mn1);
            float p3 = __expf(sacc[j][3] - mn1);
            ls0 += p0 + p1; ls1 += p2 + p3;
            unsigned h = pack_bf2(p0, p1); float2 f = unpack_bf2(h);
            ph0[j] = h; pl0[j] = pack_bf2(p0 - f.x, p1 - f.y);
            h = pack_bf2(p2, p3); f = unpack_bf2(h);
            ph1[j] = h; pl1[j] = pack_bf2(p2 - f.x, p3 - f.y);
        }
        ls0 += __shfl_xor_sync(0xffffffffu, ls0, 1);
        ls0 += __shfl_xor_sync(0xffffffffu, ls0, 2);
        ls1 += __shfl_xor_sync(0xffffffffu, ls1, 1);
        ls1 += __shfl_xor_sync(0xffffffffu, ls1, 2);
        lrow0 = lrow0 * al0 + ls0; mrow0 = mn0;
        lrow1 = lrow1 * al1 + ls1; mrow1 = mn1;
#pragma unroll
        for (int j = 0; j < 8; j++) {
            oacc[j][0] *= al0; oacc[j][1] *= al0;
            oacc[j][2] *= al1; oacc[j][3] *= al1;
        }

        // ---- O += P V (P fragment reused directly as A fragment) ----
#pragma unroll
        for (int s = 0; s < 4; s++) {
            const unsigned a0 = ph0[2 * s],     a1 = ph1[2 * s];
            const unsigned a2 = ph0[2 * s + 1], a3 = ph1[2 * s + 1];
            const unsigned c0 = pl0[2 * s],     c1 = pl1[2 * s];
            const unsigned c2 = pl0[2 * s + 1], c3 = pl1[2 * s + 1];
#pragma unroll
            for (int j = 0; j < 8; j++) {
                const int base = (8 * j + g) * KPITCH + 8 * s + tq;
                unsigned vb0 = Vh[base], vb1 = Vh[base + 4];
                mma1(a0, a1, a2, a3, vb0, vb1, oacc[j]);
                mma1(c0, c1, c2, c3, vb0, vb1, oacc[j]);
                unsigned wl0 = Vl[base], wl1 = Vl[base + 4];
                mma1(a0, a1, a2, a3, wl0, wl1, oacc[j]);
            }
        }
    }

    const float inv0 = 1.f / lrow0, inv1 = 1.f / lrow1;
#pragma unroll
    for (int j = 0; j < 8; j++) {
        float2 v0; v0.x = oacc[j][0] * inv0; v0.y = oacc[j][1] * inv0;
        float2 v1; v1.x = oacc[j][2] * inv1; v1.y = oacc[j][3] * inv1;
        *(float2*)(obase + (size_t)(wq0 + g) * ostride + 8 * j + 2 * tq) = v0;
        *(float2*)(obase + (size_t)(wq0 + g + 8) * ostride + 8 * j + 2 * tq) = v1;
    }
}

// prefill: grid (S/64, B*H), 128 threads
__global__ void __launch_bounds__(128, 3) attn_prefill(const float* __restrict__ qkv,
                                                       float* __restrict__ attn)
{
    extern __shared__ unsigned smu[];
    const int b  = blockIdx.y >> 3;
    const int h  = blockIdx.y & 7;
    const int l0 = blockIdx.x * 64;
    const size_t rowbase = (size_t)(b * S_) * 1536;
    flash64_mma(qkv + rowbase + (size_t)l0 * 1536 + h * 64, 1536,
                qkv + rowbase + 512 + h * 64, 1536,
                qkv + rowbase + 1024 + h * 64, 1536,
                attn + (size_t)(b * S_ + l0) * 512 + h * 64, 512,
                (l0 >> 6) + 1, l0 >> 6, smu, threadIdx.x);
}

// decode: grid (B*H), 64 queries (steps), 17 KV tiles, diag at 16
__global__ void __launch_bounds__(128, 3) attn_decode(const float* __restrict__ qdec,
                                                      const float* __restrict__ kc,
                                                      const float* __restrict__ vc,
                                                      float* __restrict__ dattn)
{
    extern __shared__ unsigned smu[];
    const int b = blockIdx.x >> 3;
    const int h = blockIdx.x & 7;
    flash64_mma(qdec + (size_t)b * 1536 + h * 64, 8 * 1536,
                kc + (size_t)b * CAP_ * 512 + h * 64, 512,
                vc + (size_t)b * CAP_ * 512 + h * 64, 512,
                dattn + (size_t)b * 512 + h * 64, 8 * 512,
                CAP_ / 64, (CAP_ / 64) - 1, smu, threadIdx.x);
}

// ---------------- LayerNorm over rows of 512 ----------------
template<int MODE>
__global__ void __launch_bounds__(256) ln_rows(const float* __restrict__ in,
                                               const float* __restrict__ g,
                                               const float* __restrict__ be,
                                               float* __restrict__ out)
{
    const int r = blockIdx.x;
    const int tid = threadIdx.x;
    const float* row = in + (size_t)r * 512;
    float v0 = row[tid], v1 = row[tid + 256];
    float s  = warpRedSum(v0 + v1);
    float s2 = warpRedSum(v0 * v0 + v1 * v1);
    __shared__ float r1[8], r2[8];
    __shared__ float smu2, srs;
    const int w = tid >> 5, lane = tid & 31;
    if (lane == 0) { r1[w] = s; r2[w] = s2; }
    __syncthreads();
    if (tid == 0) {
        float S = 0.f, S2 = 0.f;
#pragma unroll
        for (int i = 0; i < 8; i++) { S += r1[i]; S2 += r2[i]; }
        float mu  = S * (1.f / 512.f);
        float var = S2 * (1.f / 512.f) - mu * mu;
        smu2 = mu; srs = rsqrtf(var + 1e-5f);
    }
    __syncthreads();
    int orow;
    if (MODE == 0)      orow = r;
    else if (MODE == 1) orow = r + (r >> 10) * 64;
    else                orow = (r & 7) * CAP_ + S_ + (r >> 3);
    float* od = out + (size_t)orow * 512;
    od[tid]       = (v0 - smu2) * srs * g[tid]       + be[tid];
    od[tid + 256] = (v1 - smu2) * srs * g[tid + 256] + be[tid + 256];
}

// ---------------- host launcher ----------------
struct ScratchPtrs {
    float *Qkv, *Qdec, *Attn, *Pre, *Hb, *Hff, *Kc, *Vc;
    float *Dattn, *Dpre, *Dhb, *Dhff;
    cudaStream_t sDec;
    cudaEvent_t evQkv, evDec;
};

static const ScratchPtrs& get_scratch() {
    static ScratchPtrs p;
    static bool init = false;
    if (!init) {
        cudaGetSymbolAddress((void**)&p.Qkv,  g_qkv);
        cudaGetSymbolAddress((void**)&p.Qdec, g_qkvdec);
        cudaGetSymbolAddress((void**)&p.Attn, g_attn);
        cudaGetSymbolAddress((void**)&p.Pre,  g_pre);
        cudaGetSymbolAddress((void**)&p.Hb,   g_h);
        cudaGetSymbolAddress((void**)&p.Hff,  g_hff);
        cudaGetSymbolAddress((void**)&p.Kc,   g_kc);
        cudaGetSymbolAddress((void**)&p.Vc,   g_vc);
        cudaGetSymbolAddress((void**)&p.Dattn, g_dattn);
        cudaGetSymbolAddress((void**)&p.Dpre,  g_dpre);
        cudaGetSymbolAddress((void**)&p.Dhb,   g_dhb);
        cudaGetSymbolAddress((void**)&p.Dhff,  g_dhff);
        cudaFuncSetAttribute(attn_prefill,
                             cudaFuncAttributeMaxDynamicSharedMemorySize, ATTN_SMEM);
        cudaFuncSetAttribute(attn_decode,
                             cudaFuncAttributeMaxDynamicSharedMemorySize, ATTN_SMEM);
        cudaStreamCreateWithFlags(&p.sDec, cudaStreamNonBlocking);
        cudaEventCreateWithFlags(&p.evQkv, cudaEventDisableTiming);
        cudaEventCreateWithFlags(&p.evDec, cudaEventDisableTiming);
        init = true;
    }
    return p;
}

extern "C" void kernel_launch(void* const* d_in, const int* in_sizes, int n_in,
                              void* d_out, int out_size)
{
    (void)in_sizes; (void)n_in; (void)out_size;
    const float* x    = (const float*)d_in[0];
    const float* dx   = (const float*)d_in[1];
    // d_in[2] = causal_mask (bool) — unused, causality computed analytically
    const float* qkvW = (const float*)d_in[3];
    const float* qkvB = (const float*)d_in[4];
    const float* outW = (const float*)d_in[5];
    const float* outB = (const float*)d_in[6];
    const float* w1   = (const float*)d_in[7];
    const float* b1   = (const float*)d_in[8];
    const float* w2   = (const float*)d_in[9];
    const float* b2   = (const float*)d_in[10];
    const float* ln1w = (const float*)d_in[11];
    const float* ln1b = (const float*)d_in[12];
    const float* ln2w = (const float*)d_in[13];
    const float* ln2b = (const float*)d_in[14];
    float* out = (float*)d_out;

    const ScratchPtrs& sp = get_scratch();

    // ---- QKV GEMMs: prefill (seeds KV rows 0..1023) + all decode steps ----
    sgemm_nt<1,0,0,1><<<dim3(12, 64), 256>>>(x, qkvW, qkvB, nullptr, sp.Qkv,
                                             MTOK, 1536, 512, sp.Kc, sp.Vc);
    sgemm_nt<1,0,0,2><<<dim3(12, 4), 256>>>(dx, qkvW, qkvB, nullptr, sp.Qdec,
                                            MDEC, 1536, 512, sp.Kc, sp.Vc);

    // ---- fork: decode chain (batched, M=512) on a second stream ----
    cudaEventRecord(sp.evQkv, 0);
    cudaStreamWaitEvent(sp.sDec, sp.evQkv, 0);
    attn_decode<<<64, 128, ATTN_SMEM, sp.sDec>>>(sp.Qdec, sp.Kc, sp.Vc, sp.Dattn);
    sgemm_nt<1,0,1,0><<<dim3(4, 4), 256, 0, sp.sDec>>>(
        sp.Dattn, outW, outB, dx, sp.Dpre, MDEC, 512, 512, nullptr, nullptr);
    ln_rows<0><<<MDEC, 256, 0, sp.sDec>>>(sp.Dpre, ln1w, ln1b, sp.Dhb);
    sgemm_nt<1,1,0,0><<<dim3(16, 4), 256, 0, sp.sDec>>>(
        sp.Dhb, w1, b1, nullptr, sp.Dhff, MDEC, 2048, 512, nullptr, nullptr);
    sgemm_nt<1,0,1,0><<<dim3(4, 4), 256, 0, sp.sDec>>>(
        sp.Dhff, w2, b2, sp.Dhb, sp.Dpre, MDEC, 512, 2048, nullptr, nullptr);
    ln_rows<2><<<MDEC, 256, 0, sp.sDec>>>(sp.Dpre, ln2w, ln2b, out);
    cudaEventRecord(sp.evDec, sp.sDec);

    // ---- prefill chain on the main stream ----
    attn_prefill<<<dim3(16, 64), 128, ATTN_SMEM>>>(sp.Qkv, sp.Attn);
    sgemm_nt<1,0,1,0><<<dim3(4, 64), 256>>>(sp.Attn, outW, outB, x, sp.Pre,
                                            MTOK, 512, 512, nullptr, nullptr);
    ln_rows<0><<<MTOK, 256>>>(sp.Pre, ln1w, ln1b, sp.Hb);
    sgemm_nt<1,1,0,0><<<dim3(16, 64), 256>>>(sp.Hb, w1, b1, nullptr, sp.Hff,
                                             MTOK, 2048, 512, nullptr, nullptr);
    sgemm_nt<1,0,1,0><<<dim3(4, 64), 256>>>(sp.Hff, w2, b2, sp.Hb, sp.Pre,
                                            MTOK, 512, 2048, nullptr, nullptr);
    ln_rows<1><<<MTOK, 256>>>(sp.Pre, ln2w, ln2b, out);

    // ---- join ----
    cudaStreamWaitEvent(0, sp.evDec, 0);
}